// round 9
// baseline (speedup 1.0000x reference)
#include <cuda_runtime.h>
#include <cuda_bf16.h>

#define BB 8
#define NN 1024
#define DIN 512
#define HH 8
#define INNER 512
#define DOUT 512
#define NROWS (BB*NN)            // 8192
#define QKV_COLS 1536
#define SCALE 0.125f
#define LOG2E 1.4426950408889634f

// ---- scratch (device globals; no runtime allocation) ----
__device__ float g_qkv[(size_t)NROWS * QKV_COLS];           // q|k (tf32-rounded); V region unused
__device__ float g_vT[(size_t)BB * HH * 64 * NN];           // V^T per (b,h): [d][token], tf32
__device__ float g_bias_t[(size_t)BB * HH * NN * NN];       // bias transposed+masked f32, 256MB
__device__ unsigned g_xh[(size_t)NROWS * (DIN/2)];          // x hi bf16 pairs [row][kp]
__device__ unsigned g_xl[(size_t)NROWS * (DIN/2)];
__device__ unsigned g_wqkvh[(size_t)QKV_COLS * 256];        // [SCALE*Wq|Wkv] n-major [n][kp]
__device__ unsigned g_wqkvl[(size_t)QKV_COLS * 256];
__device__ unsigned g_wouth[(size_t)DOUT * 256];            // Wout n-major [n][kp]
__device__ unsigned g_woutl[(size_t)DOUT * 256];
__device__ unsigned g_atth[(size_t)NROWS * (INNER/2)];      // attention out hi pairs [row][kp]
__device__ unsigned g_attl[(size_t)NROWS * (INNER/2)];
__device__ unsigned char g_maskb[BB * NN];

// ---- helpers ----
__device__ __forceinline__ float to_tf32(float x) {
    unsigned u;
    asm("cvt.rna.tf32.f32 %0, %1;" : "=r"(u) : "f"(x));
    return __uint_as_float(u);
}
__device__ __forceinline__ float ex2(float x) {
    float y;
    asm("ex2.approx.ftz.f32 %0, %1;" : "=f"(y) : "f"(x));
    return y;
}
__device__ __forceinline__ unsigned pack_bf16(float hi_elem, float lo_elem) {
    unsigned r;
    asm("cvt.rn.bf16x2.f32 %0, %1, %2;" : "=r"(r) : "f"(hi_elem), "f"(lo_elem));
    return r;
}
__device__ __forceinline__ void cp16(void* sp, const void* gp) {
    unsigned s = (unsigned)__cvta_generic_to_shared(sp);
    asm volatile("cp.async.cg.shared.global [%0], [%1], 16;\n" :: "r"(s), "l"(gp));
}
#define CP_COMMIT asm volatile("cp.async.commit_group;\n")
#define CP_WAIT0  asm volatile("cp.async.wait_group 0;\n")
#define CP_WAIT1  asm volatile("cp.async.wait_group 1;\n")

__device__ __forceinline__ void ldsm4(unsigned& r0, unsigned& r1, unsigned& r2, unsigned& r3,
                                      unsigned saddr) {
    asm volatile("ldmatrix.sync.aligned.m8n8.x4.shared.b16 {%0,%1,%2,%3}, [%4];"
                 : "=r"(r0), "=r"(r1), "=r"(r2), "=r"(r3) : "r"(saddr));
}
__device__ __forceinline__ void mma8(float& c0, float& c1, float& c2, float& c3,
                                     unsigned a0, unsigned a1, unsigned a2, unsigned a3,
                                     unsigned b0, unsigned b1) {
    asm volatile(
        "mma.sync.aligned.m16n8k8.row.col.f32.tf32.tf32.f32 "
        "{%0,%1,%2,%3},{%4,%5,%6,%7},{%8,%9},{%0,%1,%2,%3};\n"
        : "+f"(c0), "+f"(c1), "+f"(c2), "+f"(c3)
        : "r"(a0), "r"(a1), "r"(a2), "r"(a3), "r"(b0), "r"(b1));
}
__device__ __forceinline__ void mma16bf(float& c0, float& c1, float& c2, float& c3,
                                        unsigned a0, unsigned a1, unsigned a2, unsigned a3,
                                        unsigned b0, unsigned b1) {
    asm volatile(
        "mma.sync.aligned.m16n8k16.row.col.f32.bf16.bf16.f32 "
        "{%0,%1,%2,%3},{%4,%5,%6,%7},{%8,%9},{%0,%1,%2,%3};\n"
        : "+f"(c0), "+f"(c1), "+f"(c2), "+f"(c3)
        : "r"(a0), "r"(a1), "r"(a2), "r"(a3), "r"(b0), "r"(b1));
}

// =====================================================================
// k_prep: [CTA 0] mask expand; [1..8192] split x; [8193..10240] split W
// =====================================================================
__global__ __launch_bounds__(256) void k_prep(const unsigned char* __restrict__ m,
                                              const float* __restrict__ x,
                                              const float* __restrict__ Wq,
                                              const float* __restrict__ Wkv,
                                              const float* __restrict__ Wout) {
    const int bid = blockIdx.x;
    if (bid == 0) {
        __shared__ int s_notI32, s_notF32;
        if (threadIdx.x == 0) { s_notI32 = 0; s_notF32 = 0; }
        __syncthreads();
        const unsigned* mw = (const unsigned*)m;
        int notI = 0, notF = 0;
        for (int i = threadIdx.x; i < BB * NN / 4; i += 256) {
            unsigned w = mw[i];
            if (w & 0xFFFFFF00u) notI = 1;
            if (w != 0u && w != 0x3F800000u) notF = 1;
        }
        if (notI) atomicOr(&s_notI32, 1);
        if (notF) atomicOr(&s_notF32, 1);
        __syncthreads();
        const int notI32 = s_notI32, notF32 = s_notF32;
        for (int i = threadIdx.x; i < BB * NN; i += 256) {
            unsigned char v;
            if (!notF32)      v = (((const unsigned*)m)[i] != 0u) ? 1 : 0;
            else if (!notI32) v = (((const int*)m)[i] != 0) ? 1 : 0;
            else              v = (m[i] != 0) ? 1 : 0;
            g_maskb[i] = v;
        }
    } else if (bid <= NROWS) {
        int idx = (bid - 1) * 256 + threadIdx.x;
        float2 v = ((const float2*)x)[idx];
        unsigned hp = pack_bf16(v.y, v.x);
        float b0 = __uint_as_float(hp << 16);
        float b1 = __uint_as_float(hp & 0xFFFF0000u);
        unsigned lp = pack_bf16(v.y - b1, v.x - b0);
        g_xh[idx] = hp;
        g_xl[idx] = lp;
    } else {
        int idx = (bid - NROWS - 1) * 256 + threadIdx.x;
        const int total1 = 256 * QKV_COLS;
        float a, b;
        unsigned* dh;
        unsigned* dl;
        size_t off;
        if (idx < total1) {
            int kp = idx / QKV_COLS, n = idx % QKV_COLS;
            if (n < 512) {
                a = Wq[(2 * kp) * 512 + n] * SCALE;
                b = Wq[(2 * kp + 1) * 512 + n] * SCALE;
            } else {
                int nn = n - 512;
                a = Wkv[(2 * kp) * 1024 + nn];
                b = Wkv[(2 * kp + 1) * 1024 + nn];
            }
            dh = g_wqkvh; dl = g_wqkvl;
            off = (size_t)n * 256 + kp;
        } else {
            int j = idx - total1;
            int kp = j / DOUT, n = j % DOUT;
            a = Wout[(2 * kp) * DOUT + n];
            b = Wout[(2 * kp + 1) * DOUT + n];
            dh = g_wouth; dl = g_woutl;
            off = (size_t)n * 256 + kp;
        }
        unsigned hp = pack_bf16(b, a);
        float a0 = __uint_as_float(hp << 16);
        float b0 = __uint_as_float(hp & 0xFFFF0000u);
        unsigned lp = pack_bf16(b - b0, a - a0);
        dh[off] = hp;
        dl[off] = lp;
    }
}

// =====================================================================
// Shared GEMM core (bf16 hi/lo 3-mma, tile 128x64, 2-stage cp.async, LDSM).
// =====================================================================
#define GAS 20
#define BS2 20
#define GEMM_SMEM ((2*128*GAS*2 + 2*64*BS2*2) * 4)   // 61440 bytes
#define N_GEMM_CTAS ((QKV_COLS/64) * (NROWS/128))    // 1536

template <int MODE>   // 0 = QKV (tf32 q/k + V^T scatter), 1 = out-proj
__device__ __forceinline__ void gemm_core(unsigned* smg, int cbid,
                                          const unsigned* __restrict__ Agh,
                                          const unsigned* __restrict__ Agl,
                                          const unsigned* __restrict__ Bgh,
                                          const unsigned* __restrict__ Bgl,
                                          const float* __restrict__ bout,
                                          float* __restrict__ Cout) {
    unsigned* sAh = smg;
    unsigned* sAl = sAh + 2 * 128 * GAS;
    unsigned* sBh = sAl + 2 * 128 * GAS;
    unsigned* sBl = sBh + 2 * 64 * BS2;

    const int tid = threadIdx.x, lane = tid & 31, warp = tid >> 5;
    const int g = lane >> 2, t = lane & 3;
    const int ncb = (MODE == 0) ? (QKV_COLS / 64) : (DOUT / 64);
    const int cb = (cbid % ncb) * 64;
    const int rb = (cbid / ncb) * 128;
    const int m0 = warp * 16;

    const int ar0 = tid >> 2, ac4 = (tid & 3) * 4;
    const int brB = tid >> 2, bc4 = (tid & 3) * 4;

    auto load_stage = [&](int st, int kt) {
        const int kp0 = kt * 16;
        unsigned* pAh = sAh + st * 128 * GAS;
        unsigned* pAl = sAl + st * 128 * GAS;
        #pragma unroll
        for (int sIt = 0; sIt < 2; sIt++) {
            int r = ar0 + sIt * 64;
            size_t go = (size_t)(rb + r) * 256 + kp0 + ac4;
            cp16(&pAh[r * GAS + ac4], Agh + go);
            cp16(&pAl[r * GAS + ac4], Agl + go);
        }
        size_t go = (size_t)(cb + brB) * 256 + kp0 + bc4;
        cp16(&sBh[st * 64 * BS2 + brB * BS2 + bc4], Bgh + go);
        cp16(&sBl[st * 64 * BS2 + brB * BS2 + bc4], Bgl + go);
    };

    const unsigned aoff = ((unsigned)((m0 + (lane & 15)) * GAS + ((lane & 16) >> 2))) * 4;
    const unsigned boff = ((unsigned)(((lane & 7) + ((lane & 16) >> 1)) * BS2 + ((lane & 8) >> 1))) * 4;
    const unsigned sAh_b = (unsigned)__cvta_generic_to_shared(sAh);
    const unsigned sAl_b = (unsigned)__cvta_generic_to_shared(sAl);
    const unsigned sBh_b = (unsigned)__cvta_generic_to_shared(sBh);
    const unsigned sBl_b = (unsigned)__cvta_generic_to_shared(sBl);

    float acc[8][4];
    #pragma unroll
    for (int i = 0; i < 8; i++)
        #pragma unroll
        for (int j = 0; j < 4; j++) acc[i][j] = 0.f;

    load_stage(0, 0);
    CP_COMMIT;

    for (int kt = 0; kt < 16; kt++) {
        CP_WAIT0;
        __syncthreads();
        if (kt < 15) { load_stage((kt + 1) & 1, kt + 1); CP_COMMIT; }

        const unsigned stA = (kt & 1) * 128 * GAS * 4;
        const unsigned stB = (kt & 1) * 64 * BS2 * 4;

        #pragma unroll
        for (int kc = 0; kc < 2; kc++) {
            const unsigned ko = kc * 8 * 4;
            unsigned ah0, ah1, ah2, ah3, al0, al1, al2, al3;
            ldsm4(ah0, ah1, ah2, ah3, sAh_b + stA + aoff + ko);
            ldsm4(al0, al1, al2, al3, sAl_b + stA + aoff + ko);
            #pragma unroll
            for (int nbp = 0; nbp < 4; nbp++) {
                const unsigned bo = boff + (unsigned)(nbp * 16 * BS2) * 4 + ko;
                unsigned bh0, bh1, bh2, bh3, bl0, bl1, bl2, bl3;
                ldsm4(bh0, bh1, bh2, bh3, sBh_b + stB + bo);
                ldsm4(bl0, bl1, bl2, bl3, sBl_b + stB + bo);
                float* A0 = acc[2 * nbp];
                float* A1 = acc[2 * nbp + 1];
                mma16bf(A0[0], A0[1], A0[2], A0[3], ah0, ah1, ah2, ah3, bh0, bh1);
                mma16bf(A0[0], A0[1], A0[2], A0[3], ah0, ah1, ah2, ah3, bl0, bl1);
                mma16bf(A0[0], A0[1], A0[2], A0[3], al0, al1, al2, al3, bh0, bh1);
                mma16bf(A1[0], A1[1], A1[2], A1[3], ah0, ah1, ah2, ah3, bh2, bh3);
                mma16bf(A1[0], A1[1], A1[2], A1[3], ah0, ah1, ah2, ah3, bl2, bl3);
                mma16bf(A1[0], A1[1], A1[2], A1[3], al0, al1, al2, al3, bh2, bh3);
            }
        }
        __syncthreads();
    }

    if (MODE == 0) {
        if (cb < 1024) {
            #pragma unroll
            for (int nb = 0; nb < 8; nb++) {
                int col = cb + nb * 8 + 2 * t;
                int r0 = rb + m0 + g;
                int r1 = r0 + 8;
                *(float2*)(g_qkv + (size_t)r0 * QKV_COLS + col) =
                    make_float2(to_tf32(acc[nb][0]), to_tf32(acc[nb][1]));
                *(float2*)(g_qkv + (size_t)r1 * QKV_COLS + col) =
                    make_float2(to_tf32(acc[nb][2]), to_tf32(acc[nb][3]));
            }
        } else {
            int h = (cb - 1024) >> 6;
            int r0 = rb + m0 + g;
            int b = r0 >> 10, n = r0 & 1023;
            float* vt = g_vT + (size_t)(b * 8 + h) * 64 * NN;
            #pragma unroll
            for (int nb = 0; nb < 8; nb++) {
                int d = nb * 8 + 2 * t;
                vt[(size_t)d * NN + n] = to_tf32(acc[nb][0]);
                vt[(size_t)(d + 1) * NN + n] = to_tf32(acc[nb][1]);
                vt[(size_t)d * NN + n + 8] = to_tf32(acc[nb][2]);
                vt[(size_t)(d + 1) * NN + n + 8] = to_tf32(acc[nb][3]);
            }
        }
    } else {
        #pragma unroll
        for (int nb = 0; nb < 8; nb++) {
            int col = cb + nb * 8 + 2 * t;
            float b0v = bout[col], b1v = bout[col + 1];
            int r0 = rb + m0 + g;
            int r1 = r0 + 8;
            *(float2*)(Cout + (size_t)r0 * DOUT + col) = make_float2(acc[nb][0] + b0v, acc[nb][1] + b1v);
            *(float2*)(Cout + (size_t)r1 * DOUT + col) = make_float2(acc[nb][2] + b0v, acc[nb][3] + b1v);
        }
    }
}

// =====================================================================
// k_mid: interleaved QKV GEMM (tensor) + bias transpose (DRAM).
// =====================================================================
__global__ __launch_bounds__(256, 2) void k_mid(const float* __restrict__ bias) {
    extern __shared__ unsigned smg[];
    const int bid = blockIdx.x;
    const int tid = threadIdx.x;
    const int grp = bid / 19, rem = bid % 19;

    if (rem < 3) {
        gemm_core<0>(smg, grp * 3 + rem, g_xh, g_xl, g_wqkvh, g_wqkvl, nullptr, nullptr);
    } else {
        float* s = (float*)smg;
        unsigned char* ms = (unsigned char*)smg + NN * 9 * 4;
        const int bi = grp * 16 + (rem - 3);
        const int b = bi >> 10;
        const float* src = bias + (size_t)bi * (NN * HH);

        #pragma unroll
        for (int sIt = 0; sIt < 8; sIt++) {
            int idx = tid + sIt * 256;
            float4 v = *(const float4*)(src + idx * 4);
            int j = idx >> 1;
            int h = (idx & 1) * 4;
            s[j * 9 + h + 0] = v.x;
            s[j * 9 + h + 1] = v.y;
            s[j * 9 + h + 2] = v.z;
            s[j * 9 + h + 3] = v.w;
        }
        for (int j = tid; j < NN; j += 256) ms[j] = g_maskb[b * NN + j];
        __syncthreads();

        const int i = bi & (NN - 1);
        #pragma unroll
        for (int h = 0; h < HH; h++) {
            float* dst = g_bias_t + (((size_t)(b * HH + h)) * NN + i) * NN;
            #pragma unroll
            for (int r = 0; r < 4; r++) {
                int j = tid + r * 256;
                dst[j] = ms[j] ? s[j * 9 + h] : -1e30f;
            }
        }
    }
}

__global__ __launch_bounds__(256, 2) void k_gemm_out(const float* __restrict__ bout,
                                                     float* __restrict__ Cout) {
    extern __shared__ unsigned smg[];
    gemm_core<1>(smg, blockIdx.x, g_atth, g_attl, g_wouth, g_woutl, bout, Cout);
}

// =====================================================================
// Flash attention with staggered single-buffer prefetch.
// CTA = (b,h,i-tile 128), 256 thr / 8 warps, LDSM fragments.
// Pipeline: at tile top pending cp groups = [K(jt), V+bias(jt)].
//   WAIT1 -> QK^T(jt);  WAIT0+sync -> prefetch K(jt+1) (hides under
//   softmax+PV);  after PV+sync -> prefetch V+bias(jt+1) (hides under
//   next QK^T).
// =====================================================================
#define FS 68
__global__ __launch_bounds__(256, 2) void k_flash() {
    extern __shared__ float sm[];
    float* Qs = sm;                       // 128*FS
    float* Ks = Qs + 128 * FS;            // 64*FS
    float* Vt = Ks + 64 * FS;             // 64*FS  V^T [d][j]
    float* Ps = Vt + 64 * FS;             // 128*FS (bias overlay + P)

    const int tid = threadIdx.x, lane = tid & 31, warp = tid >> 5;
    const int g = lane >> 2, t = lane & 3;
    const int it = blockIdx.x & 7;
    const int bh = blockIdx.x >> 3;
    const int b = bh >> 3, h = bh & 7;
    const int i0 = it * 128;
    const int m0 = warp * 16;
    const float NEG_INF = __int_as_float(0xff800000);

    const float* qbase = g_qkv + (size_t)b * NN * QKV_COLS;
    const float* kbase = qbase + 512 + h * 64;
    const float* vbase = g_vT + (size_t)bh * 64 * NN;
    const float* bbase = g_bias_t + ((size_t)bh * NN + i0) * NN;

    const unsigned aoff = ((unsigned)((m0 + (lane & 15)) * FS + ((lane & 16) >> 2))) * 4;
    const unsigned boff = ((unsigned)(((lane & 7) + ((lane & 16) >> 1)) * FS + ((lane & 8) >> 1))) * 4;
    const unsigned qs_b = (unsigned)__cvta_generic_to_shared(Qs);
    const unsigned ks_b = (unsigned)__cvta_generic_to_shared(Ks);
    const unsigned vt_b = (unsigned)__cvta_generic_to_shared(Vt);
    const unsigned ps_b = (unsigned)__cvta_generic_to_shared(Ps);

    const int kvr = tid >> 4, kvc4 = (tid & 15) * 4;

    // prologue: group1 = [Q + K0], group2 = [V0 + bias0]
    {
        int r = tid >> 4, c4 = (tid & 15) * 4;
        #pragma unroll
        for (int sIt = 0; sIt < 8; sIt++) {
            cp16(&Qs[(r + sIt * 16) * FS + c4],
                 qbase + (size_t)(i0 + r + sIt * 16) * QKV_COLS + h * 64 + c4);
        }
        #pragma unroll
        for (int sIt = 0; sIt < 4; sIt++) {
            int rr = kvr + sIt * 16;
            cp16(&Ks[rr * FS + kvc4], kbase + (size_t)rr * QKV_COLS + kvc4);
        }
        CP_COMMIT;
        #pragma unroll
        for (int sIt = 0; sIt < 4; sIt++) {
            int rr = kvr + sIt * 16;
            cp16(&Vt[rr * FS + kvc4], vbase + (size_t)rr * NN + kvc4);
        }
        #pragma unroll
        for (int sIt = 0; sIt < 8; sIt++) {
            int rr = kvr + sIt * 16;
            cp16(&Ps[rr * FS + kvc4], bbase + (size_t)rr * NN + kvc4);
        }
        CP_COMMIT;
    }

    float accO[8][4];
    #pragma unroll
    for (int i = 0; i < 8; i++)
        #pragma unroll
        for (int j = 0; j < 4; j++) accO[i][j] = 0.f;
    float mrow0 = NEG_INF, mrow1 = NEG_INF;
    float lrow0 = 0.f, lrow1 = 0.f;

    for (int jt = 0; jt < 16; jt++) {
        CP_WAIT1;                                          // K(jt) (and Q) ready
        __syncthreads();

        // S = Q @ K^T via LDSM fragments
        float s[8][4];
        #pragma unroll
        for (int i = 0; i < 8; i++)
            #pragma unroll
            for (int j = 0; j < 4; j++) s[i][j] = 0.f;
        #pragma unroll
        for (int ks = 0; ks < 8; ks++) {
            const unsigned ko = ks * 32;
            unsigned a0, a1, a2, a3;
            ldsm4(a0, a1, a2, a3, qs_b + aoff + ko);
            #pragma unroll
            for (int nbp = 0; nbp < 4; nbp++) {
                unsigned b0, b1, c0, c1;
                ldsm4(b0, b1, c0, c1, ks_b + boff + (unsigned)(nbp * 16 * FS) * 4 + ko);
                float* S0 = s[2 * nbp];
                float* S1 = s[2 * nbp + 1];
                mma8(S0[0], S0[1], S0[2], S0[3], a0, a1, a2, a3, b0, b1);
                mma8(S1[0], S1[1], S1[2], S1[3], a0, a1, a2, a3, c0, c1);
            }
        }
        CP_WAIT0;                                          // V+bias(jt) ready
        __syncthreads();                                   // all warps done with Ks

        // prefetch K(jt+1) — hides under softmax + PV
        if (jt < 15) {
            const float* kn = kbase + (size_t)(jt + 1) * 64 * QKV_COLS;
            #pragma unroll
            for (int sIt = 0; sIt < 4; sIt++) {
                int rr = kvr + sIt * 16;
                cp16(&Ks[rr * FS + kvc4], kn + (size_t)rr * QKV_COLS + kvc4);
            }
            CP_COMMIT;
        }

        // + bias, row max
        float mx0 = NEG_INF, mx1 = NEG_INF;
        #pragma unroll
        for (int nb = 0; nb < 8; nb++) {
            int c = nb * 8 + 2 * t;
            float2 bA = *(float2*)&Ps[(m0 + g) * FS + c];
            float2 bB = *(float2*)&Ps[(m0 + g + 8) * FS + c];
            s[nb][0] += bA.x;
            s[nb][1] += bA.y;
            s[nb][2] += bB.x;
            s[nb][3] += bB.y;
            mx0 = fmaxf(mx0, fmaxf(s[nb][0], s[nb][1]));
            mx1 = fmaxf(mx1, fmaxf(s[nb][2], s[nb][3]));
        }
        mx0 = fmaxf(mx0, __shfl_xor_sync(0xffffffffu, mx0, 1));
        mx0 = fmaxf(mx0, __shfl_xor_sync(0xffffffffu, mx0, 2));
        mx1 = fmaxf(mx1, __shfl_xor_sync(0xffffffffu, mx1, 1));
        mx1 = fmaxf(mx1, __shfl_xor_sync(0xffffffffu, mx1, 2));

        float mn0 = fmaxf(mrow0, mx0), mn1 = fmaxf(mrow1, mx1);
        float al0 = ex2((mrow0 - mn0) * LOG2E);
        float al1 = ex2((mrow1 - mn1) * LOG2E);
        mrow0 = mn0;
        mrow1 = mn1;

        float sum0 = 0.f, sum1 = 0.f;
        #pragma unroll
        for (int nb = 0; nb < 8; nb++) {
            float p0 = ex2((s[nb][0] - mn0) * LOG2E);
            float p1 = ex2((s[nb][1] - mn0) * LOG2E);
            float p2 = ex2((s[nb][2] - mn1) * LOG2E);
            float p3 = ex2((s[nb][3] - mn1) * LOG2E);
            sum0 += p0 + p1;
            sum1 += p2 + p3;
            int c = nb * 8 + 2 * t;
            *(float2*)&Ps[(m0 + g) * FS + c] = make_float2(to_tf32(p0), to_tf32(p1));
            *(float2*)&Ps[(m0 + g + 8) * FS + c] = make_float2(to_tf32(p2), to_tf32(p3));
        }
        sum0 += __shfl_xor_sync(0xffffffffu, sum0, 1);
        sum0 += __shfl_xor_sync(0xffffffffu, sum0, 2);
        sum1 += __shfl_xor_sync(0xffffffffu, sum1, 1);
        sum1 += __shfl_xor_sync(0xffffffffu, sum1, 2);
        lrow0 = lrow0 * al0 + sum0;
        lrow1 = lrow1 * al1 + sum1;

        #pragma unroll
        for (int nb = 0; nb < 8; nb++) {
            accO[nb][0] *= al0;
            accO[nb][1] *= al0;
            accO[nb][2] *= al1;
            accO[nb][3] *= al1;
        }
        __syncwarp();                                      // P rows warp-private
        // O += P @ V via LDSM
        #pragma unroll
        for (int ks = 0; ks < 8; ks++) {
            const unsigned ko = ks * 32;
            unsigned a0, a1, a2, a3;
            ldsm4(a0, a1, a2, a3, ps_b + aoff + ko);
            #pragma unroll
            for (int nbp = 0; nbp < 4; nbp++) {
                unsigned b0, b1, c0, c1;
                ldsm4(b0, b1, c0, c1, vt_b + boff + (unsigned)(nbp * 16 * FS) * 4 + ko);
                float* O0 = accO[2 * nbp];
                float* O1 = accO[2 * nbp + 1];
                mma8(O0[0], O0[1], O0[2], O0[3], a0, a1, a2, a3, b0, b1);
                mma8(O1[0], O1[1], O1[2], O1[3], a0, a1, a2, a3, c0, c1);
            }
        }
        __syncthreads();                                   // Vt + Ps fully consumed

        // prefetch V(jt+1) + bias(jt+1) — hides under next QK^T
        if (jt < 15) {
            const int j0n = (jt + 1) * 64;
            #pragma unroll
            for (int sIt = 0; sIt < 4; sIt++) {
                int rr = kvr + sIt * 16;
                cp16(&Vt[rr * FS + kvc4], vbase + (size_t)rr * NN + j0n + kvc4);
            }
            #pragma unroll
            for (int sIt = 0; sIt < 8; sIt++) {
                int rr = kvr + sIt * 16;
                cp16(&Ps[rr * FS + kvc4], bbase + (size_t)rr * NN + j0n + kvc4);
            }
            CP_COMMIT;
        }
    }

    // epilogue: normalize, split to bf16 hi/lo pairs
    float inv0 = 1.f / lrow0;
    float inv1 = 1.f / lrow1;
    #pragma unroll
    for (int nb = 0; nb < 8; nb++) {
        int cp = h * 32 + nb * 4 + t;
        int r0 = b * NN + i0 + m0 + g;
        int r1 = r0 + 8;
        {
            float o0 = accO[nb][0] * inv0, o1 = accO[nb][1] * inv0;
            unsigned hp = pack_bf16(o1, o0);
            float c0 = __uint_as_float(hp << 16);
            float c1 = __uint_as_float(hp & 0xFFFF0000u);
            unsigned lp = pack_bf16(o1 - c1, o0 - c0);
            g_atth[(size_t)r0 * 256 + cp] = hp;
            g_attl[(size_t)r0 * 256 + cp] = lp;
        }
        {
            float o0 = accO[nb][2] * inv1, o1 = accO[nb][3] * inv1;
            unsigned hp = pack_bf16(o1, o0);
            float c0 = __uint_as_float(hp << 16);
            float c1 = __uint_as_float(hp & 0xFFFF0000u);
            unsigned lp = pack_bf16(o1 - c1, o0 - c0);
            g_atth[(size_t)r1 * 256 + cp] = hp;
            g_attl[(size_t)r1 * 256 + cp] = lp;
        }
    }
}

// =====================================================================
extern "C" void kernel_launch(void* const* d_in, const int* in_sizes, int n_in,
                              void* d_out, int out_size) {
    (void)in_sizes; (void)n_in; (void)out_size;
    const float* x = (const float*)d_in[0];
    const unsigned char* mask = (const unsigned char*)d_in[1];
    const float* bias = (const float*)d_in[2];
    const float* Wq = (const float*)d_in[3];
    const float* Wkv = (const float*)d_in[4];
    const float* Wout = (const float*)d_in[5];
    const float* bout = (const float*)d_in[6];
    float* out = (float*)d_out;

    const int flash_smem = (128 + 64 + 64 + 128) * FS * 4;   // 104448
    cudaFuncSetAttribute(k_flash, cudaFuncAttributeMaxDynamicSharedMemorySize, flash_smem);
    cudaFuncSetAttribute(k_mid, cudaFuncAttributeMaxDynamicSharedMemorySize, GEMM_SMEM);
    cudaFuncSetAttribute(k_gemm_out, cudaFuncAttributeMaxDynamicSharedMemorySize, GEMM_SMEM);

    k_prep<<<1 + NROWS + 2048, 256>>>(mask, x, Wq, Wkv, Wout);
    k_mid<<<19 * 512, 256, GEMM_SMEM>>>(bias);
    k_flash<<<BB * HH * (NN / 128), 256, flash_smem>>>();
    k_gemm_out<<<(DOUT / 64) * (NROWS / 128), 256, GEMM_SMEM>>>(bout, out);
}

// round 10
// speedup vs baseline: 1.0497x; 1.0497x over previous
#include <cuda_runtime.h>
#include <cuda_bf16.h>
#include <cuda_fp16.h>

#define BB 8
#define NN 1024
#define DIN 512
#define HH 8
#define INNER 512
#define DOUT 512
#define NROWS (BB*NN)            // 8192
#define QKV_COLS 1536
#define SCALE 0.125f
#define LOG2E 1.4426950408889634f

// ---- scratch (device globals; no runtime allocation) ----
__device__ float g_qkv[(size_t)NROWS * QKV_COLS];           // q|k (tf32-rounded); V region unused
__device__ float g_vT[(size_t)BB * HH * 64 * NN];           // V^T per (b,h): [d][token], tf32
__device__ __half g_bias_h[(size_t)BB * HH * NN * NN];      // bias transposed+masked fp16, 128MB
__device__ unsigned g_xh[(size_t)NROWS * (DIN/2)];          // x hi bf16 pairs [row][kp]
__device__ unsigned g_xl[(size_t)NROWS * (DIN/2)];
__device__ unsigned g_wqkvh[(size_t)QKV_COLS * 256];        // [SCALE*Wq|Wkv] n-major [n][kp]
__device__ unsigned g_wqkvl[(size_t)QKV_COLS * 256];
__device__ unsigned g_wouth[(size_t)DOUT * 256];            // Wout n-major [n][kp]
__device__ unsigned g_woutl[(size_t)DOUT * 256];
__device__ unsigned g_atth[(size_t)NROWS * (INNER/2)];      // attention out hi pairs [row][kp]
__device__ unsigned g_attl[(size_t)NROWS * (INNER/2)];
__device__ unsigned char g_maskb[BB * NN];

// ---- helpers ----
__device__ __forceinline__ float to_tf32(float x) {
    unsigned u;
    asm("cvt.rna.tf32.f32 %0, %1;" : "=r"(u) : "f"(x));
    return __uint_as_float(u);
}
__device__ __forceinline__ float ex2(float x) {
    float y;
    asm("ex2.approx.ftz.f32 %0, %1;" : "=f"(y) : "f"(x));
    return y;
}
__device__ __forceinline__ unsigned pack_bf16(float hi_elem, float lo_elem) {
    unsigned r;
    asm("cvt.rn.bf16x2.f32 %0, %1, %2;" : "=r"(r) : "f"(hi_elem), "f"(lo_elem));
    return r;
}
__device__ __forceinline__ void cp16(void* sp, const void* gp) {
    unsigned s = (unsigned)__cvta_generic_to_shared(sp);
    asm volatile("cp.async.cg.shared.global [%0], [%1], 16;\n" :: "r"(s), "l"(gp));
}
#define CP_COMMIT asm volatile("cp.async.commit_group;\n")
#define CP_WAIT0  asm volatile("cp.async.wait_group 0;\n")
#define CP_WAIT1  asm volatile("cp.async.wait_group 1;\n")

__device__ __forceinline__ void ldsm4(unsigned& r0, unsigned& r1, unsigned& r2, unsigned& r3,
                                      unsigned saddr) {
    asm volatile("ldmatrix.sync.aligned.m8n8.x4.shared.b16 {%0,%1,%2,%3}, [%4];"
                 : "=r"(r0), "=r"(r1), "=r"(r2), "=r"(r3) : "r"(saddr));
}
__device__ __forceinline__ void mma8(float& c0, float& c1, float& c2, float& c3,
                                     unsigned a0, unsigned a1, unsigned a2, unsigned a3,
                                     unsigned b0, unsigned b1) {
    asm volatile(
        "mma.sync.aligned.m16n8k8.row.col.f32.tf32.tf32.f32 "
        "{%0,%1,%2,%3},{%4,%5,%6,%7},{%8,%9},{%0,%1,%2,%3};\n"
        : "+f"(c0), "+f"(c1), "+f"(c2), "+f"(c3)
        : "r"(a0), "r"(a1), "r"(a2), "r"(a3), "r"(b0), "r"(b1));
}
__device__ __forceinline__ void mma16bf(float& c0, float& c1, float& c2, float& c3,
                                        unsigned a0, unsigned a1, unsigned a2, unsigned a3,
                                        unsigned b0, unsigned b1) {
    asm volatile(
        "mma.sync.aligned.m16n8k16.row.col.f32.bf16.bf16.f32 "
        "{%0,%1,%2,%3},{%4,%5,%6,%7},{%8,%9},{%0,%1,%2,%3};\n"
        : "+f"(c0), "+f"(c1), "+f"(c2), "+f"(c3)
        : "r"(a0), "r"(a1), "r"(a2), "r"(a3), "r"(b0), "r"(b1));
}

// =====================================================================
// k_prep (compact: 1281 CTAs, 8 items/thread):
//  [CTA 0] mask expand; [1..1024] split x; [1025..1280] split W (n-major)
// =====================================================================
__global__ __launch_bounds__(256) void k_prep(const unsigned char* __restrict__ m,
                                              const float* __restrict__ x,
                                              const float* __restrict__ Wq,
                                              const float* __restrict__ Wkv,
                                              const float* __restrict__ Wout) {
    const int bid = blockIdx.x;
    if (bid == 0) {
        __shared__ int s_notI32, s_notF32;
        if (threadIdx.x == 0) { s_notI32 = 0; s_notF32 = 0; }
        __syncthreads();
        const unsigned* mw = (const unsigned*)m;
        int notI = 0, notF = 0;
        for (int i = threadIdx.x; i < BB * NN / 4; i += 256) {
            unsigned w = mw[i];
            if (w & 0xFFFFFF00u) notI = 1;
            if (w != 0u && w != 0x3F800000u) notF = 1;
        }
        if (notI) atomicOr(&s_notI32, 1);
        if (notF) atomicOr(&s_notF32, 1);
        __syncthreads();
        const int notI32 = s_notI32, notF32 = s_notF32;
        for (int i = threadIdx.x; i < BB * NN; i += 256) {
            unsigned char v;
            if (!notF32)      v = (((const unsigned*)m)[i] != 0u) ? 1 : 0;
            else if (!notI32) v = (((const int*)m)[i] != 0) ? 1 : 0;
            else              v = (m[i] != 0) ? 1 : 0;
            g_maskb[i] = v;
        }
    } else if (bid <= 1024) {
        // split x: 2,097,152 pairs / 1024 CTAs = 2048 each
        const int base = (bid - 1) * 2048;
        #pragma unroll
        for (int s = 0; s < 8; s++) {
            int idx = base + s * 256 + threadIdx.x;
            float2 v = ((const float2*)x)[idx];
            unsigned hp = pack_bf16(v.y, v.x);
            float b0 = __uint_as_float(hp << 16);
            float b1 = __uint_as_float(hp & 0xFFFF0000u);
            unsigned lp = pack_bf16(v.y - b1, v.x - b0);
            g_xh[idx] = hp;
            g_xl[idx] = lp;
        }
    } else {
        // split weights: 524,288 entries / 256 CTAs = 2048 each
        const int base = (bid - 1025) * 2048;
        const int total1 = 256 * QKV_COLS;
        #pragma unroll
        for (int s = 0; s < 8; s++) {
            int idx = base + s * 256 + threadIdx.x;
            float a, b;
            unsigned* dh;
            unsigned* dl;
            size_t off;
            if (idx < total1) {
                int kp = idx / QKV_COLS, n = idx % QKV_COLS;
                if (n < 512) {
                    a = Wq[(2 * kp) * 512 + n] * SCALE;
                    b = Wq[(2 * kp + 1) * 512 + n] * SCALE;
                } else {
                    int nn = n - 512;
                    a = Wkv[(2 * kp) * 1024 + nn];
                    b = Wkv[(2 * kp + 1) * 1024 + nn];
                }
                dh = g_wqkvh; dl = g_wqkvl;
                off = (size_t)n * 256 + kp;
            } else {
                int j = idx - total1;
                int kp = j / DOUT, n = j % DOUT;
                a = Wout[(2 * kp) * DOUT + n];
                b = Wout[(2 * kp + 1) * DOUT + n];
                dh = g_wouth; dl = g_woutl;
                off = (size_t)n * 256 + kp;
            }
            unsigned hp = pack_bf16(b, a);
            float a0 = __uint_as_float(hp << 16);
            float b0 = __uint_as_float(hp & 0xFFFF0000u);
            unsigned lp = pack_bf16(b - b0, a - a0);
            dh[off] = hp;
            dl[off] = lp;
        }
    }
}

// =====================================================================
// Shared GEMM core (bf16 hi/lo 3-mma, tile 128x64, 2-stage cp.async, LDSM).
// =====================================================================
#define GAS 20
#define BS2 20
#define GEMM_SMEM ((2*128*GAS*2 + 2*64*BS2*2) * 4)   // 61440 bytes
#define N_GEMM_CTAS ((QKV_COLS/64) * (NROWS/128))    // 1536

template <int MODE>   // 0 = QKV (tf32 q/k + V^T scatter), 1 = out-proj
__device__ __forceinline__ void gemm_core(unsigned* smg, int cbid,
                                          const unsigned* __restrict__ Agh,
                                          const unsigned* __restrict__ Agl,
                                          const unsigned* __restrict__ Bgh,
                                          const unsigned* __restrict__ Bgl,
                                          const float* __restrict__ bout,
                                          float* __restrict__ Cout) {
    unsigned* sAh = smg;
    unsigned* sAl = sAh + 2 * 128 * GAS;
    unsigned* sBh = sAl + 2 * 128 * GAS;
    unsigned* sBl = sBh + 2 * 64 * BS2;

    const int tid = threadIdx.x, lane = tid & 31, warp = tid >> 5;
    const int g = lane >> 2, t = lane & 3;
    const int ncb = (MODE == 0) ? (QKV_COLS / 64) : (DOUT / 64);
    const int cb = (cbid % ncb) * 64;
    const int rb = (cbid / ncb) * 128;
    const int m0 = warp * 16;

    const int ar0 = tid >> 2, ac4 = (tid & 3) * 4;
    const int brB = tid >> 2, bc4 = (tid & 3) * 4;

    auto load_stage = [&](int st, int kt) {
        const int kp0 = kt * 16;
        unsigned* pAh = sAh + st * 128 * GAS;
        unsigned* pAl = sAl + st * 128 * GAS;
        #pragma unroll
        for (int sIt = 0; sIt < 2; sIt++) {
            int r = ar0 + sIt * 64;
            size_t go = (size_t)(rb + r) * 256 + kp0 + ac4;
            cp16(&pAh[r * GAS + ac4], Agh + go);
            cp16(&pAl[r * GAS + ac4], Agl + go);
        }
        size_t go = (size_t)(cb + brB) * 256 + kp0 + bc4;
        cp16(&sBh[st * 64 * BS2 + brB * BS2 + bc4], Bgh + go);
        cp16(&sBl[st * 64 * BS2 + brB * BS2 + bc4], Bgl + go);
    };

    const unsigned aoff = ((unsigned)((m0 + (lane & 15)) * GAS + ((lane & 16) >> 2))) * 4;
    const unsigned boff = ((unsigned)(((lane & 7) + ((lane & 16) >> 1)) * BS2 + ((lane & 8) >> 1))) * 4;
    const unsigned sAh_b = (unsigned)__cvta_generic_to_shared(sAh);
    const unsigned sAl_b = (unsigned)__cvta_generic_to_shared(sAl);
    const unsigned sBh_b = (unsigned)__cvta_generic_to_shared(sBh);
    const unsigned sBl_b = (unsigned)__cvta_generic_to_shared(sBl);

    float acc[8][4];
    #pragma unroll
    for (int i = 0; i < 8; i++)
        #pragma unroll
        for (int j = 0; j < 4; j++) acc[i][j] = 0.f;

    load_stage(0, 0);
    CP_COMMIT;

    for (int kt = 0; kt < 16; kt++) {
        CP_WAIT0;
        __syncthreads();
        if (kt < 15) { load_stage((kt + 1) & 1, kt + 1); CP_COMMIT; }

        const unsigned stA = (kt & 1) * 128 * GAS * 4;
        const unsigned stB = (kt & 1) * 64 * BS2 * 4;

        #pragma unroll
        for (int kc = 0; kc < 2; kc++) {
            const unsigned ko = kc * 8 * 4;
            unsigned ah0, ah1, ah2, ah3, al0, al1, al2, al3;
            ldsm4(ah0, ah1, ah2, ah3, sAh_b + stA + aoff + ko);
            ldsm4(al0, al1, al2, al3, sAl_b + stA + aoff + ko);
            #pragma unroll
            for (int nbp = 0; nbp < 4; nbp++) {
                const unsigned bo = boff + (unsigned)(nbp * 16 * BS2) * 4 + ko;
                unsigned bh0, bh1, bh2, bh3, bl0, bl1, bl2, bl3;
                ldsm4(bh0, bh1, bh2, bh3, sBh_b + stB + bo);
                ldsm4(bl0, bl1, bl2, bl3, sBl_b + stB + bo);
                float* A0 = acc[2 * nbp];
                float* A1 = acc[2 * nbp + 1];
                mma16bf(A0[0], A0[1], A0[2], A0[3], ah0, ah1, ah2, ah3, bh0, bh1);
                mma16bf(A0[0], A0[1], A0[2], A0[3], ah0, ah1, ah2, ah3, bl0, bl1);
                mma16bf(A0[0], A0[1], A0[2], A0[3], al0, al1, al2, al3, bh0, bh1);
                mma16bf(A1[0], A1[1], A1[2], A1[3], ah0, ah1, ah2, ah3, bh2, bh3);
                mma16bf(A1[0], A1[1], A1[2], A1[3], ah0, ah1, ah2, ah3, bl2, bl3);
                mma16bf(A1[0], A1[1], A1[2], A1[3], al0, al1, al2, al3, bh2, bh3);
            }
        }
        __syncthreads();
    }

    if (MODE == 0) {
        if (cb < 1024) {
            #pragma unroll
            for (int nb = 0; nb < 8; nb++) {
                int col = cb + nb * 8 + 2 * t;
                int r0 = rb + m0 + g;
                int r1 = r0 + 8;
                *(float2*)(g_qkv + (size_t)r0 * QKV_COLS + col) =
                    make_float2(to_tf32(acc[nb][0]), to_tf32(acc[nb][1]));
                *(float2*)(g_qkv + (size_t)r1 * QKV_COLS + col) =
                    make_float2(to_tf32(acc[nb][2]), to_tf32(acc[nb][3]));
            }
        } else {
            int h = (cb - 1024) >> 6;
            int r0 = rb + m0 + g;
            int b = r0 >> 10, n = r0 & 1023;
            float* vt = g_vT + (size_t)(b * 8 + h) * 64 * NN;
            #pragma unroll
            for (int nb = 0; nb < 8; nb++) {
                int d = nb * 8 + 2 * t;
                vt[(size_t)d * NN + n] = to_tf32(acc[nb][0]);
                vt[(size_t)(d + 1) * NN + n] = to_tf32(acc[nb][1]);
                vt[(size_t)d * NN + n + 8] = to_tf32(acc[nb][2]);
                vt[(size_t)(d + 1) * NN + n + 8] = to_tf32(acc[nb][3]);
            }
        }
    } else {
        #pragma unroll
        for (int nb = 0; nb < 8; nb++) {
            int col = cb + nb * 8 + 2 * t;
            float b0v = bout[col], b1v = bout[col + 1];
            int r0 = rb + m0 + g;
            int r1 = r0 + 8;
            *(float2*)(Cout + (size_t)r0 * DOUT + col) = make_float2(acc[nb][0] + b0v, acc[nb][1] + b1v);
            *(float2*)(Cout + (size_t)r1 * DOUT + col) = make_float2(acc[nb][2] + b0v, acc[nb][3] + b1v);
        }
    }
}

// =====================================================================
// k_mid: interleaved QKV GEMM (tensor) + bias transpose (DRAM, fp16 out).
// bias_h[b,h,i,j] = mask[b,j] ? fp16(sim_bias[b,i,j,h]) : -60000
// =====================================================================
__global__ __launch_bounds__(256, 2) void k_mid(const float* __restrict__ bias) {
    extern __shared__ unsigned smg[];
    const int bid = blockIdx.x;
    const int tid = threadIdx.x;
    const int grp = bid / 19, rem = bid % 19;

    if (rem < 3) {
        gemm_core<0>(smg, grp * 3 + rem, g_xh, g_xl, g_wqkvh, g_wqkvl, nullptr, nullptr);
    } else {
        float* s = (float*)smg;
        unsigned char* ms = (unsigned char*)smg + NN * 9 * 4;
        const int bi = grp * 16 + (rem - 3);
        const int b = bi >> 10;
        const float* src = bias + (size_t)bi * (NN * HH);

        #pragma unroll
        for (int sIt = 0; sIt < 8; sIt++) {
            int idx = tid + sIt * 256;
            float4 v = *(const float4*)(src + idx * 4);
            int j = idx >> 1;
            int h = (idx & 1) * 4;
            s[j * 9 + h + 0] = v.x;
            s[j * 9 + h + 1] = v.y;
            s[j * 9 + h + 2] = v.z;
            s[j * 9 + h + 3] = v.w;
        }
        for (int j = tid; j < NN; j += 256) ms[j] = g_maskb[b * NN + j];
        __syncthreads();

        const int i = bi & (NN - 1);
        #pragma unroll
        for (int h = 0; h < HH; h++) {
            __half* dst = g_bias_h + (((size_t)(b * HH + h)) * NN + i) * NN;
            #pragma unroll
            for (int r = 0; r < 4; r++) {
                int j = tid + r * 256;
                float v = ms[j] ? s[j * 9 + h] : -60000.0f;
                dst[j] = __float2half_rn(v);
            }
        }
    }
}

__global__ __launch_bounds__(256, 2) void k_gemm_out(const float* __restrict__ bout,
                                                     float* __restrict__ Cout) {
    extern __shared__ unsigned smg[];
    gemm_core<1>(smg, blockIdx.x, g_atth, g_attl, g_wouth, g_woutl, bout, Cout);
}

// =====================================================================
// Flash attention (round-7 pipeline). CTA = (b,h,i-tile 128), 256 thr.
// Bias is fp16, staged into the P region with the SAME FS row stride
// (128B payload per 272B row); each warp reads bias only for its own rows,
// and the shfl max-reduce warp-orders bias-consume before P-overwrite.
// =====================================================================
#define FS 68
__global__ __launch_bounds__(256, 2) void k_flash() {
    extern __shared__ float sm[];
    float* Qs = sm;                       // 128*FS
    float* Ks = Qs + 128 * FS;            // 64*FS
    float* Vt = Ks + 64 * FS;             // 64*FS  V^T [d][j]
    float* Ps = Vt + 64 * FS;             // 128*FS (fp16 bias overlay + P f32)

    const int tid = threadIdx.x, lane = tid & 31, warp = tid >> 5;
    const int g = lane >> 2, t = lane & 3;
    const int it = blockIdx.x & 7;
    const int bh = blockIdx.x >> 3;
    const int b = bh >> 3, h = bh & 7;
    const int i0 = it * 128;
    const int m0 = warp * 16;
    const float NEG_INF = __int_as_float(0xff800000);

    const float* qbase = g_qkv + (size_t)b * NN * QKV_COLS;
    const float* kbase = qbase + 512 + h * 64;
    const float* vbase = g_vT + (size_t)bh * 64 * NN;
    const __half* bbase = g_bias_h + ((size_t)bh * NN + i0) * NN;

    const unsigned aoff = ((unsigned)((m0 + (lane & 15)) * FS + ((lane & 16) >> 2))) * 4;
    const unsigned boff = ((unsigned)(((lane & 7) + ((lane & 16) >> 1)) * FS + ((lane & 8) >> 1))) * 4;
    const unsigned qs_b = (unsigned)__cvta_generic_to_shared(Qs);
    const unsigned ks_b = (unsigned)__cvta_generic_to_shared(Ks);
    const unsigned vt_b = (unsigned)__cvta_generic_to_shared(Vt);
    const unsigned ps_b = (unsigned)__cvta_generic_to_shared(Ps);

    // Q tile via cp.async (own group)
    {
        int r = tid >> 4, c4 = (tid & 15) * 4;
        #pragma unroll
        for (int sIt = 0; sIt < 8; sIt++) {
            cp16(&Qs[(r + sIt * 16) * FS + c4],
                 qbase + (size_t)(i0 + r + sIt * 16) * QKV_COLS + h * 64 + c4);
        }
    }
    CP_COMMIT;

    float accO[8][4];
    #pragma unroll
    for (int i = 0; i < 8; i++)
        #pragma unroll
        for (int j = 0; j < 4; j++) accO[i][j] = 0.f;
    float mrow0 = NEG_INF, mrow1 = NEG_INF;
    float lrow0 = 0.f, lrow1 = 0.f;

    const int kvr = tid >> 4, kvc4 = (tid & 15) * 4;
    // bias chunk coords: 128 rows x 8 16B-chunks = 1024 chunks, 4/thread
    const int bbr = tid >> 1, bbc8 = (tid & 1) * 8;      // row, half-col base (x8 halves/chunk, 2 chunks per 16 halves...)

    for (int jt = 0; jt < 16; jt++) {
        const int j0 = jt * 64;
        __syncthreads();                                   // buffers free
        #pragma unroll
        for (int sIt = 0; sIt < 4; sIt++) {
            int r = kvr + sIt * 16;
            cp16(&Ks[r * FS + kvc4], kbase + (size_t)(j0 + r) * QKV_COLS + kvc4);
            cp16(&Vt[r * FS + kvc4], vbase + (size_t)r * NN + j0 + kvc4);
        }
        CP_COMMIT;                                         // group: K/V
        // bias fp16: 128 rows x 64 halves (128B) = 8 chunks/row... 1024 chunks, 4/thread
        #pragma unroll
        for (int sIt = 0; sIt < 4; sIt++) {
            int idx = tid + sIt * 256;                     // chunk id 0..1023
            int r = idx >> 3;                              // row 0..127
            int c8 = (idx & 7) * 8;                        // half-col 0,8,...,56
            cp16((__half*)(Ps + r * FS) + c8, bbase + (size_t)r * NN + j0 + c8);
        }
        CP_COMMIT;                                         // group: bias
        CP_WAIT1;                                          // Q + K/V landed
        __syncthreads();

        // S = Q @ K^T via LDSM fragments
        float s[8][4];
        #pragma unroll
        for (int i = 0; i < 8; i++)
            #pragma unroll
            for (int j = 0; j < 4; j++) s[i][j] = 0.f;
        #pragma unroll
        for (int ks = 0; ks < 8; ks++) {
            const unsigned ko = ks * 32;
            unsigned a0, a1, a2, a3;
            ldsm4(a0, a1, a2, a3, qs_b + aoff + ko);
            #pragma unroll
            for (int nbp = 0; nbp < 4; nbp++) {
                unsigned b0, b1, c0, c1;
                ldsm4(b0, b1, c0, c1, ks_b + boff + (unsigned)(nbp * 16 * FS) * 4 + ko);
                float* S0 = s[2 * nbp];
                float* S1 = s[2 * nbp + 1];
                mma8(S0[0], S0[1], S0[2], S0[3], a0, a1, a2, a3, b0, b1);
                mma8(S1[0], S1[1], S1[2], S1[3], a0, a1, a2, a3, c0, c1);
            }
        }
        CP_WAIT0;                                          // bias landed
        __syncthreads();

        // + bias (fp16 -> f32), row max
        float mx0 = NEG_INF, mx1 = NEG_INF;
        #pragma unroll
        for (int nb = 0; nb < 8; nb++) {
            int c = nb * 8 + 2 * t;
            float2 fA = __half22float2(*(__half2*)((__half*)(Ps + (m0 + g) * FS) + c));
            float2 fB = __half22float2(*(__half2*)((__half*)(Ps + (m0 + g + 8) * FS) + c));
            s[nb][0] += fA.x;
            s[nb][1] += fA.y;
            s[nb][2] += fB.x;
            s[nb][3] += fB.y;
            mx0 = fmaxf(mx0, fmaxf(s[nb][0], s[nb][1]));
            mx1 = fmaxf(mx1, fmaxf(s[nb][2], s[nb][3]));
        }
        mx0 = fmaxf(mx0, __shfl_xor_sync(0xffffffffu, mx0, 1));
        mx0 = fmaxf(mx0, __shfl_xor_sync(0xffffffffu, mx0, 2));
        mx1 = fmaxf(mx1, __shfl_xor_sync(0xffffffffu, mx1, 1));
        mx1 = fmaxf(mx1, __shfl_xor_sync(0xffffffffu, mx1, 2));
        // (the shfl chain warp-orders all bias reads before the P writes below)

        float mn0 = fmaxf(mrow0, mx0), mn1 = fmaxf(mrow1, mx1);
        float al0 = ex2((mrow0 - mn0) * LOG2E);
        float al1 = ex2((mrow1 - mn1) * LOG2E);
        mrow0 = mn0;
        mrow1 = mn1;

        float sum0 = 0.f, sum1 = 0.f;
        #pragma unroll
        for (int nb = 0; nb < 8; nb++) {
            float p0 = ex2((s[nb][0] - mn0) * LOG2E);
            float p1 = ex2((s[nb][1] - mn0) * LOG2E);
            float p2 = ex2((s[nb][2] - mn1) * LOG2E);
            float p3 = ex2((s[nb][3] - mn1) * LOG2E);
            sum0 += p0 + p1;
            sum1 += p2 + p3;
            int c = nb * 8 + 2 * t;
            *(float2*)&Ps[(m0 + g) * FS + c] = make_float2(to_tf32(p0), to_tf32(p1));
            *(float2*)&Ps[(m0 + g + 8) * FS + c] = make_float2(to_tf32(p2), to_tf32(p3));
        }
        sum0 += __shfl_xor_sync(0xffffffffu, sum0, 1);
        sum0 += __shfl_xor_sync(0xffffffffu, sum0, 2);
        sum1 += __shfl_xor_sync(0xffffffffu, sum1, 1);
        sum1 += __shfl_xor_sync(0xffffffffu, sum1, 2);
        lrow0 = lrow0 * al0 + sum0;
        lrow1 = lrow1 * al1 + sum1;

        #pragma unroll
        for (int nb = 0; nb < 8; nb++) {
            accO[nb][0] *= al0;
            accO[nb][1] *= al0;
            accO[nb][2] *= al1;
            accO[nb][3] *= al1;
        }
        __syncwarp();                                      // P rows warp-private
        // O += P @ V via LDSM
        #pragma unroll
        for (int ks = 0; ks < 8; ks++) {
            const unsigned ko = ks * 32;
            unsigned a0, a1, a2, a3;
            ldsm4(a0, a1, a2, a3, ps_b + aoff + ko);
            #pragma unroll
            for (int nbp = 0; nbp < 4; nbp++) {
                unsigned b0, b1, c0, c1;
                ldsm4(b0, b1, c0, c1, vt_b + boff + (unsigned)(nbp * 16 * FS) * 4 + ko);
                float* O0 = accO[2 * nbp];
                float* O1 = accO[2 * nbp + 1];
                mma8(O0[0], O0[1], O0[2], O0[3], a0, a1, a2, a3, b0, b1);
                mma8(O1[0], O1[1], O1[2], O1[3], a0, a1, a2, a3, c0, c1);
            }
        }
    }

    // epilogue: normalize, split to bf16 hi/lo pairs
    float inv0 = 1.f / lrow0;
    float inv1 = 1.f / lrow1;
    #pragma unroll
    for (int nb = 0; nb < 8; nb++) {
        int cp = h * 32 + nb * 4 + t;
        int r0 = b * NN + i0 + m0 + g;
        int r1 = r0 + 8;
        {
            float o0 = accO[nb][0] * inv0, o1 = accO[nb][1] * inv0;
            unsigned hp = pack_bf16(o1, o0);
            float c0 = __uint_as_float(hp << 16);
            float c1 = __uint_as_float(hp & 0xFFFF0000u);
            unsigned lp = pack_bf16(o1 - c1, o0 - c0);
            g_atth[(size_t)r0 * 256 + cp] = hp;
            g_attl[(size_t)r0 * 256 + cp] = lp;
        }
        {
            float o0 = accO[nb][2] * inv1, o1 = accO[nb][3] * inv1;
            unsigned hp = pack_bf16(o1, o0);
            float c0 = __uint_as_float(hp << 16);
            float c1 = __uint_as_float(hp & 0xFFFF0000u);
            unsigned lp = pack_bf16(o1 - c1, o0 - c0);
            g_atth[(size_t)r1 * 256 + cp] = hp;
            g_attl[(size_t)r1 * 256 + cp] = lp;
        }
    }
}

// =====================================================================
extern "C" void kernel_launch(void* const* d_in, const int* in_sizes, int n_in,
                              void* d_out, int out_size) {
    (void)in_sizes; (void)n_in; (void)out_size;
    const float* x = (const float*)d_in[0];
    const unsigned char* mask = (const unsigned char*)d_in[1];
    const float* bias = (const float*)d_in[2];
    const float* Wq = (const float*)d_in[3];
    const float* Wkv = (const float*)d_in[4];
    const float* Wout = (const float*)d_in[5];
    const float* bout = (const float*)d_in[6];
    float* out = (float*)d_out;

    const int flash_smem = (128 + 64 + 64 + 128) * FS * 4;   // 104448
    cudaFuncSetAttribute(k_flash, cudaFuncAttributeMaxDynamicSharedMemorySize, flash_smem);
    cudaFuncSetAttribute(k_mid, cudaFuncAttributeMaxDynamicSharedMemorySize, GEMM_SMEM);
    cudaFuncSetAttribute(k_gemm_out, cudaFuncAttributeMaxDynamicSharedMemorySize, GEMM_SMEM);

    k_prep<<<1281, 256>>>(mask, x, Wq, Wkv, Wout);
    k_mid<<<19 * 512, 256, GEMM_SMEM>>>(bias);
    k_flash<<<BB * HH * (NN / 128), 256, flash_smem>>>();
    k_gemm_out<<<(DOUT / 64) * (NROWS / 128), 256, GEMM_SMEM>>>(bout, out);
}

// round 11
// speedup vs baseline: 1.2382x; 1.1796x over previous
#include <cuda_runtime.h>
#include <cuda_bf16.h>
#include <cuda_fp16.h>

#define BB 8
#define NN 1024
#define DIN 512
#define HH 8
#define INNER 512
#define DOUT 512
#define NROWS (BB*NN)            // 8192
#define SCALE 0.125f
#define LOG2E 1.4426950408889634f
#define QKCOLS 1024              // q|k halves per row

// ---- scratch (device globals; no runtime allocation) ----
__device__ __half g_qk[(size_t)NROWS * QKCOLS];             // q|k fp16, 16MB
__device__ __half g_vTh[(size_t)BB * HH * 64 * NN];         // V^T fp16 per (b,h): [d][token], 8MB
__device__ __half g_bias_h[(size_t)BB * HH * NN * NN];      // bias transposed+masked fp16, 128MB
__device__ unsigned g_xh[(size_t)NROWS * (DIN/2)];          // x hi bf16 pairs [row][kp]
__device__ unsigned g_xl[(size_t)NROWS * (DIN/2)];
__device__ unsigned g_wqkvh[(size_t)(3*DIN) * 256];         // [SCALE*Wq|Wkv] n-major [n][kp]
__device__ unsigned g_wqkvl[(size_t)(3*DIN) * 256];
__device__ unsigned g_wouth[(size_t)DOUT * 256];            // Wout n-major [n][kp]
__device__ unsigned g_woutl[(size_t)DOUT * 256];
__device__ unsigned g_atth[(size_t)NROWS * (INNER/2)];      // attention out hi pairs [row][kp]
__device__ unsigned g_attl[(size_t)NROWS * (INNER/2)];
__device__ unsigned char g_maskb[BB * NN];

#define QKV_COLS 1536

// ---- helpers ----
__device__ __forceinline__ float to_tf32(float x) {
    unsigned u;
    asm("cvt.rna.tf32.f32 %0, %1;" : "=r"(u) : "f"(x));
    return __uint_as_float(u);
}
__device__ __forceinline__ float ex2(float x) {
    float y;
    asm("ex2.approx.ftz.f32 %0, %1;" : "=f"(y) : "f"(x));
    return y;
}
__device__ __forceinline__ unsigned pack_bf16(float hi_elem, float lo_elem) {
    unsigned r;
    asm("cvt.rn.bf16x2.f32 %0, %1, %2;" : "=r"(r) : "f"(hi_elem), "f"(lo_elem));
    return r;
}
__device__ __forceinline__ void cp16(void* sp, const void* gp) {
    unsigned s = (unsigned)__cvta_generic_to_shared(sp);
    asm volatile("cp.async.cg.shared.global [%0], [%1], 16;\n" :: "r"(s), "l"(gp));
}
#define CP_COMMIT asm volatile("cp.async.commit_group;\n")
#define CP_WAIT0  asm volatile("cp.async.wait_group 0;\n")
#define CP_WAIT1  asm volatile("cp.async.wait_group 1;\n")

__device__ __forceinline__ void ldsm4(unsigned& r0, unsigned& r1, unsigned& r2, unsigned& r3,
                                      unsigned saddr) {
    asm volatile("ldmatrix.sync.aligned.m8n8.x4.shared.b16 {%0,%1,%2,%3}, [%4];"
                 : "=r"(r0), "=r"(r1), "=r"(r2), "=r"(r3) : "r"(saddr));
}
__device__ __forceinline__ void mma16f(float& c0, float& c1, float& c2, float& c3,
                                       unsigned a0, unsigned a1, unsigned a2, unsigned a3,
                                       unsigned b0, unsigned b1) {
    asm volatile(
        "mma.sync.aligned.m16n8k16.row.col.f32.f16.f16.f32 "
        "{%0,%1,%2,%3},{%4,%5,%6,%7},{%8,%9},{%0,%1,%2,%3};\n"
        : "+f"(c0), "+f"(c1), "+f"(c2), "+f"(c3)
        : "r"(a0), "r"(a1), "r"(a2), "r"(a3), "r"(b0), "r"(b1));
}
__device__ __forceinline__ void mma16bf(float& c0, float& c1, float& c2, float& c3,
                                        unsigned a0, unsigned a1, unsigned a2, unsigned a3,
                                        unsigned b0, unsigned b1) {
    asm volatile(
        "mma.sync.aligned.m16n8k16.row.col.f32.bf16.bf16.f32 "
        "{%0,%1,%2,%3},{%4,%5,%6,%7},{%8,%9},{%0,%1,%2,%3};\n"
        : "+f"(c0), "+f"(c1), "+f"(c2), "+f"(c3)
        : "r"(a0), "r"(a1), "r"(a2), "r"(a3), "r"(b0), "r"(b1));
}

// =====================================================================
// k_prep (compact: 1281 CTAs, 8 items/thread):
//  [CTA 0] mask expand; [1..1024] split x; [1025..1280] split W (n-major)
// =====================================================================
__global__ __launch_bounds__(256) void k_prep(const unsigned char* __restrict__ m,
                                              const float* __restrict__ x,
                                              const float* __restrict__ Wq,
                                              const float* __restrict__ Wkv,
                                              const float* __restrict__ Wout) {
    const int bid = blockIdx.x;
    if (bid == 0) {
        __shared__ int s_notI32, s_notF32;
        if (threadIdx.x == 0) { s_notI32 = 0; s_notF32 = 0; }
        __syncthreads();
        const unsigned* mw = (const unsigned*)m;
        int notI = 0, notF = 0;
        for (int i = threadIdx.x; i < BB * NN / 4; i += 256) {
            unsigned w = mw[i];
            if (w & 0xFFFFFF00u) notI = 1;
            if (w != 0u && w != 0x3F800000u) notF = 1;
        }
        if (notI) atomicOr(&s_notI32, 1);
        if (notF) atomicOr(&s_notF32, 1);
        __syncthreads();
        const int notI32 = s_notI32, notF32 = s_notF32;
        for (int i = threadIdx.x; i < BB * NN; i += 256) {
            unsigned char v;
            if (!notF32)      v = (((const unsigned*)m)[i] != 0u) ? 1 : 0;
            else if (!notI32) v = (((const int*)m)[i] != 0) ? 1 : 0;
            else              v = (m[i] != 0) ? 1 : 0;
            g_maskb[i] = v;
        }
    } else if (bid <= 1024) {
        const int base = (bid - 1) * 2048;
        #pragma unroll
        for (int s = 0; s < 8; s++) {
            int idx = base + s * 256 + threadIdx.x;
            float2 v = ((const float2*)x)[idx];
            unsigned hp = pack_bf16(v.y, v.x);
            float b0 = __uint_as_float(hp << 16);
            float b1 = __uint_as_float(hp & 0xFFFF0000u);
            unsigned lp = pack_bf16(v.y - b1, v.x - b0);
            g_xh[idx] = hp;
            g_xl[idx] = lp;
        }
    } else {
        const int base = (bid - 1025) * 2048;
        const int total1 = 256 * QKV_COLS;
        #pragma unroll
        for (int s = 0; s < 8; s++) {
            int idx = base + s * 256 + threadIdx.x;
            float a, b;
            unsigned* dh;
            unsigned* dl;
            size_t off;
            if (idx < total1) {
                int kp = idx / QKV_COLS, n = idx % QKV_COLS;
                if (n < 512) {
                    a = Wq[(2 * kp) * 512 + n] * SCALE;
                    b = Wq[(2 * kp + 1) * 512 + n] * SCALE;
                } else {
                    int nn = n - 512;
                    a = Wkv[(2 * kp) * 1024 + nn];
                    b = Wkv[(2 * kp + 1) * 1024 + nn];
                }
                dh = g_wqkvh; dl = g_wqkvl;
                off = (size_t)n * 256 + kp;
            } else {
                int j = idx - total1;
                int kp = j / DOUT, n = j % DOUT;
                a = Wout[(2 * kp) * DOUT + n];
                b = Wout[(2 * kp + 1) * DOUT + n];
                dh = g_wouth; dl = g_woutl;
                off = (size_t)n * 256 + kp;
            }
            unsigned hp = pack_bf16(b, a);
            float a0 = __uint_as_float(hp << 16);
            float b0 = __uint_as_float(hp & 0xFFFF0000u);
            unsigned lp = pack_bf16(b - b0, a - a0);
            dh[off] = hp;
            dl[off] = lp;
        }
    }
}

// =====================================================================
// Shared GEMM core (bf16 hi/lo 3-mma, tile 128x64, 2-stage cp.async, LDSM).
// MODE 0 epilogue: q/k -> g_qk fp16; v -> g_vTh fp16 transposed scatter.
// =====================================================================
#define GAS 20
#define BS2 20
#define GEMM_SMEM ((2*128*GAS*2 + 2*64*BS2*2) * 4)   // 61440 bytes

template <int MODE>
__device__ __forceinline__ void gemm_core(unsigned* smg, int cbid,
                                          const unsigned* __restrict__ Agh,
                                          const unsigned* __restrict__ Agl,
                                          const unsigned* __restrict__ Bgh,
                                          const unsigned* __restrict__ Bgl,
                                          const float* __restrict__ bout,
                                          float* __restrict__ Cout) {
    unsigned* sAh = smg;
    unsigned* sAl = sAh + 2 * 128 * GAS;
    unsigned* sBh = sAl + 2 * 128 * GAS;
    unsigned* sBl = sBh + 2 * 64 * BS2;

    const int tid = threadIdx.x, lane = tid & 31, warp = tid >> 5;
    const int g = lane >> 2, t = lane & 3;
    const int ncb = (MODE == 0) ? (QKV_COLS / 64) : (DOUT / 64);
    const int cb = (cbid % ncb) * 64;
    const int rb = (cbid / ncb) * 128;
    const int m0 = warp * 16;

    const int ar0 = tid >> 2, ac4 = (tid & 3) * 4;
    const int brB = tid >> 2, bc4 = (tid & 3) * 4;

    auto load_stage = [&](int st, int kt) {
        const int kp0 = kt * 16;
        unsigned* pAh = sAh + st * 128 * GAS;
        unsigned* pAl = sAl + st * 128 * GAS;
        #pragma unroll
        for (int sIt = 0; sIt < 2; sIt++) {
            int r = ar0 + sIt * 64;
            size_t go = (size_t)(rb + r) * 256 + kp0 + ac4;
            cp16(&pAh[r * GAS + ac4], Agh + go);
            cp16(&pAl[r * GAS + ac4], Agl + go);
        }
        size_t go = (size_t)(cb + brB) * 256 + kp0 + bc4;
        cp16(&sBh[st * 64 * BS2 + brB * BS2 + bc4], Bgh + go);
        cp16(&sBl[st * 64 * BS2 + brB * BS2 + bc4], Bgl + go);
    };

    const unsigned aoff = ((unsigned)((m0 + (lane & 15)) * GAS + ((lane & 16) >> 2))) * 4;
    const unsigned boff = ((unsigned)(((lane & 7) + ((lane & 16) >> 1)) * BS2 + ((lane & 8) >> 1))) * 4;
    const unsigned sAh_b = (unsigned)__cvta_generic_to_shared(sAh);
    const unsigned sAl_b = (unsigned)__cvta_generic_to_shared(sAl);
    const unsigned sBh_b = (unsigned)__cvta_generic_to_shared(sBh);
    const unsigned sBl_b = (unsigned)__cvta_generic_to_shared(sBl);

    float acc[8][4];
    #pragma unroll
    for (int i = 0; i < 8; i++)
        #pragma unroll
        for (int j = 0; j < 4; j++) acc[i][j] = 0.f;

    load_stage(0, 0);
    CP_COMMIT;

    for (int kt = 0; kt < 16; kt++) {
        CP_WAIT0;
        __syncthreads();
        if (kt < 15) { load_stage((kt + 1) & 1, kt + 1); CP_COMMIT; }

        const unsigned stA = (kt & 1) * 128 * GAS * 4;
        const unsigned stB = (kt & 1) * 64 * BS2 * 4;

        #pragma unroll
        for (int kc = 0; kc < 2; kc++) {
            const unsigned ko = kc * 8 * 4;
            unsigned ah0, ah1, ah2, ah3, al0, al1, al2, al3;
            ldsm4(ah0, ah1, ah2, ah3, sAh_b + stA + aoff + ko);
            ldsm4(al0, al1, al2, al3, sAl_b + stA + aoff + ko);
            #pragma unroll
            for (int nbp = 0; nbp < 4; nbp++) {
                const unsigned bo = boff + (unsigned)(nbp * 16 * BS2) * 4 + ko;
                unsigned bh0, bh1, bh2, bh3, bl0, bl1, bl2, bl3;
                ldsm4(bh0, bh1, bh2, bh3, sBh_b + stB + bo);
                ldsm4(bl0, bl1, bl2, bl3, sBl_b + stB + bo);
                float* A0 = acc[2 * nbp];
                float* A1 = acc[2 * nbp + 1];
                mma16bf(A0[0], A0[1], A0[2], A0[3], ah0, ah1, ah2, ah3, bh0, bh1);
                mma16bf(A0[0], A0[1], A0[2], A0[3], ah0, ah1, ah2, ah3, bl0, bl1);
                mma16bf(A0[0], A0[1], A0[2], A0[3], al0, al1, al2, al3, bh0, bh1);
                mma16bf(A1[0], A1[1], A1[2], A1[3], ah0, ah1, ah2, ah3, bh2, bh3);
                mma16bf(A1[0], A1[1], A1[2], A1[3], ah0, ah1, ah2, ah3, bl2, bl3);
                mma16bf(A1[0], A1[1], A1[2], A1[3], al0, al1, al2, al3, bh2, bh3);
            }
        }
        __syncthreads();
    }

    if (MODE == 0) {
        if (cb < 1024) {
            // q/k -> fp16
            #pragma unroll
            for (int nb = 0; nb < 8; nb++) {
                int col = cb + nb * 8 + 2 * t;
                int r0 = rb + m0 + g;
                int r1 = r0 + 8;
                *(__half2*)(g_qk + (size_t)r0 * QKCOLS + col) = __floats2half2_rn(acc[nb][0], acc[nb][1]);
                *(__half2*)(g_qk + (size_t)r1 * QKCOLS + col) = __floats2half2_rn(acc[nb][2], acc[nb][3]);
            }
        } else {
            // v -> V^T fp16 scatter
            int h = (cb - 1024) >> 6;
            int r0 = rb + m0 + g;
            int b = r0 >> 10, n = r0 & 1023;
            __half* vt = g_vTh + (size_t)(b * 8 + h) * 64 * NN;
            #pragma unroll
            for (int nb = 0; nb < 8; nb++) {
                int d = nb * 8 + 2 * t;
                vt[(size_t)d * NN + n] = __float2half_rn(acc[nb][0]);
                vt[(size_t)(d + 1) * NN + n] = __float2half_rn(acc[nb][1]);
                vt[(size_t)d * NN + n + 8] = __float2half_rn(acc[nb][2]);
                vt[(size_t)(d + 1) * NN + n + 8] = __float2half_rn(acc[nb][3]);
            }
        }
    } else {
        #pragma unroll
        for (int nb = 0; nb < 8; nb++) {
            int col = cb + nb * 8 + 2 * t;
            float b0v = bout[col], b1v = bout[col + 1];
            int r0 = rb + m0 + g;
            int r1 = r0 + 8;
            *(float2*)(Cout + (size_t)r0 * DOUT + col) = make_float2(acc[nb][0] + b0v, acc[nb][1] + b1v);
            *(float2*)(Cout + (size_t)r1 * DOUT + col) = make_float2(acc[nb][2] + b0v, acc[nb][3] + b1v);
        }
    }
}

// =====================================================================
// k_mid: interleaved QKV GEMM (tensor) + bias transpose (DRAM, fp16 out).
// =====================================================================
__global__ __launch_bounds__(256, 2) void k_mid(const float* __restrict__ bias) {
    extern __shared__ unsigned smg[];
    const int bid = blockIdx.x;
    const int tid = threadIdx.x;
    const int grp = bid / 19, rem = bid % 19;

    if (rem < 3) {
        gemm_core<0>(smg, grp * 3 + rem, g_xh, g_xl, g_wqkvh, g_wqkvl, nullptr, nullptr);
    } else {
        float* s = (float*)smg;
        unsigned char* ms = (unsigned char*)smg + NN * 9 * 4;
        const int bi = grp * 16 + (rem - 3);
        const int b = bi >> 10;
        const float* src = bias + (size_t)bi * (NN * HH);

        #pragma unroll
        for (int sIt = 0; sIt < 8; sIt++) {
            int idx = tid + sIt * 256;
            float4 v = *(const float4*)(src + idx * 4);
            int j = idx >> 1;
            int h = (idx & 1) * 4;
            s[j * 9 + h + 0] = v.x;
            s[j * 9 + h + 1] = v.y;
            s[j * 9 + h + 2] = v.z;
            s[j * 9 + h + 3] = v.w;
        }
        for (int j = tid; j < NN; j += 256) ms[j] = g_maskb[b * NN + j];
        __syncthreads();

        const int i = bi & (NN - 1);
        #pragma unroll
        for (int h = 0; h < HH; h++) {
            __half* dst = g_bias_h + (((size_t)(b * HH + h)) * NN + i) * NN;
            #pragma unroll
            for (int r = 0; r < 4; r++) {
                int j = tid + r * 256;
                float v = ms[j] ? s[j * 9 + h] : -60000.0f;
                dst[j] = __float2half_rn(v);
            }
        }
    }
}

__global__ __launch_bounds__(256, 2) void k_gemm_out(const float* __restrict__ bout,
                                                     float* __restrict__ Cout) {
    extern __shared__ unsigned smg[];
    gemm_core<1>(smg, blockIdx.x, g_atth, g_attl, g_wouth, g_woutl, bout, Cout);
}

// =====================================================================
// Flash attention, ALL-fp16 tiles + m16n8k16.f16 mma (same 11-bit mantissa
// as tf32 -> identical precision class, half the mma/ldsm instructions).
// CTA = (b,h,i-tile 128), 256 thr / 8 warps. Bias fp16 overlays P (both
// fp16 now, same region; round-10 aliasing discipline).
// =====================================================================
#define HS 72            // half stride per smem row (144B)
#define HSB 144
__global__ __launch_bounds__(256, 2) void k_flash() {
    extern __shared__ __half smh[];
    __half* Qs = smh;                     // 128*HS
    __half* Ks = Qs + 128 * HS;           // 64*HS  [token][d]
    __half* Vt = Ks + 64 * HS;            // 64*HS  [d][token]
    __half* Ps = Vt + 64 * HS;            // 128*HS (bias overlay + P)

    const int tid = threadIdx.x, lane = tid & 31, warp = tid >> 5;
    const int g = lane >> 2, t = lane & 3;
    const int it = blockIdx.x & 7;
    const int bh = blockIdx.x >> 3;
    const int b = bh >> 3, h = bh & 7;
    const int i0 = it * 128;
    const int m0 = warp * 16;
    const float NEG_INF = __int_as_float(0xff800000);

    const __half* qbase = g_qk + (size_t)b * NN * QKCOLS + h * 64;
    const __half* kbase = qbase + 512;
    const __half* vbase = g_vTh + (size_t)bh * 64 * NN;
    const __half* bbase = g_bias_h + ((size_t)bh * NN + i0) * NN;

    // ldmatrix byte offsets (fp16 geometry)
    const unsigned aoff = (unsigned)((m0 + (lane & 15)) * HSB + ((lane & 16) >> 4) * 16);
    const unsigned boff = (unsigned)(((lane & 7) + ((lane & 16) >> 1)) * HSB + ((lane & 8) >> 3) * 16);
    const unsigned qs_b = (unsigned)__cvta_generic_to_shared(Qs);
    const unsigned ks_b = (unsigned)__cvta_generic_to_shared(Ks);
    const unsigned vt_b = (unsigned)__cvta_generic_to_shared(Vt);
    const unsigned ps_b = (unsigned)__cvta_generic_to_shared(Ps);

    // Q tile: 128 rows x 64 halves = 1024 16B-chunks, 4/thread (own cp group)
    #pragma unroll
    for (int sIt = 0; sIt < 4; sIt++) {
        int idx = tid + sIt * 256;
        int r = idx >> 3, c8 = (idx & 7) * 8;
        cp16(&Qs[r * HS + c8], qbase + (size_t)(i0 + r) * QKCOLS + c8);
    }
    CP_COMMIT;

    float accO[8][4];
    #pragma unroll
    for (int i = 0; i < 8; i++)
        #pragma unroll
        for (int j = 0; j < 4; j++) accO[i][j] = 0.f;
    float mrow0 = NEG_INF, mrow1 = NEG_INF;
    float lrow0 = 0.f, lrow1 = 0.f;

    for (int jt = 0; jt < 16; jt++) {
        const int j0 = jt * 64;
        __syncthreads();                                   // buffers free
        // K + V: 64 rows x 8 chunks each = 512 chunks, 2/thread each
        #pragma unroll
        for (int sIt = 0; sIt < 2; sIt++) {
            int idx = tid + sIt * 256;
            int r = idx >> 3, c8 = (idx & 7) * 8;
            cp16(&Ks[r * HS + c8], kbase + (size_t)(j0 + r) * QKCOLS + c8);
            cp16(&Vt[r * HS + c8], vbase + (size_t)r * NN + j0 + c8);
        }
        CP_COMMIT;                                         // group: K/V
        // bias: 128 rows x 8 chunks = 1024 chunks, 4/thread
        #pragma unroll
        for (int sIt = 0; sIt < 4; sIt++) {
            int idx = tid + sIt * 256;
            int r = idx >> 3, c8 = (idx & 7) * 8;
            cp16(&Ps[r * HS + c8], bbase + (size_t)r * NN + j0 + c8);
        }
        CP_COMMIT;                                         // group: bias
        CP_WAIT1;                                          // Q + K/V landed
        __syncthreads();

        // S = Q @ K^T (fp16 mma16)
        float s[8][4];
        #pragma unroll
        for (int i = 0; i < 8; i++)
            #pragma unroll
            for (int j = 0; j < 4; j++) s[i][j] = 0.f;
        #pragma unroll
        for (int kc = 0; kc < 4; kc++) {
            const unsigned ko = kc * 32;                   // 16 halves = 32B
            unsigned a0, a1, a2, a3;
            ldsm4(a0, a1, a2, a3, qs_b + aoff + ko);
            #pragma unroll
            for (int nbp = 0; nbp < 4; nbp++) {
                unsigned b0, b1, c0, c1;
                ldsm4(b0, b1, c0, c1, ks_b + boff + (unsigned)(nbp * 16 * HSB) + ko);
                float* S0 = s[2 * nbp];
                float* S1 = s[2 * nbp + 1];
                mma16f(S0[0], S0[1], S0[2], S0[3], a0, a1, a2, a3, b0, b1);
                mma16f(S1[0], S1[1], S1[2], S1[3], a0, a1, a2, a3, c0, c1);
            }
        }
        CP_WAIT0;                                          // bias landed
        __syncthreads();

        // + bias (fp16), row max
        float mx0 = NEG_INF, mx1 = NEG_INF;
        #pragma unroll
        for (int nb = 0; nb < 8; nb++) {
            int c = nb * 8 + 2 * t;
            float2 fA = __half22float2(*(__half2*)&Ps[(m0 + g) * HS + c]);
            float2 fB = __half22float2(*(__half2*)&Ps[(m0 + g + 8) * HS + c]);
            s[nb][0] += fA.x;
            s[nb][1] += fA.y;
            s[nb][2] += fB.x;
            s[nb][3] += fB.y;
            mx0 = fmaxf(mx0, fmaxf(s[nb][0], s[nb][1]));
            mx1 = fmaxf(mx1, fmaxf(s[nb][2], s[nb][3]));
        }
        mx0 = fmaxf(mx0, __shfl_xor_sync(0xffffffffu, mx0, 1));
        mx0 = fmaxf(mx0, __shfl_xor_sync(0xffffffffu, mx0, 2));
        mx1 = fmaxf(mx1, __shfl_xor_sync(0xffffffffu, mx1, 1));
        mx1 = fmaxf(mx1, __shfl_xor_sync(0xffffffffu, mx1, 2));
        // (shfl chain warp-orders bias reads before P overwrite below)

        float mn0 = fmaxf(mrow0, mx0), mn1 = fmaxf(mrow1, mx1);
        float al0 = ex2((mrow0 - mn0) * LOG2E);
        float al1 = ex2((mrow1 - mn1) * LOG2E);
        mrow0 = mn0;
        mrow1 = mn1;

        float sum0 = 0.f, sum1 = 0.f;
        #pragma unroll
        for (int nb = 0; nb < 8; nb++) {
            float p0 = ex2((s[nb][0] - mn0) * LOG2E);
            float p1 = ex2((s[nb][1] - mn0) * LOG2E);
            float p2 = ex2((s[nb][2] - mn1) * LOG2E);
            float p3 = ex2((s[nb][3] - mn1) * LOG2E);
            sum0 += p0 + p1;
            sum1 += p2 + p3;
            int c = nb * 8 + 2 * t;
            *(__half2*)&Ps[(m0 + g) * HS + c] = __floats2half2_rn(p0, p1);
            *(__half2*)&Ps[(m0 + g + 8) * HS + c] = __floats2half2_rn(p2, p3);
        }
        sum0 += __shfl_xor_sync(0xffffffffu, sum0, 1);
        sum0 += __shfl_xor_sync(0xffffffffu, sum0, 2);
        sum1 += __shfl_xor_sync(0xffffffffu, sum1, 1);
        sum1 += __shfl_xor_sync(0xffffffffu, sum1, 2);
        lrow0 = lrow0 * al0 + sum0;
        lrow1 = lrow1 * al1 + sum1;

        #pragma unroll
        for (int nb = 0; nb < 8; nb++) {
            accO[nb][0] *= al0;
            accO[nb][1] *= al0;
            accO[nb][2] *= al1;
            accO[nb][3] *= al1;
        }
        __syncwarp();                                      // P rows warp-private
        // O += P @ V (fp16 mma16)
        #pragma unroll
        for (int kc = 0; kc < 4; kc++) {
            const unsigned ko = kc * 32;
            unsigned a0, a1, a2, a3;
            ldsm4(a0, a1, a2, a3, ps_b + aoff + ko);
            #pragma unroll
            for (int nbp = 0; nbp < 4; nbp++) {
                unsigned b0, b1, c0, c1;
                ldsm4(b0, b1, c0, c1, vt_b + boff + (unsigned)(nbp * 16 * HSB) + ko);
                float* O0 = accO[2 * nbp];
                float* O1 = accO[2 * nbp + 1];
                mma16f(O0[0], O0[1], O0[2], O0[3], a0, a1, a2, a3, b0, b1);
                mma16f(O1[0], O1[1], O1[2], O1[3], a0, a1, a2, a3, c0, c1);
            }
        }
    }

    // epilogue: normalize, split to bf16 hi/lo pairs
    float inv0 = 1.f / lrow0;
    float inv1 = 1.f / lrow1;
    #pragma unroll
    for (int nb = 0; nb < 8; nb++) {
        int cp = h * 32 + nb * 4 + t;
        int r0 = b * NN + i0 + m0 + g;
        int r1 = r0 + 8;
        {
            float o0 = accO[nb][0] * inv0, o1 = accO[nb][1] * inv0;
            unsigned hp = pack_bf16(o1, o0);
            float c0 = __uint_as_float(hp << 16);
            float c1 = __uint_as_float(hp & 0xFFFF0000u);
            unsigned lp = pack_bf16(o1 - c1, o0 - c0);
            g_atth[(size_t)r0 * 256 + cp] = hp;
            g_attl[(size_t)r0 * 256 + cp] = lp;
        }
        {
            float o0 = accO[nb][2] * inv1, o1 = accO[nb][3] * inv1;
            unsigned hp = pack_bf16(o1, o0);
            float c0 = __uint_as_float(hp << 16);
            float c1 = __uint_as_float(hp & 0xFFFF0000u);
            unsigned lp = pack_bf16(o1 - c1, o0 - c0);
            g_atth[(size_t)r1 * 256 + cp] = hp;
            g_attl[(size_t)r1 * 256 + cp] = lp;
        }
    }
}

// =====================================================================
extern "C" void kernel_launch(void* const* d_in, const int* in_sizes, int n_in,
                              void* d_out, int out_size) {
    (void)in_sizes; (void)n_in; (void)out_size;
    const float* x = (const float*)d_in[0];
    const unsigned char* mask = (const unsigned char*)d_in[1];
    const float* bias = (const float*)d_in[2];
    const float* Wq = (const float*)d_in[3];
    const float* Wkv = (const float*)d_in[4];
    const float* Wout = (const float*)d_in[5];
    const float* bout = (const float*)d_in[6];
    float* out = (float*)d_out;

    const int flash_smem = (128 + 64 + 64 + 128) * HS * 2;   // 55296
    cudaFuncSetAttribute(k_flash, cudaFuncAttributeMaxDynamicSharedMemorySize, flash_smem);
    cudaFuncSetAttribute(k_mid, cudaFuncAttributeMaxDynamicSharedMemorySize, GEMM_SMEM);
    cudaFuncSetAttribute(k_gemm_out, cudaFuncAttributeMaxDynamicSharedMemorySize, GEMM_SMEM);

    k_prep<<<1281, 256>>>(mask, x, Wq, Wkv, Wout);
    k_mid<<<19 * 512, 256, GEMM_SMEM>>>(bias);
    k_flash<<<BB * HH * (NN / 128), 256, flash_smem>>>();
    k_gemm_out<<<(DOUT / 64) * (NROWS / 128), 256, GEMM_SMEM>>>(bout, out);
}

// round 12
// speedup vs baseline: 1.3568x; 1.0957x over previous
#include <cuda_runtime.h>
#include <cuda_bf16.h>
#include <cuda_fp16.h>

#define BB 8
#define NN 1024
#define DIN 512
#define HH 8
#define INNER 512
#define DOUT 512
#define NROWS (BB*NN)            // 8192
#define SCALE 0.125f
#define LOG2E 1.4426950408889634f
#define QKCOLS 1024              // q|k halves per row
#define QKV_COLS 1536

// ---- scratch (device globals; no runtime allocation) ----
__device__ __half g_qk[(size_t)NROWS * QKCOLS];             // q|k fp16
__device__ __half g_vTh[(size_t)BB * HH * 64 * NN];         // V^T fp16 per (b,h): [d][token]
__device__ __half g_bias_h[(size_t)BB * HH * NN * NN];      // bias transposed+masked fp16, 128MB
__device__ __half g_attf[(size_t)NROWS * INNER];            // attention out fp16 [row][hd]
__device__ __half g_woutf[(size_t)DOUT * INNER];            // Wout fp16 n-major [n][k]
__device__ unsigned g_xh[(size_t)NROWS * (DIN/2)];          // x hi bf16 pairs [row][kp]
__device__ unsigned g_xl[(size_t)NROWS * (DIN/2)];
__device__ unsigned g_wqkvh[(size_t)QKV_COLS * 256];        // [SCALE*Wq|Wkv] n-major [n][kp]
__device__ unsigned g_wqkvl[(size_t)QKV_COLS * 256];
__device__ unsigned char g_maskb[BB * NN];

// ---- helpers ----
__device__ __forceinline__ float ex2(float x) {
    float y;
    asm("ex2.approx.ftz.f32 %0, %1;" : "=f"(y) : "f"(x));
    return y;
}
__device__ __forceinline__ unsigned h2ex2(unsigned a) {
    unsigned d;
    asm("ex2.approx.f16x2 %0, %1;" : "=r"(d) : "r"(a));
    return d;
}
// pack two f32 into f16x2: low half = lo, high half = hi
__device__ __forceinline__ unsigned pack_h2(float lo, float hi) {
    unsigned d;
    asm("cvt.rn.f16x2.f32 %0, %1, %2;" : "=r"(d) : "f"(hi), "f"(lo));
    return d;
}
__device__ __forceinline__ unsigned pack_bf16(float hi_elem, float lo_elem) {
    unsigned r;
    asm("cvt.rn.bf16x2.f32 %0, %1, %2;" : "=r"(r) : "f"(hi_elem), "f"(lo_elem));
    return r;
}
__device__ __forceinline__ void cp16(void* sp, const void* gp) {
    unsigned s = (unsigned)__cvta_generic_to_shared(sp);
    asm volatile("cp.async.cg.shared.global [%0], [%1], 16;\n" :: "r"(s), "l"(gp));
}
#define CP_COMMIT asm volatile("cp.async.commit_group;\n")
#define CP_WAIT0  asm volatile("cp.async.wait_group 0;\n")
#define CP_WAIT1  asm volatile("cp.async.wait_group 1;\n")

__device__ __forceinline__ void ldsm4(unsigned& r0, unsigned& r1, unsigned& r2, unsigned& r3,
                                      unsigned saddr) {
    asm volatile("ldmatrix.sync.aligned.m8n8.x4.shared.b16 {%0,%1,%2,%3}, [%4];"
                 : "=r"(r0), "=r"(r1), "=r"(r2), "=r"(r3) : "r"(saddr));
}
__device__ __forceinline__ void mma16f(float& c0, float& c1, float& c2, float& c3,
                                       unsigned a0, unsigned a1, unsigned a2, unsigned a3,
                                       unsigned b0, unsigned b1) {
    asm volatile(
        "mma.sync.aligned.m16n8k16.row.col.f32.f16.f16.f32 "
        "{%0,%1,%2,%3},{%4,%5,%6,%7},{%8,%9},{%0,%1,%2,%3};\n"
        : "+f"(c0), "+f"(c1), "+f"(c2), "+f"(c3)
        : "r"(a0), "r"(a1), "r"(a2), "r"(a3), "r"(b0), "r"(b1));
}
__device__ __forceinline__ void mma16bf(float& c0, float& c1, float& c2, float& c3,
                                        unsigned a0, unsigned a1, unsigned a2, unsigned a3,
                                        unsigned b0, unsigned b1) {
    asm volatile(
        "mma.sync.aligned.m16n8k16.row.col.f32.bf16.bf16.f32 "
        "{%0,%1,%2,%3},{%4,%5,%6,%7},{%8,%9},{%0,%1,%2,%3};\n"
        : "+f"(c0), "+f"(c1), "+f"(c2), "+f"(c3)
        : "r"(a0), "r"(a1), "r"(a2), "r"(a3), "r"(b0), "r"(b1));
}

// =====================================================================
// k_prep (compact): [CTA 0] mask; [1..1024] split x; [1025..1280] weights
// qkv weights -> bf16 hi/lo pairs n-major; Wout -> fp16 n-major.
// =====================================================================
__global__ __launch_bounds__(256) void k_prep(const unsigned char* __restrict__ m,
                                              const float* __restrict__ x,
                                              const float* __restrict__ Wq,
                                              const float* __restrict__ Wkv,
                                              const float* __restrict__ Wout) {
    const int bid = blockIdx.x;
    if (bid == 0) {
        __shared__ int s_notI32, s_notF32;
        if (threadIdx.x == 0) { s_notI32 = 0; s_notF32 = 0; }
        __syncthreads();
        const unsigned* mw = (const unsigned*)m;
        int notI = 0, notF = 0;
        for (int i = threadIdx.x; i < BB * NN / 4; i += 256) {
            unsigned w = mw[i];
            if (w & 0xFFFFFF00u) notI = 1;
            if (w != 0u && w != 0x3F800000u) notF = 1;
        }
        if (notI) atomicOr(&s_notI32, 1);
        if (notF) atomicOr(&s_notF32, 1);
        __syncthreads();
        const int notI32 = s_notI32, notF32 = s_notF32;
        for (int i = threadIdx.x; i < BB * NN; i += 256) {
            unsigned char v;
            if (!notF32)      v = (((const unsigned*)m)[i] != 0u) ? 1 : 0;
            else if (!notI32) v = (((const int*)m)[i] != 0) ? 1 : 0;
            else              v = (m[i] != 0) ? 1 : 0;
            g_maskb[i] = v;
        }
    } else if (bid <= 1024) {
        const int base = (bid - 1) * 2048;
        #pragma unroll
        for (int s = 0; s < 8; s++) {
            int idx = base + s * 256 + threadIdx.x;
            float2 v = ((const float2*)x)[idx];
            unsigned hp = pack_bf16(v.y, v.x);
            float b0 = __uint_as_float(hp << 16);
            float b1 = __uint_as_float(hp & 0xFFFF0000u);
            unsigned lp = pack_bf16(v.y - b1, v.x - b0);
            g_xh[idx] = hp;
            g_xl[idx] = lp;
        }
    } else {
        const int base = (bid - 1025) * 2048;
        const int total1 = 256 * QKV_COLS;
        #pragma unroll
        for (int s = 0; s < 8; s++) {
            int idx = base + s * 256 + threadIdx.x;
            if (idx < total1) {
                int kp = idx / QKV_COLS, n = idx % QKV_COLS;
                float a, b;
                if (n < 512) {
                    a = Wq[(2 * kp) * 512 + n] * SCALE;
                    b = Wq[(2 * kp + 1) * 512 + n] * SCALE;
                } else {
                    int nn = n - 512;
                    a = Wkv[(2 * kp) * 1024 + nn];
                    b = Wkv[(2 * kp + 1) * 1024 + nn];
                }
                size_t off = (size_t)n * 256 + kp;
                unsigned hp = pack_bf16(b, a);
                float a0 = __uint_as_float(hp << 16);
                float b0 = __uint_as_float(hp & 0xFFFF0000u);
                unsigned lp = pack_bf16(b - b0, a - a0);
                g_wqkvh[off] = hp;
                g_wqkvl[off] = lp;
            } else {
                int j = idx - total1;
                int kp = j / DOUT, n = j % DOUT;
                float a = Wout[(2 * kp) * DOUT + n];
                float b = Wout[(2 * kp + 1) * DOUT + n];
                ((unsigned*)g_woutf)[(size_t)n * 256 + kp] = pack_h2(a, b);
            }
        }
    }
}

// =====================================================================
// QKV GEMM core (bf16 hi/lo 3-mma, tile 128x64, 2-stage cp.async, LDSM).
// Epilogue: q/k -> g_qk fp16; v -> g_vTh fp16 transposed scatter.
// =====================================================================
#define GAS 20
#define BS2 20
#define GEMM_SMEM ((2*128*GAS*2 + 2*64*BS2*2) * 4)   // 61440 bytes

__device__ __forceinline__ void gemm_qkv(unsigned* smg, int cbid) {
    unsigned* sAh = smg;
    unsigned* sAl = sAh + 2 * 128 * GAS;
    unsigned* sBh = sAl + 2 * 128 * GAS;
    unsigned* sBl = sBh + 2 * 64 * BS2;

    const int tid = threadIdx.x, lane = tid & 31, warp = tid >> 5;
    const int g = lane >> 2, t = lane & 3;
    const int cb = (cbid % (QKV_COLS / 64)) * 64;
    const int rb = (cbid / (QKV_COLS / 64)) * 128;
    const int m0 = warp * 16;

    const int ar0 = tid >> 2, ac4 = (tid & 3) * 4;
    const int brB = tid >> 2, bc4 = (tid & 3) * 4;

    auto load_stage = [&](int st, int kt) {
        const int kp0 = kt * 16;
        unsigned* pAh = sAh + st * 128 * GAS;
        unsigned* pAl = sAl + st * 128 * GAS;
        #pragma unroll
        for (int sIt = 0; sIt < 2; sIt++) {
            int r = ar0 + sIt * 64;
            size_t go = (size_t)(rb + r) * 256 + kp0 + ac4;
            cp16(&pAh[r * GAS + ac4], g_xh + go);
            cp16(&pAl[r * GAS + ac4], g_xl + go);
        }
        size_t go = (size_t)(cb + brB) * 256 + kp0 + bc4;
        cp16(&sBh[st * 64 * BS2 + brB * BS2 + bc4], g_wqkvh + go);
        cp16(&sBl[st * 64 * BS2 + brB * BS2 + bc4], g_wqkvl + go);
    };

    const unsigned aoff = ((unsigned)((m0 + (lane & 15)) * GAS + ((lane & 16) >> 2))) * 4;
    const unsigned boff = ((unsigned)(((lane & 7) + ((lane & 16) >> 1)) * BS2 + ((lane & 8) >> 1))) * 4;
    const unsigned sAh_b = (unsigned)__cvta_generic_to_shared(sAh);
    const unsigned sAl_b = (unsigned)__cvta_generic_to_shared(sAl);
    const unsigned sBh_b = (unsigned)__cvta_generic_to_shared(sBh);
    const unsigned sBl_b = (unsigned)__cvta_generic_to_shared(sBl);

    float acc[8][4];
    #pragma unroll
    for (int i = 0; i < 8; i++)
        #pragma unroll
        for (int j = 0; j < 4; j++) acc[i][j] = 0.f;

    load_stage(0, 0);
    CP_COMMIT;

    for (int kt = 0; kt < 16; kt++) {
        CP_WAIT0;
        __syncthreads();
        if (kt < 15) { load_stage((kt + 1) & 1, kt + 1); CP_COMMIT; }

        const unsigned stA = (kt & 1) * 128 * GAS * 4;
        const unsigned stB = (kt & 1) * 64 * BS2 * 4;

        #pragma unroll
        for (int kc = 0; kc < 2; kc++) {
            const unsigned ko = kc * 8 * 4;
            unsigned ah0, ah1, ah2, ah3, al0, al1, al2, al3;
            ldsm4(ah0, ah1, ah2, ah3, sAh_b + stA + aoff + ko);
            ldsm4(al0, al1, al2, al3, sAl_b + stA + aoff + ko);
            #pragma unroll
            for (int nbp = 0; nbp < 4; nbp++) {
                const unsigned bo = boff + (unsigned)(nbp * 16 * BS2) * 4 + ko;
                unsigned bh0, bh1, bh2, bh3, bl0, bl1, bl2, bl3;
                ldsm4(bh0, bh1, bh2, bh3, sBh_b + stB + bo);
                ldsm4(bl0, bl1, bl2, bl3, sBl_b + stB + bo);
                float* A0 = acc[2 * nbp];
                float* A1 = acc[2 * nbp + 1];
                mma16bf(A0[0], A0[1], A0[2], A0[3], ah0, ah1, ah2, ah3, bh0, bh1);
                mma16bf(A0[0], A0[1], A0[2], A0[3], ah0, ah1, ah2, ah3, bl0, bl1);
                mma16bf(A0[0], A0[1], A0[2], A0[3], al0, al1, al2, al3, bh0, bh1);
                mma16bf(A1[0], A1[1], A1[2], A1[3], ah0, ah1, ah2, ah3, bh2, bh3);
                mma16bf(A1[0], A1[1], A1[2], A1[3], ah0, ah1, ah2, ah3, bl2, bl3);
                mma16bf(A1[0], A1[1], A1[2], A1[3], al0, al1, al2, al3, bh2, bh3);
            }
        }
        __syncthreads();
    }

    if (cb < 1024) {
        #pragma unroll
        for (int nb = 0; nb < 8; nb++) {
            int col = cb + nb * 8 + 2 * t;
            int r0 = rb + m0 + g;
            int r1 = r0 + 8;
            *(__half2*)(g_qk + (size_t)r0 * QKCOLS + col) = __floats2half2_rn(acc[nb][0], acc[nb][1]);
            *(__half2*)(g_qk + (size_t)r1 * QKCOLS + col) = __floats2half2_rn(acc[nb][2], acc[nb][3]);
        }
    } else {
        int h = (cb - 1024) >> 6;
        int r0 = rb + m0 + g;
        int b = r0 >> 10, n = r0 & 1023;
        __half* vt = g_vTh + (size_t)(b * 8 + h) * 64 * NN;
        #pragma unroll
        for (int nb = 0; nb < 8; nb++) {
            int d = nb * 8 + 2 * t;
            vt[(size_t)d * NN + n] = __float2half_rn(acc[nb][0]);
            vt[(size_t)(d + 1) * NN + n] = __float2half_rn(acc[nb][1]);
            vt[(size_t)d * NN + n + 8] = __float2half_rn(acc[nb][2]);
            vt[(size_t)(d + 1) * NN + n + 8] = __float2half_rn(acc[nb][3]);
        }
    }
}

// =====================================================================
// k_mid: interleaved QKV GEMM (tensor) + bias transpose (DRAM, fp16 out).
// =====================================================================
__global__ __launch_bounds__(256, 2) void k_mid(const float* __restrict__ bias) {
    extern __shared__ unsigned smg[];
    const int bid = blockIdx.x;
    const int tid = threadIdx.x;
    const int grp = bid / 19, rem = bid % 19;

    if (rem < 3) {
        gemm_qkv(smg, grp * 3 + rem);
    } else {
        float* s = (float*)smg;
        unsigned char* ms = (unsigned char*)smg + NN * 9 * 4;
        const int bi = grp * 16 + (rem - 3);
        const int b = bi >> 10;
        const float* src = bias + (size_t)bi * (NN * HH);

        #pragma unroll
        for (int sIt = 0; sIt < 8; sIt++) {
            int idx = tid + sIt * 256;
            float4 v = *(const float4*)(src + idx * 4);
            int j = idx >> 1;
            int h = (idx & 1) * 4;
            s[j * 9 + h + 0] = v.x;
            s[j * 9 + h + 1] = v.y;
            s[j * 9 + h + 2] = v.z;
            s[j * 9 + h + 3] = v.w;
        }
        for (int j = tid; j < NN; j += 256) ms[j] = g_maskb[b * NN + j];
        __syncthreads();

        const int i = bi & (NN - 1);
        #pragma unroll
        for (int h = 0; h < HH; h++) {
            __half* dst = g_bias_h + (((size_t)(b * HH + h)) * NN + i) * NN;
            #pragma unroll
            for (int r = 0; r < 4; r++) {
                int j = tid + r * 256;
                float v = ms[j] ? s[j * 9 + h] : -60000.0f;
                dst[j] = __float2half_rn(v);
            }
        }
    }
}

// =====================================================================
// out-proj GEMM, plain fp16: out = att(fp16) @ Wout(fp16) + bout.
// tile 128x64, 2-stage cp.async, LDSM; k-tile = 32 halves.
// =====================================================================
#define AS2 40     // half stride (80B) for A and B smem rows
#define GEMM2_SMEM ((2*128*AS2 + 2*64*AS2) * 2)   // 30720 bytes
__global__ __launch_bounds__(256, 3) void k_gemm_out(const float* __restrict__ bout,
                                                     float* __restrict__ Cout) {
    extern __shared__ __half smh2[];
    __half* sA = smh2;                       // 2 stages x 128*AS2
    __half* sB = sA + 2 * 128 * AS2;         // 2 stages x 64*AS2

    const int tid = threadIdx.x, lane = tid & 31, warp = tid >> 5;
    const int g = lane >> 2, t = lane & 3;
    const int cb = (blockIdx.x & 7) * 64;
    const int rb = (blockIdx.x >> 3) * 128;
    const int m0 = warp * 16;

    const int ar = tid >> 2, ac8 = (tid & 3) * 8;    // A: 128 rows x 4 chunks, 2/thread
    const int br = tid >> 2, bc8 = (tid & 3) * 8;    // B: 64 rows x 4 chunks, 1/thread

    auto load_stage = [&](int st, int kt) {
        const int k0 = kt * 32;
        __half* pA = sA + st * 128 * AS2;
        #pragma unroll
        for (int sIt = 0; sIt < 2; sIt++) {
            int r = ar + sIt * 64;
            cp16(&pA[r * AS2 + ac8], g_attf + (size_t)(rb + r) * INNER + k0 + ac8);
        }
        cp16(&sB[st * 64 * AS2 + br * AS2 + bc8], g_woutf + (size_t)(cb + br) * INNER + k0 + bc8);
    };

    const unsigned aoff = (unsigned)((m0 + (lane & 15)) * 80 + ((lane & 16) >> 4) * 16);
    const unsigned boff = (unsigned)(((lane & 7) + ((lane & 16) >> 1)) * 80 + ((lane & 8) >> 3) * 16);
    const unsigned sA_b = (unsigned)__cvta_generic_to_shared(sA);
    const unsigned sB_b = (unsigned)__cvta_generic_to_shared(sB);

    float acc[8][4];
    #pragma unroll
    for (int i = 0; i < 8; i++)
        #pragma unroll
        for (int j = 0; j < 4; j++) acc[i][j] = 0.f;

    load_stage(0, 0);
    CP_COMMIT;

    for (int kt = 0; kt < 16; kt++) {
        CP_WAIT0;
        __syncthreads();
        if (kt < 15) { load_stage((kt + 1) & 1, kt + 1); CP_COMMIT; }

        const unsigned stA = (kt & 1) * 128 * AS2 * 2;
        const unsigned stB = (kt & 1) * 64 * AS2 * 2;

        #pragma unroll
        for (int kc = 0; kc < 2; kc++) {
            const unsigned ko = kc * 32;                  // 16 halves = 32B
            unsigned a0, a1, a2, a3;
            ldsm4(a0, a1, a2, a3, sA_b + stA + aoff + ko);
            #pragma unroll
            for (int nbp = 0; nbp < 4; nbp++) {
                unsigned b0, b1, c0, c1;
                ldsm4(b0, b1, c0, c1, sB_b + stB + boff + (unsigned)(nbp * 16 * 80) + ko);
                float* A0 = acc[2 * nbp];
                float* A1 = acc[2 * nbp + 1];
                mma16f(A0[0], A0[1], A0[2], A0[3], a0, a1, a2, a3, b0, b1);
                mma16f(A1[0], A1[1], A1[2], A1[3], a0, a1, a2, a3, c0, c1);
            }
        }
        __syncthreads();
    }

    #pragma unroll
    for (int nb = 0; nb < 8; nb++) {
        int col = cb + nb * 8 + 2 * t;
        float b0v = bout[col], b1v = bout[col + 1];
        int r0 = rb + m0 + g;
        int r1 = r0 + 8;
        *(float2*)(Cout + (size_t)r0 * DOUT + col) = make_float2(acc[nb][0] + b0v, acc[nb][1] + b1v);
        *(float2*)(Cout + (size_t)r1 * DOUT + col) = make_float2(acc[nb][2] + b0v, acc[nb][3] + b1v);
    }
}

// =====================================================================
// Flash attention, fp16 tiles + m16n8k16.f16.
// Softmax: ex2.approx.f16x2 (half the MUFU work; result IS the stored P),
// row-sums via an extra ones-B mma in the PV loop (f32 accumulate, exact).
// =====================================================================
#define HS 72            // half stride per smem row (144B)
#define HSB 144
#define ONES16 0x3C003C00u
__global__ __launch_bounds__(256, 2) void k_flash() {
    extern __shared__ __half smh[];
    __half* Qs = smh;                     // 128*HS
    __half* Ks = Qs + 128 * HS;           // 64*HS  [token][d]
    __half* Vt = Ks + 64 * HS;            // 64*HS  [d][token]
    __half* Ps = Vt + 64 * HS;            // 128*HS (bias overlay + P)

    const int tid = threadIdx.x, lane = tid & 31, warp = tid >> 5;
    const int g = lane >> 2, t = lane & 3;
    const int it = blockIdx.x & 7;
    const int bh = blockIdx.x >> 3;
    const int b = bh >> 3, h = bh & 7;
    const int i0 = it * 128;
    const int m0 = warp * 16;
    const float NEG_INF = __int_as_float(0xff800000);

    const __half* qbase = g_qk + (size_t)b * NN * QKCOLS + h * 64;
    const __half* kbase = qbase + 512;
    const __half* vbase = g_vTh + (size_t)bh * 64 * NN;
    const __half* bbase = g_bias_h + ((size_t)bh * NN + i0) * NN;

    const unsigned aoff = (unsigned)((m0 + (lane & 15)) * HSB + ((lane & 16) >> 4) * 16);
    const unsigned boff = (unsigned)(((lane & 7) + ((lane & 16) >> 1)) * HSB + ((lane & 8) >> 3) * 16);
    const unsigned qs_b = (unsigned)__cvta_generic_to_shared(Qs);
    const unsigned ks_b = (unsigned)__cvta_generic_to_shared(Ks);
    const unsigned vt_b = (unsigned)__cvta_generic_to_shared(Vt);
    const unsigned ps_b = (unsigned)__cvta_generic_to_shared(Ps);

    // Q tile (own cp group)
    #pragma unroll
    for (int sIt = 0; sIt < 4; sIt++) {
        int idx = tid + sIt * 256;
        int r = idx >> 3, c8 = (idx & 7) * 8;
        cp16(&Qs[r * HS + c8], qbase + (size_t)(i0 + r) * QKCOLS + c8);
    }
    CP_COMMIT;

    float accO[8][4];
    #pragma unroll
    for (int i = 0; i < 8; i++)
        #pragma unroll
        for (int j = 0; j < 4; j++) accO[i][j] = 0.f;
    float mrow0 = NEG_INF, mrow1 = NEG_INF;
    float lrow0 = 0.f, lrow1 = 0.f;

    for (int jt = 0; jt < 16; jt++) {
        const int j0 = jt * 64;
        __syncthreads();
        #pragma unroll
        for (int sIt = 0; sIt < 2; sIt++) {
            int idx = tid + sIt * 256;
            int r = idx >> 3, c8 = (idx & 7) * 8;
            cp16(&Ks[r * HS + c8], kbase + (size_t)(j0 + r) * QKCOLS + c8);
            cp16(&Vt[r * HS + c8], vbase + (size_t)r * NN + j0 + c8);
        }
        CP_COMMIT;                                         // group: K/V
        #pragma unroll
        for (int sIt = 0; sIt < 4; sIt++) {
            int idx = tid + sIt * 256;
            int r = idx >> 3, c8 = (idx & 7) * 8;
            cp16(&Ps[r * HS + c8], bbase + (size_t)r * NN + j0 + c8);
        }
        CP_COMMIT;                                         // group: bias
        CP_WAIT1;
        __syncthreads();

        // S = Q @ K^T
        float s[8][4];
        #pragma unroll
        for (int i = 0; i < 8; i++)
            #pragma unroll
            for (int j = 0; j < 4; j++) s[i][j] = 0.f;
        #pragma unroll
        for (int kc = 0; kc < 4; kc++) {
            const unsigned ko = kc * 32;
            unsigned a0, a1, a2, a3;
            ldsm4(a0, a1, a2, a3, qs_b + aoff + ko);
            #pragma unroll
            for (int nbp = 0; nbp < 4; nbp++) {
                unsigned b0, b1, c0, c1;
                ldsm4(b0, b1, c0, c1, ks_b + boff + (unsigned)(nbp * 16 * HSB) + ko);
                float* S0 = s[2 * nbp];
                float* S1 = s[2 * nbp + 1];
                mma16f(S0[0], S0[1], S0[2], S0[3], a0, a1, a2, a3, b0, b1);
                mma16f(S1[0], S1[1], S1[2], S1[3], a0, a1, a2, a3, c0, c1);
            }
        }
        CP_WAIT0;
        __syncthreads();

        // + bias (fp16), row max
        float mx0 = NEG_INF, mx1 = NEG_INF;
        #pragma unroll
        for (int nb = 0; nb < 8; nb++) {
            int c = nb * 8 + 2 * t;
            float2 fA = __half22float2(*(__half2*)&Ps[(m0 + g) * HS + c]);
            float2 fB = __half22float2(*(__half2*)&Ps[(m0 + g + 8) * HS + c]);
            s[nb][0] += fA.x;
            s[nb][1] += fA.y;
            s[nb][2] += fB.x;
            s[nb][3] += fB.y;
            mx0 = fmaxf(mx0, fmaxf(s[nb][0], s[nb][1]));
            mx1 = fmaxf(mx1, fmaxf(s[nb][2], s[nb][3]));
        }
        mx0 = fmaxf(mx0, __shfl_xor_sync(0xffffffffu, mx0, 1));
        mx0 = fmaxf(mx0, __shfl_xor_sync(0xffffffffu, mx0, 2));
        mx1 = fmaxf(mx1, __shfl_xor_sync(0xffffffffu, mx1, 1));
        mx1 = fmaxf(mx1, __shfl_xor_sync(0xffffffffu, mx1, 2));
        // (shfl chain warp-orders bias reads before P overwrite below)

        float mn0 = fmaxf(mrow0, mx0), mn1 = fmaxf(mrow1, mx1);
        float al0 = ex2((mrow0 - mn0) * LOG2E);
        float al1 = ex2((mrow1 - mn1) * LOG2E);
        mrow0 = mn0;
        mrow1 = mn1;

        // P = exp(s - mn) via f16x2 ex2 -> directly stored as fp16 pairs
        #pragma unroll
        for (int nb = 0; nb < 8; nb++) {
            int c = nb * 8 + 2 * t;
            unsigned q01 = h2ex2(pack_h2((s[nb][0] - mn0) * LOG2E, (s[nb][1] - mn0) * LOG2E));
            unsigned q23 = h2ex2(pack_h2((s[nb][2] - mn1) * LOG2E, (s[nb][3] - mn1) * LOG2E));
            *(unsigned*)&Ps[(m0 + g) * HS + c] = q01;
            *(unsigned*)&Ps[(m0 + g + 8) * HS + c] = q23;
        }

        #pragma unroll
        for (int nb = 0; nb < 8; nb++) {
            accO[nb][0] *= al0;
            accO[nb][1] *= al0;
            accO[nb][2] *= al1;
            accO[nb][3] *= al1;
        }
        __syncwarp();                                      // P rows warp-private
        // O += P @ V ; row sums via ones-B mma (sacc0 = sum row g, sacc2 = row g+8)
        float sacc0 = 0.f, sacc1 = 0.f, sacc2 = 0.f, sacc3 = 0.f;
        #pragma unroll
        for (int kc = 0; kc < 4; kc++) {
            const unsigned ko = kc * 32;
            unsigned a0, a1, a2, a3;
            ldsm4(a0, a1, a2, a3, ps_b + aoff + ko);
            mma16f(sacc0, sacc1, sacc2, sacc3, a0, a1, a2, a3, ONES16, ONES16);
            #pragma unroll
            for (int nbp = 0; nbp < 4; nbp++) {
                unsigned b0, b1, c0, c1;
                ldsm4(b0, b1, c0, c1, vt_b + boff + (unsigned)(nbp * 16 * HSB) + ko);
                float* O0 = accO[2 * nbp];
                float* O1 = accO[2 * nbp + 1];
                mma16f(O0[0], O0[1], O0[2], O0[3], a0, a1, a2, a3, b0, b1);
                mma16f(O1[0], O1[1], O1[2], O1[3], a0, a1, a2, a3, c0, c1);
            }
        }
        lrow0 = lrow0 * al0 + sacc0;
        lrow1 = lrow1 * al1 + sacc2;
    }

    // epilogue: normalize, store attention output as fp16
    float inv0 = 1.f / lrow0;
    float inv1 = 1.f / lrow1;
    __half* arow = g_attf + (size_t)h * 64;
    #pragma unroll
    for (int nb = 0; nb < 8; nb++) {
        int col = nb * 8 + 2 * t;
        int r0 = b * NN + i0 + m0 + g;
        int r1 = r0 + 8;
        *(__half2*)(arow + (size_t)r0 * INNER + col) =
            __floats2half2_rn(accO[nb][0] * inv0, accO[nb][1] * inv0);
        *(__half2*)(arow + (size_t)r1 * INNER + col) =
            __floats2half2_rn(accO[nb][2] * inv1, accO[nb][3] * inv1);
    }
}

// =====================================================================
extern "C" void kernel_launch(void* const* d_in, const int* in_sizes, int n_in,
                              void* d_out, int out_size) {
    (void)in_sizes; (void)n_in; (void)out_size;
    const float* x = (const float*)d_in[0];
    const unsigned char* mask = (const unsigned char*)d_in[1];
    const float* bias = (const float*)d_in[2];
    const float* Wq = (const float*)d_in[3];
    const float* Wkv = (const float*)d_in[4];
    const float* Wout = (const float*)d_in[5];
    const float* bout = (const float*)d_in[6];
    float* out = (float*)d_out;

    const int flash_smem = (128 + 64 + 64 + 128) * HS * 2;   // 55296
    cudaFuncSetAttribute(k_flash, cudaFuncAttributeMaxDynamicSharedMemorySize, flash_smem);
    cudaFuncSetAttribute(k_mid, cudaFuncAttributeMaxDynamicSharedMemorySize, GEMM_SMEM);
    cudaFuncSetAttribute(k_gemm_out, cudaFuncAttributeMaxDynamicSharedMemorySize, GEMM2_SMEM);

    k_prep<<<1281, 256>>>(mask, x, Wq, Wkv, Wout);
    k_mid<<<19 * 512, 256, GEMM_SMEM>>>(bias);
    k_flash<<<BB * HH * (NN / 128), 256, flash_smem>>>();
    k_gemm_out<<<(DOUT / 64) * (NROWS / 128), 256, GEMM2_SMEM>>>(bout, out);
}

// round 13
// speedup vs baseline: 1.5002x; 1.1057x over previous
#include <cuda_runtime.h>
#include <cuda_bf16.h>
#include <cuda_fp16.h>

#define BB 8
#define NN 1024
#define DIN 512
#define HH 8
#define INNER 512
#define DOUT 512
#define NROWS (BB*NN)            // 8192
#define SCALE 0.125f
#define LOG2E 1.4426950408889634f
#define QKCOLS 1024              // q|k halves per row
#define QKV_COLS 1536

// ---- scratch (device globals; no runtime allocation) ----
__device__ __half g_qk[(size_t)NROWS * QKCOLS];             // q|k fp16
__device__ __half g_vTh[(size_t)BB * HH * 64 * NN];         // V^T fp16 per (b,h): [d][token]
__device__ __half g_bias_h[(size_t)BB * HH * NN * NN];      // bias transposed+masked fp16, 128MB
__device__ __half g_attf[(size_t)NROWS * INNER];            // attention out fp16 [row][hd]
__device__ __half g_woutf[(size_t)DOUT * INNER];            // Wout fp16 n-major [n][k]
__device__ __half g_xf[(size_t)NROWS * DIN];                // x fp16 [row][k]
__device__ unsigned g_wqh[(size_t)QKV_COLS * 256];          // [SCALE*Wq|Wkv] fp16-hi pairs n-major
__device__ unsigned g_wql[(size_t)QKV_COLS * 256];          // fp16-lo pairs (subnormal-range residual)
__device__ unsigned char g_maskb[BB * NN];

// ---- helpers ----
__device__ __forceinline__ float ex2(float x) {
    float y;
    asm("ex2.approx.ftz.f32 %0, %1;" : "=f"(y) : "f"(x));
    return y;
}
__device__ __forceinline__ unsigned h2ex2(unsigned a) {
    unsigned d;
    asm("ex2.approx.f16x2 %0, %1;" : "=r"(d) : "r"(a));
    return d;
}
// pack two f32 into f16x2: low half = lo, high half = hi
__device__ __forceinline__ unsigned pack_h2(float lo, float hi) {
    unsigned d;
    asm("cvt.rn.f16x2.f32 %0, %1, %2;" : "=r"(d) : "f"(hi), "f"(lo));
    return d;
}
__device__ __forceinline__ void cp16(void* sp, const void* gp) {
    unsigned s = (unsigned)__cvta_generic_to_shared(sp);
    asm volatile("cp.async.cg.shared.global [%0], [%1], 16;\n" :: "r"(s), "l"(gp));
}
#define CP_COMMIT asm volatile("cp.async.commit_group;\n")
#define CP_WAIT0  asm volatile("cp.async.wait_group 0;\n")
#define CP_WAIT1  asm volatile("cp.async.wait_group 1;\n")

__device__ __forceinline__ void ldsm4(unsigned& r0, unsigned& r1, unsigned& r2, unsigned& r3,
                                      unsigned saddr) {
    asm volatile("ldmatrix.sync.aligned.m8n8.x4.shared.b16 {%0,%1,%2,%3}, [%4];"
                 : "=r"(r0), "=r"(r1), "=r"(r2), "=r"(r3) : "r"(saddr));
}
__device__ __forceinline__ void mma16f(float& c0, float& c1, float& c2, float& c3,
                                       unsigned a0, unsigned a1, unsigned a2, unsigned a3,
                                       unsigned b0, unsigned b1) {
    asm volatile(
        "mma.sync.aligned.m16n8k16.row.col.f32.f16.f16.f32 "
        "{%0,%1,%2,%3},{%4,%5,%6,%7},{%8,%9},{%0,%1,%2,%3};\n"
        : "+f"(c0), "+f"(c1), "+f"(c2), "+f"(c3)
        : "r"(a0), "r"(a1), "r"(a2), "r"(a3), "r"(b0), "r"(b1));
}

// =====================================================================
// k_prep (compact): [CTA 0] mask; [1..1024] x -> fp16; [1025..1280] weights
// qkv weights -> fp16 hi/lo pairs n-major; Wout -> fp16 n-major.
// =====================================================================
__global__ __launch_bounds__(256) void k_prep(const unsigned char* __restrict__ m,
                                              const float* __restrict__ x,
                                              const float* __restrict__ Wq,
                                              const float* __restrict__ Wkv,
                                              const float* __restrict__ Wout) {
    const int bid = blockIdx.x;
    if (bid == 0) {
        __shared__ int s_notI32, s_notF32;
        if (threadIdx.x == 0) { s_notI32 = 0; s_notF32 = 0; }
        __syncthreads();
        const unsigned* mw = (const unsigned*)m;
        int notI = 0, notF = 0;
        for (int i = threadIdx.x; i < BB * NN / 4; i += 256) {
            unsigned w = mw[i];
            if (w & 0xFFFFFF00u) notI = 1;
            if (w != 0u && w != 0x3F800000u) notF = 1;
        }
        if (notI) atomicOr(&s_notI32, 1);
        if (notF) atomicOr(&s_notF32, 1);
        __syncthreads();
        const int notI32 = s_notI32, notF32 = s_notF32;
        for (int i = threadIdx.x; i < BB * NN; i += 256) {
            unsigned char v;
            if (!notF32)      v = (((const unsigned*)m)[i] != 0u) ? 1 : 0;
            else if (!notI32) v = (((const int*)m)[i] != 0) ? 1 : 0;
            else              v = (m[i] != 0) ? 1 : 0;
            g_maskb[i] = v;
        }
    } else if (bid <= 1024) {
        // x -> fp16: 2,097,152 float2 pairs / 1024 CTAs = 2048 each
        const int base = (bid - 1) * 2048;
        #pragma unroll
        for (int s = 0; s < 8; s++) {
            int idx = base + s * 256 + threadIdx.x;
            float2 v = ((const float2*)x)[idx];
            ((unsigned*)g_xf)[idx] = pack_h2(v.x, v.y);
        }
    } else {
        const int base = (bid - 1025) * 2048;
        const int total1 = 256 * QKV_COLS;
        #pragma unroll
        for (int s = 0; s < 8; s++) {
            int idx = base + s * 256 + threadIdx.x;
            if (idx < total1) {
                int kp = idx / QKV_COLS, n = idx % QKV_COLS;
                float a, b;
                if (n < 512) {
                    a = Wq[(2 * kp) * 512 + n] * SCALE;
                    b = Wq[(2 * kp + 1) * 512 + n] * SCALE;
                } else {
                    int nn = n - 512;
                    a = Wkv[(2 * kp) * 1024 + nn];
                    b = Wkv[(2 * kp + 1) * 1024 + nn];
                }
                size_t off = (size_t)n * 256 + kp;
                unsigned hp = pack_h2(a, b);
                float2 hf = __half22float2(*(__half2*)&hp);
                unsigned lp = pack_h2(a - hf.x, b - hf.y);   // residual (fp16 subnormal range)
                g_wqh[off] = hp;
                g_wql[off] = lp;
            } else {
                int j = idx - total1;
                int kp = j / DOUT, n = j % DOUT;
                float a = Wout[(2 * kp) * DOUT + n];
                float b = Wout[(2 * kp + 1) * DOUT + n];
                ((unsigned*)g_woutf)[(size_t)n * 256 + kp] = pack_h2(a, b);
            }
        }
    }
}

// =====================================================================
// QKV GEMM, fp16 A + fp16 hi/lo W (2-mma): tile 128x64, 2-stage cp.async.
// Epilogue: q/k -> g_qk fp16; v -> g_vTh fp16 transposed scatter.
// =====================================================================
#define AS2 40     // half stride (80B) for smem rows
#define GEMMQ_SMEM ((2*128*AS2 + 2*2*64*AS2) * 2)   // 40960 bytes

__device__ __forceinline__ void gemm_qkv(__half* smh2, int cbid) {
    __half* sA = smh2;                       // 2 stages x 128*AS2
    __half* sBh = sA + 2 * 128 * AS2;        // 2 stages x 64*AS2
    __half* sBl = sBh + 2 * 64 * AS2;        // 2 stages x 64*AS2

    const int tid = threadIdx.x, lane = tid & 31, warp = tid >> 5;
    const int g = lane >> 2, t = lane & 3;
    const int cb = (cbid % (QKV_COLS / 64)) * 64;
    const int rb = (cbid / (QKV_COLS / 64)) * 128;
    const int m0 = warp * 16;

    const __half* Bh = (const __half*)g_wqh;
    const __half* Bl = (const __half*)g_wql;

    const int ar = tid >> 2, ac8 = (tid & 3) * 8;    // A: 128 rows x 4 chunks, 2/thread
    const int br = tid >> 2, bc8 = (tid & 3) * 8;    // B: 64 rows x 4 chunks, 1/thread each array

    auto load_stage = [&](int st, int kt) {
        const int k0 = kt * 32;
        __half* pA = sA + st * 128 * AS2;
        #pragma unroll
        for (int sIt = 0; sIt < 2; sIt++) {
            int r = ar + sIt * 64;
            cp16(&pA[r * AS2 + ac8], g_xf + (size_t)(rb + r) * DIN + k0 + ac8);
        }
        size_t go = (size_t)(cb + br) * DIN + k0 + bc8;
        cp16(&sBh[st * 64 * AS2 + br * AS2 + bc8], Bh + go);
        cp16(&sBl[st * 64 * AS2 + br * AS2 + bc8], Bl + go);
    };

    const unsigned aoff = (unsigned)((m0 + (lane & 15)) * 80 + ((lane & 16) >> 4) * 16);
    const unsigned boff = (unsigned)(((lane & 7) + ((lane & 16) >> 1)) * 80 + ((lane & 8) >> 3) * 16);
    const unsigned sA_b = (unsigned)__cvta_generic_to_shared(sA);
    const unsigned sBh_b = (unsigned)__cvta_generic_to_shared(sBh);
    const unsigned sBl_b = (unsigned)__cvta_generic_to_shared(sBl);

    float acc[8][4];
    #pragma unroll
    for (int i = 0; i < 8; i++)
        #pragma unroll
        for (int j = 0; j < 4; j++) acc[i][j] = 0.f;

    load_stage(0, 0);
    CP_COMMIT;

    for (int kt = 0; kt < 16; kt++) {
        CP_WAIT0;
        __syncthreads();
        if (kt < 15) { load_stage((kt + 1) & 1, kt + 1); CP_COMMIT; }

        const unsigned stA = (kt & 1) * 128 * AS2 * 2;
        const unsigned stB = (kt & 1) * 64 * AS2 * 2;

        #pragma unroll
        for (int kc = 0; kc < 2; kc++) {
            const unsigned ko = kc * 32;
            unsigned a0, a1, a2, a3;
            ldsm4(a0, a1, a2, a3, sA_b + stA + aoff + ko);
            #pragma unroll
            for (int nbp = 0; nbp < 4; nbp++) {
                const unsigned bo = boff + (unsigned)(nbp * 16 * 80) + ko;
                unsigned bh0, bh1, bh2, bh3, bl0, bl1, bl2, bl3;
                ldsm4(bh0, bh1, bh2, bh3, sBh_b + stB + bo);
                ldsm4(bl0, bl1, bl2, bl3, sBl_b + stB + bo);
                float* A0 = acc[2 * nbp];
                float* A1 = acc[2 * nbp + 1];
                mma16f(A0[0], A0[1], A0[2], A0[3], a0, a1, a2, a3, bh0, bh1);
                mma16f(A0[0], A0[1], A0[2], A0[3], a0, a1, a2, a3, bl0, bl1);
                mma16f(A1[0], A1[1], A1[2], A1[3], a0, a1, a2, a3, bh2, bh3);
                mma16f(A1[0], A1[1], A1[2], A1[3], a0, a1, a2, a3, bl2, bl3);
            }
        }
        __syncthreads();
    }

    if (cb < 1024) {
        #pragma unroll
        for (int nb = 0; nb < 8; nb++) {
            int col = cb + nb * 8 + 2 * t;
            int r0 = rb + m0 + g;
            int r1 = r0 + 8;
            *(__half2*)(g_qk + (size_t)r0 * QKCOLS + col) = __floats2half2_rn(acc[nb][0], acc[nb][1]);
            *(__half2*)(g_qk + (size_t)r1 * QKCOLS + col) = __floats2half2_rn(acc[nb][2], acc[nb][3]);
        }
    } else {
        int h = (cb - 1024) >> 6;
        int r0 = rb + m0 + g;
        int b = r0 >> 10, n = r0 & 1023;
        __half* vt = g_vTh + (size_t)(b * 8 + h) * 64 * NN;
        #pragma unroll
        for (int nb = 0; nb < 8; nb++) {
            int d = nb * 8 + 2 * t;
            vt[(size_t)d * NN + n] = __float2half_rn(acc[nb][0]);
            vt[(size_t)(d + 1) * NN + n] = __float2half_rn(acc[nb][1]);
            vt[(size_t)d * NN + n + 8] = __float2half_rn(acc[nb][2]);
            vt[(size_t)(d + 1) * NN + n + 8] = __float2half_rn(acc[nb][3]);
        }
    }
}

// =====================================================================
// k_mid: interleaved QKV GEMM (tensor) + bias transpose (DRAM, fp16 out).
// =====================================================================
__global__ __launch_bounds__(256, 2) void k_mid(const float* __restrict__ bias) {
    extern __shared__ __half smh2[];
    const int bid = blockIdx.x;
    const int tid = threadIdx.x;
    const int grp = bid / 19, rem = bid % 19;

    if (rem < 3) {
        gemm_qkv(smh2, grp * 3 + rem);
    } else {
        float* s = (float*)smh2;
        unsigned char* ms = (unsigned char*)smh2 + NN * 9 * 4;
        const int bi = grp * 16 + (rem - 3);
        const int b = bi >> 10;
        const float* src = bias + (size_t)bi * (NN * HH);

        #pragma unroll
        for (int sIt = 0; sIt < 8; sIt++) {
            int idx = tid + sIt * 256;
            float4 v = *(const float4*)(src + idx * 4);
            int j = idx >> 1;
            int h = (idx & 1) * 4;
            s[j * 9 + h + 0] = v.x;
            s[j * 9 + h + 1] = v.y;
            s[j * 9 + h + 2] = v.z;
            s[j * 9 + h + 3] = v.w;
        }
        for (int j = tid; j < NN; j += 256) ms[j] = g_maskb[b * NN + j];
        __syncthreads();

        const int i = bi & (NN - 1);
        #pragma unroll
        for (int h = 0; h < HH; h++) {
            __half* dst = g_bias_h + (((size_t)(b * HH + h)) * NN + i) * NN;
            #pragma unroll
            for (int r = 0; r < 4; r++) {
                int j = tid + r * 256;
                float v = ms[j] ? s[j * 9 + h] : -60000.0f;
                dst[j] = __float2half_rn(v);
            }
        }
    }
}

// =====================================================================
// out-proj GEMM, plain fp16 (unchanged from round 12).
// =====================================================================
#define GEMM2_SMEM ((2*128*AS2 + 2*64*AS2) * 2)   // 30720 bytes
__global__ __launch_bounds__(256, 3) void k_gemm_out(const float* __restrict__ bout,
                                                     float* __restrict__ Cout) {
    extern __shared__ __half smh2[];
    __half* sA = smh2;
    __half* sB = sA + 2 * 128 * AS2;

    const int tid = threadIdx.x, lane = tid & 31, warp = tid >> 5;
    const int g = lane >> 2, t = lane & 3;
    const int cb = (blockIdx.x & 7) * 64;
    const int rb = (blockIdx.x >> 3) * 128;
    const int m0 = warp * 16;

    const int ar = tid >> 2, ac8 = (tid & 3) * 8;
    const int br = tid >> 2, bc8 = (tid & 3) * 8;

    auto load_stage = [&](int st, int kt) {
        const int k0 = kt * 32;
        __half* pA = sA + st * 128 * AS2;
        #pragma unroll
        for (int sIt = 0; sIt < 2; sIt++) {
            int r = ar + sIt * 64;
            cp16(&pA[r * AS2 + ac8], g_attf + (size_t)(rb + r) * INNER + k0 + ac8);
        }
        cp16(&sB[st * 64 * AS2 + br * AS2 + bc8], g_woutf + (size_t)(cb + br) * INNER + k0 + bc8);
    };

    const unsigned aoff = (unsigned)((m0 + (lane & 15)) * 80 + ((lane & 16) >> 4) * 16);
    const unsigned boff = (unsigned)(((lane & 7) + ((lane & 16) >> 1)) * 80 + ((lane & 8) >> 3) * 16);
    const unsigned sA_b = (unsigned)__cvta_generic_to_shared(sA);
    const unsigned sB_b = (unsigned)__cvta_generic_to_shared(sB);

    float acc[8][4];
    #pragma unroll
    for (int i = 0; i < 8; i++)
        #pragma unroll
        for (int j = 0; j < 4; j++) acc[i][j] = 0.f;

    load_stage(0, 0);
    CP_COMMIT;

    for (int kt = 0; kt < 16; kt++) {
        CP_WAIT0;
        __syncthreads();
        if (kt < 15) { load_stage((kt + 1) & 1, kt + 1); CP_COMMIT; }

        const unsigned stA = (kt & 1) * 128 * AS2 * 2;
        const unsigned stB = (kt & 1) * 64 * AS2 * 2;

        #pragma unroll
        for (int kc = 0; kc < 2; kc++) {
            const unsigned ko = kc * 32;
            unsigned a0, a1, a2, a3;
            ldsm4(a0, a1, a2, a3, sA_b + stA + aoff + ko);
            #pragma unroll
            for (int nbp = 0; nbp < 4; nbp++) {
                unsigned b0, b1, c0, c1;
                ldsm4(b0, b1, c0, c1, sB_b + stB + boff + (unsigned)(nbp * 16 * 80) + ko);
                float* A0 = acc[2 * nbp];
                float* A1 = acc[2 * nbp + 1];
                mma16f(A0[0], A0[1], A0[2], A0[3], a0, a1, a2, a3, b0, b1);
                mma16f(A1[0], A1[1], A1[2], A1[3], a0, a1, a2, a3, c0, c1);
            }
        }
        __syncthreads();
    }

    #pragma unroll
    for (int nb = 0; nb < 8; nb++) {
        int col = cb + nb * 8 + 2 * t;
        float b0v = bout[col], b1v = bout[col + 1];
        int r0 = rb + m0 + g;
        int r1 = r0 + 8;
        *(float2*)(Cout + (size_t)r0 * DOUT + col) = make_float2(acc[nb][0] + b0v, acc[nb][1] + b1v);
        *(float2*)(Cout + (size_t)r1 * DOUT + col) = make_float2(acc[nb][2] + b0v, acc[nb][3] + b1v);
    }
}

// =====================================================================
// Flash attention (unchanged from round 12): fp16 tiles, f16x2 ex2 softmax,
// row-sums via ones-B mma.
// =====================================================================
#define HS 72            // half stride per smem row (144B)
#define HSB 144
#define ONES16 0x3C003C00u
__global__ __launch_bounds__(256, 2) void k_flash() {
    extern __shared__ __half smh[];
    __half* Qs = smh;                     // 128*HS
    __half* Ks = Qs + 128 * HS;           // 64*HS  [token][d]
    __half* Vt = Ks + 64 * HS;            // 64*HS  [d][token]
    __half* Ps = Vt + 64 * HS;            // 128*HS (bias overlay + P)

    const int tid = threadIdx.x, lane = tid & 31, warp = tid >> 5;
    const int g = lane >> 2, t = lane & 3;
    const int it = blockIdx.x & 7;
    const int bh = blockIdx.x >> 3;
    const int b = bh >> 3, h = bh & 7;
    const int i0 = it * 128;
    const int m0 = warp * 16;
    const float NEG_INF = __int_as_float(0xff800000);

    const __half* qbase = g_qk + (size_t)b * NN * QKCOLS + h * 64;
    const __half* kbase = qbase + 512;
    const __half* vbase = g_vTh + (size_t)bh * 64 * NN;
    const __half* bbase = g_bias_h + ((size_t)bh * NN + i0) * NN;

    const unsigned aoff = (unsigned)((m0 + (lane & 15)) * HSB + ((lane & 16) >> 4) * 16);
    const unsigned boff = (unsigned)(((lane & 7) + ((lane & 16) >> 1)) * HSB + ((lane & 8) >> 3) * 16);
    const unsigned qs_b = (unsigned)__cvta_generic_to_shared(Qs);
    const unsigned ks_b = (unsigned)__cvta_generic_to_shared(Ks);
    const unsigned vt_b = (unsigned)__cvta_generic_to_shared(Vt);
    const unsigned ps_b = (unsigned)__cvta_generic_to_shared(Ps);

    // Q tile (own cp group)
    #pragma unroll
    for (int sIt = 0; sIt < 4; sIt++) {
        int idx = tid + sIt * 256;
        int r = idx >> 3, c8 = (idx & 7) * 8;
        cp16(&Qs[r * HS + c8], qbase + (size_t)(i0 + r) * QKCOLS + c8);
    }
    CP_COMMIT;

    float accO[8][4];
    #pragma unroll
    for (int i = 0; i < 8; i++)
        #pragma unroll
        for (int j = 0; j < 4; j++) accO[i][j] = 0.f;
    float mrow0 = NEG_INF, mrow1 = NEG_INF;
    float lrow0 = 0.f, lrow1 = 0.f;

    for (int jt = 0; jt < 16; jt++) {
        const int j0 = jt * 64;
        __syncthreads();
        #pragma unroll
        for (int sIt = 0; sIt < 2; sIt++) {
            int idx = tid + sIt * 256;
            int r = idx >> 3, c8 = (idx & 7) * 8;
            cp16(&Ks[r * HS + c8], kbase + (size_t)(j0 + r) * QKCOLS + c8);
            cp16(&Vt[r * HS + c8], vbase + (size_t)r * NN + j0 + c8);
        }
        CP_COMMIT;                                         // group: K/V
        #pragma unroll
        for (int sIt = 0; sIt < 4; sIt++) {
            int idx = tid + sIt * 256;
            int r = idx >> 3, c8 = (idx & 7) * 8;
            cp16(&Ps[r * HS + c8], bbase + (size_t)r * NN + j0 + c8);
        }
        CP_COMMIT;                                         // group: bias
        CP_WAIT1;
        __syncthreads();

        // S = Q @ K^T
        float s[8][4];
        #pragma unroll
        for (int i = 0; i < 8; i++)
            #pragma unroll
            for (int j = 0; j < 4; j++) s[i][j] = 0.f;
        #pragma unroll
        for (int kc = 0; kc < 4; kc++) {
            const unsigned ko = kc * 32;
            unsigned a0, a1, a2, a3;
            ldsm4(a0, a1, a2, a3, qs_b + aoff + ko);
            #pragma unroll
            for (int nbp = 0; nbp < 4; nbp++) {
                unsigned b0, b1, c0, c1;
                ldsm4(b0, b1, c0, c1, ks_b + boff + (unsigned)(nbp * 16 * HSB) + ko);
                float* S0 = s[2 * nbp];
                float* S1 = s[2 * nbp + 1];
                mma16f(S0[0], S0[1], S0[2], S0[3], a0, a1, a2, a3, b0, b1);
                mma16f(S1[0], S1[1], S1[2], S1[3], a0, a1, a2, a3, c0, c1);
            }
        }
        CP_WAIT0;
        __syncthreads();

        // + bias (fp16), row max
        float mx0 = NEG_INF, mx1 = NEG_INF;
        #pragma unroll
        for (int nb = 0; nb < 8; nb++) {
            int c = nb * 8 + 2 * t;
            float2 fA = __half22float2(*(__half2*)&Ps[(m0 + g) * HS + c]);
            float2 fB = __half22float2(*(__half2*)&Ps[(m0 + g + 8) * HS + c]);
            s[nb][0] += fA.x;
            s[nb][1] += fA.y;
            s[nb][2] += fB.x;
            s[nb][3] += fB.y;
            mx0 = fmaxf(mx0, fmaxf(s[nb][0], s[nb][1]));
            mx1 = fmaxf(mx1, fmaxf(s[nb][2], s[nb][3]));
        }
        mx0 = fmaxf(mx0, __shfl_xor_sync(0xffffffffu, mx0, 1));
        mx0 = fmaxf(mx0, __shfl_xor_sync(0xffffffffu, mx0, 2));
        mx1 = fmaxf(mx1, __shfl_xor_sync(0xffffffffu, mx1, 1));
        mx1 = fmaxf(mx1, __shfl_xor_sync(0xffffffffu, mx1, 2));
        // (shfl chain warp-orders bias reads before P overwrite below)

        float mn0 = fmaxf(mrow0, mx0), mn1 = fmaxf(mrow1, mx1);
        float al0 = ex2((mrow0 - mn0) * LOG2E);
        float al1 = ex2((mrow1 - mn1) * LOG2E);
        mrow0 = mn0;
        mrow1 = mn1;

        // P = exp(s - mn) via f16x2 ex2 -> stored directly as fp16 pairs
        #pragma unroll
        for (int nb = 0; nb < 8; nb++) {
            int c = nb * 8 + 2 * t;
            unsigned q01 = h2ex2(pack_h2((s[nb][0] - mn0) * LOG2E, (s[nb][1] - mn0) * LOG2E));
            unsigned q23 = h2ex2(pack_h2((s[nb][2] - mn1) * LOG2E, (s[nb][3] - mn1) * LOG2E));
            *(unsigned*)&Ps[(m0 + g) * HS + c] = q01;
            *(unsigned*)&Ps[(m0 + g + 8) * HS + c] = q23;
        }

        #pragma unroll
        for (int nb = 0; nb < 8; nb++) {
            accO[nb][0] *= al0;
            accO[nb][1] *= al0;
            accO[nb][2] *= al1;
            accO[nb][3] *= al1;
        }
        __syncwarp();                                      // P rows warp-private
        // O += P @ V ; row sums via ones-B mma
        float sacc0 = 0.f, sacc1 = 0.f, sacc2 = 0.f, sacc3 = 0.f;
        #pragma unroll
        for (int kc = 0; kc < 4; kc++) {
            const unsigned ko = kc * 32;
            unsigned a0, a1, a2, a3;
            ldsm4(a0, a1, a2, a3, ps_b + aoff + ko);
            mma16f(sacc0, sacc1, sacc2, sacc3, a0, a1, a2, a3, ONES16, ONES16);
            #pragma unroll
            for (int nbp = 0; nbp < 4; nbp++) {
                unsigned b0, b1, c0, c1;
                ldsm4(b0, b1, c0, c1, vt_b + boff + (unsigned)(nbp * 16 * HSB) + ko);
                float* O0 = accO[2 * nbp];
                float* O1 = accO[2 * nbp + 1];
                mma16f(O0[0], O0[1], O0[2], O0[3], a0, a1, a2, a3, b0, b1);
                mma16f(O1[0], O1[1], O1[2], O1[3], a0, a1, a2, a3, c0, c1);
            }
        }
        lrow0 = lrow0 * al0 + sacc0;
        lrow1 = lrow1 * al1 + sacc2;
    }

    // epilogue: normalize, store attention output as fp16
    float inv0 = 1.f / lrow0;
    float inv1 = 1.f / lrow1;
    __half* arow = g_attf + (size_t)h * 64;
    #pragma unroll
    for (int nb = 0; nb < 8; nb++) {
        int col = nb * 8 + 2 * t;
        int r0 = b * NN + i0 + m0 + g;
        int r1 = r0 + 8;
        *(__half2*)(arow + (size_t)r0 * INNER + col) =
            __floats2half2_rn(accO[nb][0] * inv0, accO[nb][1] * inv0);
        *(__half2*)(arow + (size_t)r1 * INNER + col) =
            __floats2half2_rn(accO[nb][2] * inv1, accO[nb][3] * inv1);
    }
}

// =====================================================================
extern "C" void kernel_launch(void* const* d_in, const int* in_sizes, int n_in,
                              void* d_out, int out_size) {
    (void)in_sizes; (void)n_in; (void)out_size;
    const float* x = (const float*)d_in[0];
    const unsigned char* mask = (const unsigned char*)d_in[1];
    const float* bias = (const float*)d_in[2];
    const float* Wq = (const float*)d_in[3];
    const float* Wkv = (const float*)d_in[4];
    const float* Wout = (const float*)d_in[5];
    const float* bout = (const float*)d_in[6];
    float* out = (float*)d_out;

    const int flash_smem = (128 + 64 + 64 + 128) * HS * 2;   // 55296
    cudaFuncSetAttribute(k_flash, cudaFuncAttributeMaxDynamicSharedMemorySize, flash_smem);
    cudaFuncSetAttribute(k_mid, cudaFuncAttributeMaxDynamicSharedMemorySize, GEMMQ_SMEM);
    cudaFuncSetAttribute(k_gemm_out, cudaFuncAttributeMaxDynamicSharedMemorySize, GEMM2_SMEM);

    k_prep<<<1281, 256>>>(mask, x, Wq, Wkv, Wout);
    k_mid<<<19 * 512, 256, GEMMQ_SMEM>>>(bias);
    k_flash<<<BB * HH * (NN / 128), 256, flash_smem>>>();
    k_gemm_out<<<(DOUT / 64) * (NROWS / 128), 256, GEMM2_SMEM>>>(bout, out);
}

// round 14
// speedup vs baseline: 1.5783x; 1.0521x over previous
#include <cuda_runtime.h>
#include <cuda_bf16.h>
#include <cuda_fp16.h>

#define BB 8
#define NN 1024
#define DIN 512
#define HH 8
#define INNER 512
#define DOUT 512
#define NROWS (BB*NN)            // 8192
#define SCALE 0.125f
#define LOG2E 1.4426950408889634f
#define QKCOLS 1024              // q|k halves per row
#define QKV_COLS 1536

// ---- scratch (device globals; no runtime allocation) ----
__device__ __half g_qk[(size_t)NROWS * QKCOLS];             // q|k fp16
__device__ __half g_vTh[(size_t)BB * HH * 64 * NN];         // V^T fp16 per (b,h): [d][token]
__device__ __half g_bias_h[(size_t)BB * HH * NN * NN];      // bias transposed+masked fp16, 128MB
__device__ __half g_attf[(size_t)NROWS * INNER];            // attention out fp16 [row][hd]
__device__ __half g_woutf[(size_t)DOUT * INNER];            // Wout fp16 n-major [n][k]
__device__ __half g_xf[(size_t)NROWS * DIN];                // x fp16 [row][k]
__device__ unsigned g_wqh[(size_t)QKV_COLS * 256];          // [SCALE*Wq|Wkv] fp16-hi pairs n-major
__device__ unsigned g_wql[(size_t)QKV_COLS * 256];          // fp16-lo pairs (subnormal residual)
__device__ unsigned char g_maskb[BB * NN];

// ---- helpers ----
__device__ __forceinline__ float ex2(float x) {
    float y;
    asm("ex2.approx.ftz.f32 %0, %1;" : "=f"(y) : "f"(x));
    return y;
}
__device__ __forceinline__ unsigned h2ex2(unsigned a) {
    unsigned d;
    asm("ex2.approx.f16x2 %0, %1;" : "=r"(d) : "r"(a));
    return d;
}
// pack two f32 into f16x2: low half = lo, high half = hi
__device__ __forceinline__ unsigned pack_h2(float lo, float hi) {
    unsigned d;
    asm("cvt.rn.f16x2.f32 %0, %1, %2;" : "=r"(d) : "f"(hi), "f"(lo));
    return d;
}
__device__ __forceinline__ void cp16(void* sp, const void* gp) {
    unsigned s = (unsigned)__cvta_generic_to_shared(sp);
    asm volatile("cp.async.cg.shared.global [%0], [%1], 16;\n" :: "r"(s), "l"(gp));
}
#define CP_COMMIT asm volatile("cp.async.commit_group;\n")
#define CP_WAIT0  asm volatile("cp.async.wait_group 0;\n")
#define CP_WAIT1  asm volatile("cp.async.wait_group 1;\n")

__device__ __forceinline__ void ldsm4(unsigned& r0, unsigned& r1, unsigned& r2, unsigned& r3,
                                      unsigned saddr) {
    asm volatile("ldmatrix.sync.aligned.m8n8.x4.shared.b16 {%0,%1,%2,%3}, [%4];"
                 : "=r"(r0), "=r"(r1), "=r"(r2), "=r"(r3) : "r"(saddr));
}
__device__ __forceinline__ void mma16f(float& c0, float& c1, float& c2, float& c3,
                                       unsigned a0, unsigned a1, unsigned a2, unsigned a3,
                                       unsigned b0, unsigned b1) {
    asm volatile(
        "mma.sync.aligned.m16n8k16.row.col.f32.f16.f16.f32 "
        "{%0,%1,%2,%3},{%4,%5,%6,%7},{%8,%9},{%0,%1,%2,%3};\n"
        : "+f"(c0), "+f"(c1), "+f"(c2), "+f"(c3)
        : "r"(a0), "r"(a1), "r"(a2), "r"(a3), "r"(b0), "r"(b1));
}

// =====================================================================
// k_prep (compact): [CTA 0] mask; [1..1024] x -> fp16; [1025..1280] weights
// =====================================================================
__global__ __launch_bounds__(256) void k_prep(const unsigned char* __restrict__ m,
                                              const float* __restrict__ x,
                                              const float* __restrict__ Wq,
                                              const float* __restrict__ Wkv,
                                              const float* __restrict__ Wout) {
    const int bid = blockIdx.x;
    if (bid == 0) {
        __shared__ int s_notI32, s_notF32;
        if (threadIdx.x == 0) { s_notI32 = 0; s_notF32 = 0; }
        __syncthreads();
        const unsigned* mw = (const unsigned*)m;
        int notI = 0, notF = 0;
        for (int i = threadIdx.x; i < BB * NN / 4; i += 256) {
            unsigned w = mw[i];
            if (w & 0xFFFFFF00u) notI = 1;
            if (w != 0u && w != 0x3F800000u) notF = 1;
        }
        if (notI) atomicOr(&s_notI32, 1);
        if (notF) atomicOr(&s_notF32, 1);
        __syncthreads();
        const int notI32 = s_notI32, notF32 = s_notF32;
        for (int i = threadIdx.x; i < BB * NN; i += 256) {
            unsigned char v;
            if (!notF32)      v = (((const unsigned*)m)[i] != 0u) ? 1 : 0;
            else if (!notI32) v = (((const int*)m)[i] != 0) ? 1 : 0;
            else              v = (m[i] != 0) ? 1 : 0;
            g_maskb[i] = v;
        }
    } else if (bid <= 1024) {
        const int base = (bid - 1) * 2048;
        #pragma unroll
        for (int s = 0; s < 8; s++) {
            int idx = base + s * 256 + threadIdx.x;
            float2 v = ((const float2*)x)[idx];
            ((unsigned*)g_xf)[idx] = pack_h2(v.x, v.y);
        }
    } else {
        const int base = (bid - 1025) * 2048;
        const int total1 = 256 * QKV_COLS;
        #pragma unroll
        for (int s = 0; s < 8; s++) {
            int idx = base + s * 256 + threadIdx.x;
            if (idx < total1) {
                int kp = idx / QKV_COLS, n = idx % QKV_COLS;
                float a, b;
                if (n < 512) {
                    a = Wq[(2 * kp) * 512 + n] * SCALE;
                    b = Wq[(2 * kp + 1) * 512 + n] * SCALE;
                } else {
                    int nn = n - 512;
                    a = Wkv[(2 * kp) * 1024 + nn];
                    b = Wkv[(2 * kp + 1) * 1024 + nn];
                }
                size_t off = (size_t)n * 256 + kp;
                unsigned hp = pack_h2(a, b);
                float2 hf = __half22float2(*(__half2*)&hp);
                unsigned lp = pack_h2(a - hf.x, b - hf.y);   // residual (fp16 subnormal range)
                g_wqh[off] = hp;
                g_wql[off] = lp;
            } else {
                int j = idx - total1;
                int kp = j / DOUT, n = j % DOUT;
                float a = Wout[(2 * kp) * DOUT + n];
                float b = Wout[(2 * kp + 1) * DOUT + n];
                ((unsigned*)g_woutf)[(size_t)n * 256 + kp] = pack_h2(a, b);
            }
        }
    }
}

// =====================================================================
// QKV GEMM, fp16 A + fp16 hi/lo W (2-mma): tile 128x64, 2-stage cp.async.
// =====================================================================
#define AS2 40     // half stride (80B) for smem rows
#define GEMMQ_SMEM ((2*128*AS2 + 2*2*64*AS2) * 2)   // 40960 bytes

__device__ __forceinline__ void gemm_qkv(__half* smh2, int cbid) {
    __half* sA = smh2;                       // 2 stages x 128*AS2
    __half* sBh = sA + 2 * 128 * AS2;        // 2 stages x 64*AS2
    __half* sBl = sBh + 2 * 64 * AS2;        // 2 stages x 64*AS2

    const int tid = threadIdx.x, lane = tid & 31, warp = tid >> 5;
    const int g = lane >> 2, t = lane & 3;
    const int cb = (cbid % (QKV_COLS / 64)) * 64;
    const int rb = (cbid / (QKV_COLS / 64)) * 128;
    const int m0 = warp * 16;

    const __half* Bh = (const __half*)g_wqh;
    const __half* Bl = (const __half*)g_wql;

    const int ar = tid >> 2, ac8 = (tid & 3) * 8;
    const int br = tid >> 2, bc8 = (tid & 3) * 8;

    auto load_stage = [&](int st, int kt) {
        const int k0 = kt * 32;
        __half* pA = sA + st * 128 * AS2;
        #pragma unroll
        for (int sIt = 0; sIt < 2; sIt++) {
            int r = ar + sIt * 64;
            cp16(&pA[r * AS2 + ac8], g_xf + (size_t)(rb + r) * DIN + k0 + ac8);
        }
        size_t go = (size_t)(cb + br) * DIN + k0 + bc8;
        cp16(&sBh[st * 64 * AS2 + br * AS2 + bc8], Bh + go);
        cp16(&sBl[st * 64 * AS2 + br * AS2 + bc8], Bl + go);
    };

    const unsigned aoff = (unsigned)((m0 + (lane & 15)) * 80 + ((lane & 16) >> 4) * 16);
    const unsigned boff = (unsigned)(((lane & 7) + ((lane & 16) >> 1)) * 80 + ((lane & 8) >> 3) * 16);
    const unsigned sA_b = (unsigned)__cvta_generic_to_shared(sA);
    const unsigned sBh_b = (unsigned)__cvta_generic_to_shared(sBh);
    const unsigned sBl_b = (unsigned)__cvta_generic_to_shared(sBl);

    float acc[8][4];
    #pragma unroll
    for (int i = 0; i < 8; i++)
        #pragma unroll
        for (int j = 0; j < 4; j++) acc[i][j] = 0.f;

    load_stage(0, 0);
    CP_COMMIT;

    for (int kt = 0; kt < 16; kt++) {
        CP_WAIT0;
        __syncthreads();
        if (kt < 15) { load_stage((kt + 1) & 1, kt + 1); CP_COMMIT; }

        const unsigned stA = (kt & 1) * 128 * AS2 * 2;
        const unsigned stB = (kt & 1) * 64 * AS2 * 2;

        #pragma unroll
        for (int kc = 0; kc < 2; kc++) {
            const unsigned ko = kc * 32;
            unsigned a0, a1, a2, a3;
            ldsm4(a0, a1, a2, a3, sA_b + stA + aoff + ko);
            #pragma unroll
            for (int nbp = 0; nbp < 4; nbp++) {
                const unsigned bo = boff + (unsigned)(nbp * 16 * 80) + ko;
                unsigned bh0, bh1, bh2, bh3, bl0, bl1, bl2, bl3;
                ldsm4(bh0, bh1, bh2, bh3, sBh_b + stB + bo);
                ldsm4(bl0, bl1, bl2, bl3, sBl_b + stB + bo);
                float* A0 = acc[2 * nbp];
                float* A1 = acc[2 * nbp + 1];
                mma16f(A0[0], A0[1], A0[2], A0[3], a0, a1, a2, a3, bh0, bh1);
                mma16f(A0[0], A0[1], A0[2], A0[3], a0, a1, a2, a3, bl0, bl1);
                mma16f(A1[0], A1[1], A1[2], A1[3], a0, a1, a2, a3, bh2, bh3);
                mma16f(A1[0], A1[1], A1[2], A1[3], a0, a1, a2, a3, bl2, bl3);
            }
        }
        __syncthreads();
    }

    if (cb < 1024) {
        #pragma unroll
        for (int nb = 0; nb < 8; nb++) {
            int col = cb + nb * 8 + 2 * t;
            int r0 = rb + m0 + g;
            int r1 = r0 + 8;
            *(__half2*)(g_qk + (size_t)r0 * QKCOLS + col) = __floats2half2_rn(acc[nb][0], acc[nb][1]);
            *(__half2*)(g_qk + (size_t)r1 * QKCOLS + col) = __floats2half2_rn(acc[nb][2], acc[nb][3]);
        }
    } else {
        int h = (cb - 1024) >> 6;
        int r0 = rb + m0 + g;
        int b = r0 >> 10, n = r0 & 1023;
        __half* vt = g_vTh + (size_t)(b * 8 + h) * 64 * NN;
        #pragma unroll
        for (int nb = 0; nb < 8; nb++) {
            int d = nb * 8 + 2 * t;
            vt[(size_t)d * NN + n] = __float2half_rn(acc[nb][0]);
            vt[(size_t)(d + 1) * NN + n] = __float2half_rn(acc[nb][1]);
            vt[(size_t)d * NN + n + 8] = __float2half_rn(acc[nb][2]);
            vt[(size_t)(d + 1) * NN + n + 8] = __float2half_rn(acc[nb][3]);
        }
    }
}

// =====================================================================
// k_mid: interleaved QKV GEMM (tensor) + bias transpose (DRAM, fp16 out).
// launch_bounds(256,3): regs capped ~84 so 3 CTAs/SM reside -> the DRAM-
// bound transpose CTAs get 50% more MLP (they were latency-starved at 2).
// =====================================================================
__global__ __launch_bounds__(256, 3) void k_mid(const float* __restrict__ bias) {
    extern __shared__ __half smh2[];
    const int bid = blockIdx.x;
    const int tid = threadIdx.x;
    const int grp = bid / 19, rem = bid % 19;

    if (rem < 3) {
        gemm_qkv(smh2, grp * 3 + rem);
    } else {
        float* s = (float*)smh2;
        unsigned char* ms = (unsigned char*)smh2 + NN * 9 * 4;
        const int bi = grp * 16 + (rem - 3);
        const int b = bi >> 10;
        const float* src = bias + (size_t)bi * (NN * HH);

        #pragma unroll
        for (int sIt = 0; sIt < 8; sIt++) {
            int idx = tid + sIt * 256;
            float4 v = *(const float4*)(src + idx * 4);
            int j = idx >> 1;
            int h = (idx & 1) * 4;
            s[j * 9 + h + 0] = v.x;
            s[j * 9 + h + 1] = v.y;
            s[j * 9 + h + 2] = v.z;
            s[j * 9 + h + 3] = v.w;
        }
        for (int j = tid; j < NN; j += 256) ms[j] = g_maskb[b * NN + j];
        __syncthreads();

        const int i = bi & (NN - 1);
        #pragma unroll
        for (int h = 0; h < HH; h++) {
            __half* dst = g_bias_h + (((size_t)(b * HH + h)) * NN + i) * NN;
            #pragma unroll
            for (int r = 0; r < 4; r++) {
                int j = tid + r * 256;
                float v = ms[j] ? s[j * 9 + h] : -60000.0f;
                dst[j] = __float2half_rn(v);
            }
        }
    }
}

// =====================================================================
// out-proj GEMM, plain fp16 (unchanged).
// =====================================================================
#define GEMM2_SMEM ((2*128*AS2 + 2*64*AS2) * 2)   // 30720 bytes
__global__ __launch_bounds__(256, 3) void k_gemm_out(const float* __restrict__ bout,
                                                     float* __restrict__ Cout) {
    extern __shared__ __half smh2[];
    __half* sA = smh2;
    __half* sB = sA + 2 * 128 * AS2;

    const int tid = threadIdx.x, lane = tid & 31, warp = tid >> 5;
    const int g = lane >> 2, t = lane & 3;
    const int cb = (blockIdx.x & 7) * 64;
    const int rb = (blockIdx.x >> 3) * 128;
    const int m0 = warp * 16;

    const int ar = tid >> 2, ac8 = (tid & 3) * 8;
    const int br = tid >> 2, bc8 = (tid & 3) * 8;

    auto load_stage = [&](int st, int kt) {
        const int k0 = kt * 32;
        __half* pA = sA + st * 128 * AS2;
        #pragma unroll
        for (int sIt = 0; sIt < 2; sIt++) {
            int r = ar + sIt * 64;
            cp16(&pA[r * AS2 + ac8], g_attf + (size_t)(rb + r) * INNER + k0 + ac8);
        }
        cp16(&sB[st * 64 * AS2 + br * AS2 + bc8], g_woutf + (size_t)(cb + br) * INNER + k0 + bc8);
    };

    const unsigned aoff = (unsigned)((m0 + (lane & 15)) * 80 + ((lane & 16) >> 4) * 16);
    const unsigned boff = (unsigned)(((lane & 7) + ((lane & 16) >> 1)) * 80 + ((lane & 8) >> 3) * 16);
    const unsigned sA_b = (unsigned)__cvta_generic_to_shared(sA);
    const unsigned sB_b = (unsigned)__cvta_generic_to_shared(sB);

    float acc[8][4];
    #pragma unroll
    for (int i = 0; i < 8; i++)
        #pragma unroll
        for (int j = 0; j < 4; j++) acc[i][j] = 0.f;

    load_stage(0, 0);
    CP_COMMIT;

    for (int kt = 0; kt < 16; kt++) {
        CP_WAIT0;
        __syncthreads();
        if (kt < 15) { load_stage((kt + 1) & 1, kt + 1); CP_COMMIT; }

        const unsigned stA = (kt & 1) * 128 * AS2 * 2;
        const unsigned stB = (kt & 1) * 64 * AS2 * 2;

        #pragma unroll
        for (int kc = 0; kc < 2; kc++) {
            const unsigned ko = kc * 32;
            unsigned a0, a1, a2, a3;
            ldsm4(a0, a1, a2, a3, sA_b + stA + aoff + ko);
            #pragma unroll
            for (int nbp = 0; nbp < 4; nbp++) {
                unsigned b0, b1, c0, c1;
                ldsm4(b0, b1, c0, c1, sB_b + stB + boff + (unsigned)(nbp * 16 * 80) + ko);
                float* A0 = acc[2 * nbp];
                float* A1 = acc[2 * nbp + 1];
                mma16f(A0[0], A0[1], A0[2], A0[3], a0, a1, a2, a3, b0, b1);
                mma16f(A1[0], A1[1], A1[2], A1[3], a0, a1, a2, a3, c0, c1);
            }
        }
        __syncthreads();
    }

    #pragma unroll
    for (int nb = 0; nb < 8; nb++) {
        int col = cb + nb * 8 + 2 * t;
        float b0v = bout[col], b1v = bout[col + 1];
        int r0 = rb + m0 + g;
        int r1 = r0 + 8;
        *(float2*)(Cout + (size_t)r0 * DOUT + col) = make_float2(acc[nb][0] + b0v, acc[nb][1] + b1v);
        *(float2*)(Cout + (size_t)r1 * DOUT + col) = make_float2(acc[nb][2] + b0v, acc[nb][3] + b1v);
    }
}

// =====================================================================
// Flash attention: fp16 tiles, f16x2 ex2 softmax, ones-B row sums.
// NEW: bias staged per-warp (warp w cp.asyncs its own 16 rows), so the
// post-QK^T barrier is CP_WAIT0 + __syncwarp instead of __syncthreads —
// bias/P/PV traffic on the Ps region is entirely warp-band-local.
// =====================================================================
#define HS 72            // half stride per smem row (144B)
#define HSB 144
#define ONES16 0x3C003C00u
__global__ __launch_bounds__(256, 2) void k_flash() {
    extern __shared__ __half smh[];
    __half* Qs = smh;                     // 128*HS
    __half* Ks = Qs + 128 * HS;           // 64*HS  [token][d]
    __half* Vt = Ks + 64 * HS;            // 64*HS  [d][token]
    __half* Ps = Vt + 64 * HS;            // 128*HS (bias overlay + P)

    const int tid = threadIdx.x, lane = tid & 31, warp = tid >> 5;
    const int g = lane >> 2, t = lane & 3;
    const int it = blockIdx.x & 7;
    const int bh = blockIdx.x >> 3;
    const int b = bh >> 3, h = bh & 7;
    const int i0 = it * 128;
    const int m0 = warp * 16;
    const float NEG_INF = __int_as_float(0xff800000);

    const __half* qbase = g_qk + (size_t)b * NN * QKCOLS + h * 64;
    const __half* kbase = qbase + 512;
    const __half* vbase = g_vTh + (size_t)bh * 64 * NN;
    const __half* bbase = g_bias_h + ((size_t)bh * NN + i0) * NN;

    const unsigned aoff = (unsigned)((m0 + (lane & 15)) * HSB + ((lane & 16) >> 4) * 16);
    const unsigned boff = (unsigned)(((lane & 7) + ((lane & 16) >> 1)) * HSB + ((lane & 8) >> 3) * 16);
    const unsigned qs_b = (unsigned)__cvta_generic_to_shared(Qs);
    const unsigned ks_b = (unsigned)__cvta_generic_to_shared(Ks);
    const unsigned vt_b = (unsigned)__cvta_generic_to_shared(Vt);
    const unsigned ps_b = (unsigned)__cvta_generic_to_shared(Ps);

    // per-warp bias chunk coords: warp w owns rows m0..m0+15 (16 rows x 8 chunks
    // = 128 chunks, lanes x 4)
    const int bw_r = m0 + (lane >> 3);          // +4 rows per iteration
    const int bw_c8 = (lane & 7) * 8;

    // Q tile (own cp group)
    #pragma unroll
    for (int sIt = 0; sIt < 4; sIt++) {
        int idx = tid + sIt * 256;
        int r = idx >> 3, c8 = (idx & 7) * 8;
        cp16(&Qs[r * HS + c8], qbase + (size_t)(i0 + r) * QKCOLS + c8);
    }
    CP_COMMIT;

    float accO[8][4];
    #pragma unroll
    for (int i = 0; i < 8; i++)
        #pragma unroll
        for (int j = 0; j < 4; j++) accO[i][j] = 0.f;
    float mrow0 = NEG_INF, mrow1 = NEG_INF;
    float lrow0 = 0.f, lrow1 = 0.f;

    for (int jt = 0; jt < 16; jt++) {
        const int j0 = jt * 64;
        __syncthreads();                                   // buffers free (Ks/Vt/Ps)
        #pragma unroll
        for (int sIt = 0; sIt < 2; sIt++) {
            int idx = tid + sIt * 256;
            int r = idx >> 3, c8 = (idx & 7) * 8;
            cp16(&Ks[r * HS + c8], kbase + (size_t)(j0 + r) * QKCOLS + c8);
            cp16(&Vt[r * HS + c8], vbase + (size_t)r * NN + j0 + c8);
        }
        CP_COMMIT;                                         // group: K/V
        // bias: per-warp rows
        #pragma unroll
        for (int sIt = 0; sIt < 4; sIt++) {
            int r = bw_r + sIt * 4;
            cp16(&Ps[r * HS + bw_c8], bbase + (size_t)r * NN + j0 + bw_c8);
        }
        CP_COMMIT;                                         // group: bias (warp-local rows)
        CP_WAIT1;
        __syncthreads();                                   // K/V visible to all warps

        // S = Q @ K^T
        float s[8][4];
        #pragma unroll
        for (int i = 0; i < 8; i++)
            #pragma unroll
            for (int j = 0; j < 4; j++) s[i][j] = 0.f;
        #pragma unroll
        for (int kc = 0; kc < 4; kc++) {
            const unsigned ko = kc * 32;
            unsigned a0, a1, a2, a3;
            ldsm4(a0, a1, a2, a3, qs_b + aoff + ko);
            #pragma unroll
            for (int nbp = 0; nbp < 4; nbp++) {
                unsigned b0, b1, c0, c1;
                ldsm4(b0, b1, c0, c1, ks_b + boff + (unsigned)(nbp * 16 * HSB) + ko);
                float* S0 = s[2 * nbp];
                float* S1 = s[2 * nbp + 1];
                mma16f(S0[0], S0[1], S0[2], S0[3], a0, a1, a2, a3, b0, b1);
                mma16f(S1[0], S1[1], S1[2], S1[3], a0, a1, a2, a3, c0, c1);
            }
        }
        CP_WAIT0;                                          // this thread's bias chunks done
        __syncwarp();                                      // warp's own rows visible (warp-issued)

        // + bias (fp16), row max
        float mx0 = NEG_INF, mx1 = NEG_INF;
        #pragma unroll
        for (int nb = 0; nb < 8; nb++) {
            int c = nb * 8 + 2 * t;
            float2 fA = __half22float2(*(__half2*)&Ps[(m0 + g) * HS + c]);
            float2 fB = __half22float2(*(__half2*)&Ps[(m0 + g + 8) * HS + c]);
            s[nb][0] += fA.x;
            s[nb][1] += fA.y;
            s[nb][2] += fB.x;
            s[nb][3] += fB.y;
            mx0 = fmaxf(mx0, fmaxf(s[nb][0], s[nb][1]));
            mx1 = fmaxf(mx1, fmaxf(s[nb][2], s[nb][3]));
        }
        mx0 = fmaxf(mx0, __shfl_xor_sync(0xffffffffu, mx0, 1));
        mx0 = fmaxf(mx0, __shfl_xor_sync(0xffffffffu, mx0, 2));
        mx1 = fmaxf(mx1, __shfl_xor_sync(0xffffffffu, mx1, 1));
        mx1 = fmaxf(mx1, __shfl_xor_sync(0xffffffffu, mx1, 2));

        float mn0 = fmaxf(mrow0, mx0), mn1 = fmaxf(mrow1, mx1);
        float al0 = ex2((mrow0 - mn0) * LOG2E);
        float al1 = ex2((mrow1 - mn1) * LOG2E);
        mrow0 = mn0;
        mrow1 = mn1;

        // P = exp(s - mn) via f16x2 ex2 -> stored directly as fp16 pairs
        #pragma unroll
        for (int nb = 0; nb < 8; nb++) {
            int c = nb * 8 + 2 * t;
            unsigned q01 = h2ex2(pack_h2((s[nb][0] - mn0) * LOG2E, (s[nb][1] - mn0) * LOG2E));
            unsigned q23 = h2ex2(pack_h2((s[nb][2] - mn1) * LOG2E, (s[nb][3] - mn1) * LOG2E));
            *(unsigned*)&Ps[(m0 + g) * HS + c] = q01;
            *(unsigned*)&Ps[(m0 + g + 8) * HS + c] = q23;
        }

        #pragma unroll
        for (int nb = 0; nb < 8; nb++) {
            accO[nb][0] *= al0;
            accO[nb][1] *= al0;
            accO[nb][2] *= al1;
            accO[nb][3] *= al1;
        }
        __syncwarp();                                      // P rows warp-private
        // O += P @ V ; row sums via ones-B mma
        float sacc0 = 0.f, sacc1 = 0.f, sacc2 = 0.f, sacc3 = 0.f;
        #pragma unroll
        for (int kc = 0; kc < 4; kc++) {
            const unsigned ko = kc * 32;
            unsigned a0, a1, a2, a3;
            ldsm4(a0, a1, a2, a3, ps_b + aoff + ko);
            mma16f(sacc0, sacc1, sacc2, sacc3, a0, a1, a2, a3, ONES16, ONES16);
            #pragma unroll
            for (int nbp = 0; nbp < 4; nbp++) {
                unsigned b0, b1, c0, c1;
                ldsm4(b0, b1, c0, c1, vt_b + boff + (unsigned)(nbp * 16 * HSB) + ko);
                float* O0 = accO[2 * nbp];
                float* O1 = accO[2 * nbp + 1];
                mma16f(O0[0], O0[1], O0[2], O0[3], a0, a1, a2, a3, b0, b1);
                mma16f(O1[0], O1[1], O1[2], O1[3], a0, a1, a2, a3, c0, c1);
            }
        }
        lrow0 = lrow0 * al0 + sacc0;
        lrow1 = lrow1 * al1 + sacc2;
    }

    // epilogue: normalize, store attention output as fp16
    float inv0 = 1.f / lrow0;
    float inv1 = 1.f / lrow1;
    __half* arow = g_attf + (size_t)h * 64;
    #pragma unroll
    for (int nb = 0; nb < 8; nb++) {
        int col = nb * 8 + 2 * t;
        int r0 = b * NN + i0 + m0 + g;
        int r1 = r0 + 8;
        *(__half2*)(arow + (size_t)r0 * INNER + col) =
            __floats2half2_rn(accO[nb][0] * inv0, accO[nb][1] * inv0);
        *(__half2*)(arow + (size_t)r1 * INNER + col) =
            __floats2half2_rn(accO[nb][2] * inv1, accO[nb][3] * inv1);
    }
}

// =====================================================================
extern "C" void kernel_launch(void* const* d_in, const int* in_sizes, int n_in,
                              void* d_out, int out_size) {
    (void)in_sizes; (void)n_in; (void)out_size;
    const float* x = (const float*)d_in[0];
    const unsigned char* mask = (const unsigned char*)d_in[1];
    const float* bias = (const float*)d_in[2];
    const float* Wq = (const float*)d_in[3];
    const float* Wkv = (const float*)d_in[4];
    const float* Wout = (const float*)d_in[5];
    const float* bout = (const float*)d_in[6];
    float* out = (float*)d_out;

    const int flash_smem = (128 + 64 + 64 + 128) * HS * 2;   // 55296
    cudaFuncSetAttribute(k_flash, cudaFuncAttributeMaxDynamicSharedMemorySize, flash_smem);
    cudaFuncSetAttribute(k_mid, cudaFuncAttributeMaxDynamicSharedMemorySize, GEMMQ_SMEM);
    cudaFuncSetAttribute(k_gemm_out, cudaFuncAttributeMaxDynamicSharedMemorySize, GEMM2_SMEM);

    k_prep<<<1281, 256>>>(mask, x, Wq, Wkv, Wout);
    k_mid<<<19 * 512, 256, GEMMQ_SMEM>>>(bias);
    k_flash<<<BB * HH * (NN / 128), 256, flash_smem>>>();
    k_gemm_out<<<(DOUT / 64) * (NROWS / 128), 256, GEMM2_SMEM>>>(bout, out);
}

// round 15
// speedup vs baseline: 1.6512x; 1.0462x over previous
#include <cuda_runtime.h>
#include <cuda_bf16.h>
#include <cuda_fp16.h>

#define BB 8
#define NN 1024
#define DIN 512
#define HH 8
#define INNER 512
#define DOUT 512
#define NROWS (BB*NN)            // 8192
#define SCALE 0.125f
#define LOG2E 1.4426950408889634f
#define QKCOLS 1024              // q|k halves per row
#define QKV_COLS 1536

// ---- scratch (device globals; no runtime allocation) ----
__device__ __half g_qk[(size_t)NROWS * QKCOLS];             // q|k fp16
__device__ __half g_vTh[(size_t)BB * HH * 64 * NN];         // V^T fp16 per (b,h): [d][token]
__device__ __half g_bias_h[(size_t)BB * HH * NN * NN];      // bias transposed+masked fp16, 128MB
__device__ __half g_attf[(size_t)NROWS * INNER];            // attention out fp16 [row][hd]
__device__ __half g_woutf[(size_t)DOUT * INNER];            // Wout fp16 n-major [n][k]
__device__ __half g_xf[(size_t)NROWS * DIN];                // x fp16 [row][k]
__device__ unsigned g_wqh[(size_t)QKV_COLS * 256];          // [SCALE*Wq|Wkv] fp16-hi pairs n-major
__device__ unsigned g_wql[(size_t)QKV_COLS * 256];          // fp16-lo pairs (subnormal residual)
__device__ unsigned char g_maskb[BB * NN];

// ---- helpers ----
__device__ __forceinline__ float ex2(float x) {
    float y;
    asm("ex2.approx.ftz.f32 %0, %1;" : "=f"(y) : "f"(x));
    return y;
}
__device__ __forceinline__ unsigned h2ex2(unsigned a) {
    unsigned d;
    asm("ex2.approx.f16x2 %0, %1;" : "=r"(d) : "r"(a));
    return d;
}
// pack two f32 into f16x2: low half = lo, high half = hi
__device__ __forceinline__ unsigned pack_h2(float lo, float hi) {
    unsigned d;
    asm("cvt.rn.f16x2.f32 %0, %1, %2;" : "=r"(d) : "f"(hi), "f"(lo));
    return d;
}
__device__ __forceinline__ void cp16(void* sp, const void* gp) {
    unsigned s = (unsigned)__cvta_generic_to_shared(sp);
    asm volatile("cp.async.cg.shared.global [%0], [%1], 16;\n" :: "r"(s), "l"(gp));
}
#define CP_COMMIT asm volatile("cp.async.commit_group;\n")
#define CP_WAIT0  asm volatile("cp.async.wait_group 0;\n")
#define CP_WAIT1  asm volatile("cp.async.wait_group 1;\n")

__device__ __forceinline__ void ldsm4(unsigned& r0, unsigned& r1, unsigned& r2, unsigned& r3,
                                      unsigned saddr) {
    asm volatile("ldmatrix.sync.aligned.m8n8.x4.shared.b16 {%0,%1,%2,%3}, [%4];"
                 : "=r"(r0), "=r"(r1), "=r"(r2), "=r"(r3) : "r"(saddr));
}
__device__ __forceinline__ void mma16f(float& c0, float& c1, float& c2, float& c3,
                                       unsigned a0, unsigned a1, unsigned a2, unsigned a3,
                                       unsigned b0, unsigned b1) {
    asm volatile(
        "mma.sync.aligned.m16n8k16.row.col.f32.f16.f16.f32 "
        "{%0,%1,%2,%3},{%4,%5,%6,%7},{%8,%9},{%0,%1,%2,%3};\n"
        : "+f"(c0), "+f"(c1), "+f"(c2), "+f"(c3)
        : "r"(a0), "r"(a1), "r"(a2), "r"(a3), "r"(b0), "r"(b1));
}

// =====================================================================
// k_prep (compact): [CTA 0] mask; [1..1024] x -> fp16; [1025..1280] weights
// =====================================================================
__global__ __launch_bounds__(256) void k_prep(const unsigned char* __restrict__ m,
                                              const float* __restrict__ x,
                                              const float* __restrict__ Wq,
                                              const float* __restrict__ Wkv,
                                              const float* __restrict__ Wout) {
    const int bid = blockIdx.x;
    if (bid == 0) {
        __shared__ int s_notI32, s_notF32;
        if (threadIdx.x == 0) { s_notI32 = 0; s_notF32 = 0; }
        __syncthreads();
        const unsigned* mw = (const unsigned*)m;
        int notI = 0, notF = 0;
        for (int i = threadIdx.x; i < BB * NN / 4; i += 256) {
            unsigned w = mw[i];
            if (w & 0xFFFFFF00u) notI = 1;
            if (w != 0u && w != 0x3F800000u) notF = 1;
        }
        if (notI) atomicOr(&s_notI32, 1);
        if (notF) atomicOr(&s_notF32, 1);
        __syncthreads();
        const int notI32 = s_notI32, notF32 = s_notF32;
        for (int i = threadIdx.x; i < BB * NN; i += 256) {
            unsigned char v;
            if (!notF32)      v = (((const unsigned*)m)[i] != 0u) ? 1 : 0;
            else if (!notI32) v = (((const int*)m)[i] != 0) ? 1 : 0;
            else              v = (m[i] != 0) ? 1 : 0;
            g_maskb[i] = v;
        }
    } else if (bid <= 1024) {
        const int base = (bid - 1) * 2048;
        #pragma unroll
        for (int s = 0; s < 8; s++) {
            int idx = base + s * 256 + threadIdx.x;
            float2 v = ((const float2*)x)[idx];
            ((unsigned*)g_xf)[idx] = pack_h2(v.x, v.y);
        }
    } else {
        const int base = (bid - 1025) * 2048;
        const int total1 = 256 * QKV_COLS;
        #pragma unroll
        for (int s = 0; s < 8; s++) {
            int idx = base + s * 256 + threadIdx.x;
            if (idx < total1) {
                int kp = idx / QKV_COLS, n = idx % QKV_COLS;
                float a, b;
                if (n < 512) {
                    a = Wq[(2 * kp) * 512 + n] * SCALE;
                    b = Wq[(2 * kp + 1) * 512 + n] * SCALE;
                } else {
                    int nn = n - 512;
                    a = Wkv[(2 * kp) * 1024 + nn];
                    b = Wkv[(2 * kp + 1) * 1024 + nn];
                }
                size_t off = (size_t)n * 256 + kp;
                unsigned hp = pack_h2(a, b);
                float2 hf = __half22float2(*(__half2*)&hp);
                unsigned lp = pack_h2(a - hf.x, b - hf.y);   // residual (fp16 subnormal range)
                g_wqh[off] = hp;
                g_wql[off] = lp;
            } else {
                int j = idx - total1;
                int kp = j / DOUT, n = j % DOUT;
                float a = Wout[(2 * kp) * DOUT + n];
                float b = Wout[(2 * kp + 1) * DOUT + n];
                ((unsigned*)g_woutf)[(size_t)n * 256 + kp] = pack_h2(a, b);
            }
        }
    }
}

// =====================================================================
// QKV GEMM, fp16 A + fp16 hi/lo W (2-mma): tile 128x64, 2-stage cp.async.
// =====================================================================
#define AS2 40     // half stride (80B) for smem rows
#define GEMMQ_SMEM ((2*128*AS2 + 2*2*64*AS2) * 2)   // 40960 bytes

__device__ __forceinline__ void gemm_qkv(__half* smh2, int cbid) {
    __half* sA = smh2;                       // 2 stages x 128*AS2
    __half* sBh = sA + 2 * 128 * AS2;        // 2 stages x 64*AS2
    __half* sBl = sBh + 2 * 64 * AS2;        // 2 stages x 64*AS2

    const int tid = threadIdx.x, lane = tid & 31, warp = tid >> 5;
    const int g = lane >> 2, t = lane & 3;
    const int cb = (cbid % (QKV_COLS / 64)) * 64;
    const int rb = (cbid / (QKV_COLS / 64)) * 128;
    const int m0 = warp * 16;

    const __half* Bh = (const __half*)g_wqh;
    const __half* Bl = (const __half*)g_wql;

    const int ar = tid >> 2, ac8 = (tid & 3) * 8;
    const int br = tid >> 2, bc8 = (tid & 3) * 8;

    auto load_stage = [&](int st, int kt) {
        const int k0 = kt * 32;
        __half* pA = sA + st * 128 * AS2;
        #pragma unroll
        for (int sIt = 0; sIt < 2; sIt++) {
            int r = ar + sIt * 64;
            cp16(&pA[r * AS2 + ac8], g_xf + (size_t)(rb + r) * DIN + k0 + ac8);
        }
        size_t go = (size_t)(cb + br) * DIN + k0 + bc8;
        cp16(&sBh[st * 64 * AS2 + br * AS2 + bc8], Bh + go);
        cp16(&sBl[st * 64 * AS2 + br * AS2 + bc8], Bl + go);
    };

    const unsigned aoff = (unsigned)((m0 + (lane & 15)) * 80 + ((lane & 16) >> 4) * 16);
    const unsigned boff = (unsigned)(((lane & 7) + ((lane & 16) >> 1)) * 80 + ((lane & 8) >> 3) * 16);
    const unsigned sA_b = (unsigned)__cvta_generic_to_shared(sA);
    const unsigned sBh_b = (unsigned)__cvta_generic_to_shared(sBh);
    const unsigned sBl_b = (unsigned)__cvta_generic_to_shared(sBl);

    float acc[8][4];
    #pragma unroll
    for (int i = 0; i < 8; i++)
        #pragma unroll
        for (int j = 0; j < 4; j++) acc[i][j] = 0.f;

    load_stage(0, 0);
    CP_COMMIT;

    for (int kt = 0; kt < 16; kt++) {
        CP_WAIT0;
        __syncthreads();
        if (kt < 15) { load_stage((kt + 1) & 1, kt + 1); CP_COMMIT; }

        const unsigned stA = (kt & 1) * 128 * AS2 * 2;
        const unsigned stB = (kt & 1) * 64 * AS2 * 2;

        #pragma unroll
        for (int kc = 0; kc < 2; kc++) {
            const unsigned ko = kc * 32;
            unsigned a0, a1, a2, a3;
            ldsm4(a0, a1, a2, a3, sA_b + stA + aoff + ko);
            #pragma unroll
            for (int nbp = 0; nbp < 4; nbp++) {
                const unsigned bo = boff + (unsigned)(nbp * 16 * 80) + ko;
                unsigned bh0, bh1, bh2, bh3, bl0, bl1, bl2, bl3;
                ldsm4(bh0, bh1, bh2, bh3, sBh_b + stB + bo);
                ldsm4(bl0, bl1, bl2, bl3, sBl_b + stB + bo);
                float* A0 = acc[2 * nbp];
                float* A1 = acc[2 * nbp + 1];
                mma16f(A0[0], A0[1], A0[2], A0[3], a0, a1, a2, a3, bh0, bh1);
                mma16f(A0[0], A0[1], A0[2], A0[3], a0, a1, a2, a3, bl0, bl1);
                mma16f(A1[0], A1[1], A1[2], A1[3], a0, a1, a2, a3, bh2, bh3);
                mma16f(A1[0], A1[1], A1[2], A1[3], a0, a1, a2, a3, bl2, bl3);
            }
        }
        __syncthreads();
    }

    if (cb < 1024) {
        #pragma unroll
        for (int nb = 0; nb < 8; nb++) {
            int col = cb + nb * 8 + 2 * t;
            int r0 = rb + m0 + g;
            int r1 = r0 + 8;
            *(__half2*)(g_qk + (size_t)r0 * QKCOLS + col) = __floats2half2_rn(acc[nb][0], acc[nb][1]);
            *(__half2*)(g_qk + (size_t)r1 * QKCOLS + col) = __floats2half2_rn(acc[nb][2], acc[nb][3]);
        }
    } else {
        int h = (cb - 1024) >> 6;
        int r0 = rb + m0 + g;
        int b = r0 >> 10, n = r0 & 1023;
        __half* vt = g_vTh + (size_t)(b * 8 + h) * 64 * NN;
        #pragma unroll
        for (int nb = 0; nb < 8; nb++) {
            int d = nb * 8 + 2 * t;
            vt[(size_t)d * NN + n] = __float2half_rn(acc[nb][0]);
            vt[(size_t)(d + 1) * NN + n] = __float2half_rn(acc[nb][1]);
            vt[(size_t)d * NN + n + 8] = __float2half_rn(acc[nb][2]);
            vt[(size_t)(d + 1) * NN + n + 8] = __float2half_rn(acc[nb][3]);
        }
    }
}

// =====================================================================
// k_mid: interleaved QKV GEMM (tensor) + bias transpose (DRAM, fp16 out).
// Transpose rework (LSU diet, value-identical): mask+cvt applied at LOAD
// (same __float2half_rn of same selected f32 as before); fp16 pairs staged
// as u32 words s32[j*5 + (h>>1)]; transposed emit = 2x LDS.32 + PRMT +
// 1x half2 STG (halves the STG count). Stride 5 (odd) keeps LDS ~2-way max.
// =====================================================================
__global__ __launch_bounds__(256, 3) void k_mid(const float* __restrict__ bias) {
    extern __shared__ __half smh2[];
    const int bid = blockIdx.x;
    const int tid = threadIdx.x;
    const int grp = bid / 19, rem = bid % 19;

    if (rem < 3) {
        gemm_qkv(smh2, grp * 3 + rem);
    } else {
        unsigned* s32 = (unsigned*)smh2;                 // 1024*5 u32 = 20KB
        const int bi = grp * 16 + (rem - 3);
        const int b = bi >> 10;
        const float* src = bias + (size_t)bi * (NN * HH);

        #pragma unroll
        for (int sIt = 0; sIt < 8; sIt++) {
            int idx = tid + sIt * 256;                   // float4 index
            float4 v = *(const float4*)(src + idx * 4);
            int j = idx >> 1;
            int hg = idx & 1;                            // h-group: 0 -> h0..3, 1 -> h4..7
            unsigned char mb = g_maskb[b * NN + j];
            float f0 = mb ? v.x : -60000.0f;
            float f1 = mb ? v.y : -60000.0f;
            float f2 = mb ? v.z : -60000.0f;
            float f3 = mb ? v.w : -60000.0f;
            int base = j * 5 + hg * 2;
            s32[base] = pack_h2(f0, f1);                 // low = h even, high = h odd
            s32[base + 1] = pack_h2(f2, f3);
        }
        __syncthreads();

        const int i = bi & (NN - 1);
        #pragma unroll
        for (int h = 0; h < HH; h++) {
            __half* dst = g_bias_h + (((size_t)(b * HH + h)) * NN + i) * NN;
            const int wI = h >> 1;
            const unsigned sel = (h & 1) ? 0x7632u : 0x5410u;
            #pragma unroll
            for (int r = 0; r < 2; r++) {
                int j2 = tid + r * 256;                  // j-pair index
                unsigned w0 = s32[(2 * j2) * 5 + wI];
                unsigned w1 = s32[(2 * j2 + 1) * 5 + wI];
                *(unsigned*)(dst + 2 * j2) = __byte_perm(w0, w1, sel);
            }
        }
    }
}

// =====================================================================
// out-proj GEMM, plain fp16 (unchanged).
// =====================================================================
#define GEMM2_SMEM ((2*128*AS2 + 2*64*AS2) * 2)   // 30720 bytes
__global__ __launch_bounds__(256, 3) void k_gemm_out(const float* __restrict__ bout,
                                                     float* __restrict__ Cout) {
    extern __shared__ __half smh2[];
    __half* sA = smh2;
    __half* sB = sA + 2 * 128 * AS2;

    const int tid = threadIdx.x, lane = tid & 31, warp = tid >> 5;
    const int g = lane >> 2, t = lane & 3;
    const int cb = (blockIdx.x & 7) * 64;
    const int rb = (blockIdx.x >> 3) * 128;
    const int m0 = warp * 16;

    const int ar = tid >> 2, ac8 = (tid & 3) * 8;
    const int br = tid >> 2, bc8 = (tid & 3) * 8;

    auto load_stage = [&](int st, int kt) {
        const int k0 = kt * 32;
        __half* pA = sA + st * 128 * AS2;
        #pragma unroll
        for (int sIt = 0; sIt < 2; sIt++) {
            int r = ar + sIt * 64;
            cp16(&pA[r * AS2 + ac8], g_attf + (size_t)(rb + r) * INNER + k0 + ac8);
        }
        cp16(&sB[st * 64 * AS2 + br * AS2 + bc8], g_woutf + (size_t)(cb + br) * INNER + k0 + bc8);
    };

    const unsigned aoff = (unsigned)((m0 + (lane & 15)) * 80 + ((lane & 16) >> 4) * 16);
    const unsigned boff = (unsigned)(((lane & 7) + ((lane & 16) >> 1)) * 80 + ((lane & 8) >> 3) * 16);
    const unsigned sA_b = (unsigned)__cvta_generic_to_shared(sA);
    const unsigned sB_b = (unsigned)__cvta_generic_to_shared(sB);

    float acc[8][4];
    #pragma unroll
    for (int i = 0; i < 8; i++)
        #pragma unroll
        for (int j = 0; j < 4; j++) acc[i][j] = 0.f;

    load_stage(0, 0);
    CP_COMMIT;

    for (int kt = 0; kt < 16; kt++) {
        CP_WAIT0;
        __syncthreads();
        if (kt < 15) { load_stage((kt + 1) & 1, kt + 1); CP_COMMIT; }

        const unsigned stA = (kt & 1) * 128 * AS2 * 2;
        const unsigned stB = (kt & 1) * 64 * AS2 * 2;

        #pragma unroll
        for (int kc = 0; kc < 2; kc++) {
            const unsigned ko = kc * 32;
            unsigned a0, a1, a2, a3;
            ldsm4(a0, a1, a2, a3, sA_b + stA + aoff + ko);
            #pragma unroll
            for (int nbp = 0; nbp < 4; nbp++) {
                unsigned b0, b1, c0, c1;
                ldsm4(b0, b1, c0, c1, sB_b + stB + boff + (unsigned)(nbp * 16 * 80) + ko);
                float* A0 = acc[2 * nbp];
                float* A1 = acc[2 * nbp + 1];
                mma16f(A0[0], A0[1], A0[2], A0[3], a0, a1, a2, a3, b0, b1);
                mma16f(A1[0], A1[1], A1[2], A1[3], a0, a1, a2, a3, c0, c1);
            }
        }
        __syncthreads();
    }

    #pragma unroll
    for (int nb = 0; nb < 8; nb++) {
        int col = cb + nb * 8 + 2 * t;
        float b0v = bout[col], b1v = bout[col + 1];
        int r0 = rb + m0 + g;
        int r1 = r0 + 8;
        *(float2*)(Cout + (size_t)r0 * DOUT + col) = make_float2(acc[nb][0] + b0v, acc[nb][1] + b1v);
        *(float2*)(Cout + (size_t)r1 * DOUT + col) = make_float2(acc[nb][2] + b0v, acc[nb][3] + b1v);
    }
}

// =====================================================================
// Flash attention: fp16 tiles, f16x2 ex2 softmax, ones-B row sums,
// per-warp bias staging. NEW: launch_bounds(256,3) — 3 CTAs/SM (smem
// 55.3KB x3 = 166KB fits; hot-loop live regs ~75 so 84-reg cap should
// not spill).
// =====================================================================
#define HS 72            // half stride per smem row (144B)
#define HSB 144
#define ONES16 0x3C003C00u
__global__ __launch_bounds__(256, 3) void k_flash() {
    extern __shared__ __half smh[];
    __half* Qs = smh;                     // 128*HS
    __half* Ks = Qs + 128 * HS;           // 64*HS  [token][d]
    __half* Vt = Ks + 64 * HS;            // 64*HS  [d][token]
    __half* Ps = Vt + 64 * HS;            // 128*HS (bias overlay + P)

    const int tid = threadIdx.x, lane = tid & 31, warp = tid >> 5;
    const int g = lane >> 2, t = lane & 3;
    const int it = blockIdx.x & 7;
    const int bh = blockIdx.x >> 3;
    const int b = bh >> 3, h = bh & 7;
    const int i0 = it * 128;
    const int m0 = warp * 16;
    const float NEG_INF = __int_as_float(0xff800000);

    const __half* qbase = g_qk + (size_t)b * NN * QKCOLS + h * 64;
    const __half* kbase = qbase + 512;
    const __half* vbase = g_vTh + (size_t)bh * 64 * NN;
    const __half* bbase = g_bias_h + ((size_t)bh * NN + i0) * NN;

    const unsigned aoff = (unsigned)((m0 + (lane & 15)) * HSB + ((lane & 16) >> 4) * 16);
    const unsigned boff = (unsigned)(((lane & 7) + ((lane & 16) >> 1)) * HSB + ((lane & 8) >> 3) * 16);
    const unsigned qs_b = (unsigned)__cvta_generic_to_shared(Qs);
    const unsigned ks_b = (unsigned)__cvta_generic_to_shared(Ks);
    const unsigned vt_b = (unsigned)__cvta_generic_to_shared(Vt);
    const unsigned ps_b = (unsigned)__cvta_generic_to_shared(Ps);

    // per-warp bias chunk coords: warp w owns rows m0..m0+15
    const int bw_r = m0 + (lane >> 3);
    const int bw_c8 = (lane & 7) * 8;

    // Q tile (own cp group)
    #pragma unroll
    for (int sIt = 0; sIt < 4; sIt++) {
        int idx = tid + sIt * 256;
        int r = idx >> 3, c8 = (idx & 7) * 8;
        cp16(&Qs[r * HS + c8], qbase + (size_t)(i0 + r) * QKCOLS + c8);
    }
    CP_COMMIT;

    float accO[8][4];
    #pragma unroll
    for (int i = 0; i < 8; i++)
        #pragma unroll
        for (int j = 0; j < 4; j++) accO[i][j] = 0.f;
    float mrow0 = NEG_INF, mrow1 = NEG_INF;
    float lrow0 = 0.f, lrow1 = 0.f;

    for (int jt = 0; jt < 16; jt++) {
        const int j0 = jt * 64;
        __syncthreads();                                   // buffers free (Ks/Vt/Ps)
        #pragma unroll
        for (int sIt = 0; sIt < 2; sIt++) {
            int idx = tid + sIt * 256;
            int r = idx >> 3, c8 = (idx & 7) * 8;
            cp16(&Ks[r * HS + c8], kbase + (size_t)(j0 + r) * QKCOLS + c8);
            cp16(&Vt[r * HS + c8], vbase + (size_t)r * NN + j0 + c8);
        }
        CP_COMMIT;                                         // group: K/V
        #pragma unroll
        for (int sIt = 0; sIt < 4; sIt++) {
            int r = bw_r + sIt * 4;
            cp16(&Ps[r * HS + bw_c8], bbase + (size_t)r * NN + j0 + bw_c8);
        }
        CP_COMMIT;                                         // group: bias (warp-local rows)
        CP_WAIT1;
        __syncthreads();                                   // K/V visible to all warps

        // S = Q @ K^T
        float s[8][4];
        #pragma unroll
        for (int i = 0; i < 8; i++)
            #pragma unroll
            for (int j = 0; j < 4; j++) s[i][j] = 0.f;
        #pragma unroll
        for (int kc = 0; kc < 4; kc++) {
            const unsigned ko = kc * 32;
            unsigned a0, a1, a2, a3;
            ldsm4(a0, a1, a2, a3, qs_b + aoff + ko);
            #pragma unroll
            for (int nbp = 0; nbp < 4; nbp++) {
                unsigned b0, b1, c0, c1;
                ldsm4(b0, b1, c0, c1, ks_b + boff + (unsigned)(nbp * 16 * HSB) + ko);
                float* S0 = s[2 * nbp];
                float* S1 = s[2 * nbp + 1];
                mma16f(S0[0], S0[1], S0[2], S0[3], a0, a1, a2, a3, b0, b1);
                mma16f(S1[0], S1[1], S1[2], S1[3], a0, a1, a2, a3, c0, c1);
            }
        }
        CP_WAIT0;                                          // this thread's bias chunks done
        __syncwarp();                                      // warp's own rows visible

        // + bias (fp16), row max
        float mx0 = NEG_INF, mx1 = NEG_INF;
        #pragma unroll
        for (int nb = 0; nb < 8; nb++) {
            int c = nb * 8 + 2 * t;
            float2 fA = __half22float2(*(__half2*)&Ps[(m0 + g) * HS + c]);
            float2 fB = __half22float2(*(__half2*)&Ps[(m0 + g + 8) * HS + c]);
            s[nb][0] += fA.x;
            s[nb][1] += fA.y;
            s[nb][2] += fB.x;
            s[nb][3] += fB.y;
            mx0 = fmaxf(mx0, fmaxf(s[nb][0], s[nb][1]));
            mx1 = fmaxf(mx1, fmaxf(s[nb][2], s[nb][3]));
        }
        mx0 = fmaxf(mx0, __shfl_xor_sync(0xffffffffu, mx0, 1));
        mx0 = fmaxf(mx0, __shfl_xor_sync(0xffffffffu, mx0, 2));
        mx1 = fmaxf(mx1, __shfl_xor_sync(0xffffffffu, mx1, 1));
        mx1 = fmaxf(mx1, __shfl_xor_sync(0xffffffffu, mx1, 2));

        float mn0 = fmaxf(mrow0, mx0), mn1 = fmaxf(mrow1, mx1);
        float al0 = ex2((mrow0 - mn0) * LOG2E);
        float al1 = ex2((mrow1 - mn1) * LOG2E);
        mrow0 = mn0;
        mrow1 = mn1;

        // P = exp(s - mn) via f16x2 ex2 -> stored directly as fp16 pairs
        #pragma unroll
        for (int nb = 0; nb < 8; nb++) {
            int c = nb * 8 + 2 * t;
            unsigned q01 = h2ex2(pack_h2((s[nb][0] - mn0) * LOG2E, (s[nb][1] - mn0) * LOG2E));
            unsigned q23 = h2ex2(pack_h2((s[nb][2] - mn1) * LOG2E, (s[nb][3] - mn1) * LOG2E));
            *(unsigned*)&Ps[(m0 + g) * HS + c] = q01;
            *(unsigned*)&Ps[(m0 + g + 8) * HS + c] = q23;
        }

        #pragma unroll
        for (int nb = 0; nb < 8; nb++) {
            accO[nb][0] *= al0;
            accO[nb][1] *= al0;
            accO[nb][2] *= al1;
            accO[nb][3] *= al1;
        }
        __syncwarp();                                      // P rows warp-private
        // O += P @ V ; row sums via ones-B mma
        float sacc0 = 0.f, sacc1 = 0.f, sacc2 = 0.f, sacc3 = 0.f;
        #pragma unroll
        for (int kc = 0; kc < 4; kc++) {
            const unsigned ko = kc * 32;
            unsigned a0, a1, a2, a3;
            ldsm4(a0, a1, a2, a3, ps_b + aoff + ko);
            mma16f(sacc0, sacc1, sacc2, sacc3, a0, a1, a2, a3, ONES16, ONES16);
            #pragma unroll
            for (int nbp = 0; nbp < 4; nbp++) {
                unsigned b0, b1, c0, c1;
                ldsm4(b0, b1, c0, c1, vt_b + boff + (unsigned)(nbp * 16 * HSB) + ko);
                float* O0 = accO[2 * nbp];
                float* O1 = accO[2 * nbp + 1];
                mma16f(O0[0], O0[1], O0[2], O0[3], a0, a1, a2, a3, b0, b1);
                mma16f(O1[0], O1[1], O1[2], O1[3], a0, a1, a2, a3, c0, c1);
            }
        }
        lrow0 = lrow0 * al0 + sacc0;
        lrow1 = lrow1 * al1 + sacc2;
    }

    // epilogue: normalize, store attention output as fp16
    float inv0 = 1.f / lrow0;
    float inv1 = 1.f / lrow1;
    __half* arow = g_attf + (size_t)h * 64;
    #pragma unroll
    for (int nb = 0; nb < 8; nb++) {
        int col = nb * 8 + 2 * t;
        int r0 = b * NN + i0 + m0 + g;
        int r1 = r0 + 8;
        *(__half2*)(arow + (size_t)r0 * INNER + col) =
            __floats2half2_rn(accO[nb][0] * inv0, accO[nb][1] * inv0);
        *(__half2*)(arow + (size_t)r1 * INNER + col) =
            __floats2half2_rn(accO[nb][2] * inv1, accO[nb][3] * inv1);
    }
}

// =====================================================================
extern "C" void kernel_launch(void* const* d_in, const int* in_sizes, int n_in,
                              void* d_out, int out_size) {
    (void)in_sizes; (void)n_in; (void)out_size;
    const float* x = (const float*)d_in[0];
    const unsigned char* mask = (const unsigned char*)d_in[1];
    const float* bias = (const float*)d_in[2];
    const float* Wq = (const float*)d_in[3];
    const float* Wkv = (const float*)d_in[4];
    const float* Wout = (const float*)d_in[5];
    const float* bout = (const float*)d_in[6];
    float* out = (float*)d_out;

    const int flash_smem = (128 + 64 + 64 + 128) * HS * 2;   // 55296
    cudaFuncSetAttribute(k_flash, cudaFuncAttributeMaxDynamicSharedMemorySize, flash_smem);
    cudaFuncSetAttribute(k_mid, cudaFuncAttributeMaxDynamicSharedMemorySize, GEMMQ_SMEM);
    cudaFuncSetAttribute(k_gemm_out, cudaFuncAttributeMaxDynamicSharedMemorySize, GEMM2_SMEM);

    k_prep<<<1281, 256>>>(mask, x, Wq, Wkv, Wout);
    k_mid<<<19 * 512, 256, GEMMQ_SMEM>>>(bias);
    k_flash<<<BB * HH * (NN / 128), 256, flash_smem>>>();
    k_gemm_out<<<(DOUT / 64) * (NROWS / 128), 256, GEMM2_SMEM>>>(bout, out);
}

// round 16
// speedup vs baseline: 1.6926x; 1.0251x over previous
#include <cuda_runtime.h>
#include <cuda_bf16.h>
#include <cuda_fp16.h>

#define BB 8
#define NN 1024
#define DIN 512
#define HH 8
#define INNER 512
#define DOUT 512
#define NROWS (BB*NN)            // 8192
#define SCALE 0.125f
#define LOG2E 1.4426950408889634f
#define QKCOLS 1024              // q|k halves per row
#define QKV_COLS 1536

// ---- scratch (device globals; no runtime allocation) ----
__device__ __half g_qk[(size_t)NROWS * QKCOLS];             // q|k fp16
__device__ __half g_vTh[(size_t)BB * HH * 64 * NN];         // V^T fp16 per (b,h): [d][token]
__device__ __half g_bias_h[(size_t)BB * HH * NN * NN];      // bias transposed+masked fp16, 128MB
__device__ __half g_attf[(size_t)NROWS * INNER];            // attention out fp16 [row][hd]
__device__ __half g_woutf[(size_t)DOUT * INNER];            // Wout fp16 n-major [n][k]
__device__ __half g_xf[(size_t)NROWS * DIN];                // x fp16 [row][k]
__device__ unsigned g_wqh[(size_t)QKV_COLS * 256];          // [SCALE*Wq|Wkv] fp16-hi pairs n-major
__device__ unsigned g_wql[(size_t)QKV_COLS * 256];          // fp16-lo pairs (subnormal residual)
__device__ unsigned char g_maskb[BB * NN];

// ---- helpers ----
__device__ __forceinline__ float ex2(float x) {
    float y;
    asm("ex2.approx.ftz.f32 %0, %1;" : "=f"(y) : "f"(x));
    return y;
}
__device__ __forceinline__ unsigned h2ex2(unsigned a) {
    unsigned d;
    asm("ex2.approx.f16x2 %0, %1;" : "=r"(d) : "r"(a));
    return d;
}
// pack two f32 into f16x2: low half = lo, high half = hi
__device__ __forceinline__ unsigned pack_h2(float lo, float hi) {
    unsigned d;
    asm("cvt.rn.f16x2.f32 %0, %1, %2;" : "=r"(d) : "f"(hi), "f"(lo));
    return d;
}
__device__ __forceinline__ void cp16(void* sp, const void* gp) {
    unsigned s = (unsigned)__cvta_generic_to_shared(sp);
    asm volatile("cp.async.cg.shared.global [%0], [%1], 16;\n" :: "r"(s), "l"(gp));
}
#define CP_COMMIT asm volatile("cp.async.commit_group;\n")
#define CP_WAIT0  asm volatile("cp.async.wait_group 0;\n")
#define CP_WAIT1  asm volatile("cp.async.wait_group 1;\n")

__device__ __forceinline__ void ldsm4(unsigned& r0, unsigned& r1, unsigned& r2, unsigned& r3,
                                      unsigned saddr) {
    asm volatile("ldmatrix.sync.aligned.m8n8.x4.shared.b16 {%0,%1,%2,%3}, [%4];"
                 : "=r"(r0), "=r"(r1), "=r"(r2), "=r"(r3) : "r"(saddr));
}
__device__ __forceinline__ void mma16f(float& c0, float& c1, float& c2, float& c3,
                                       unsigned a0, unsigned a1, unsigned a2, unsigned a3,
                                       unsigned b0, unsigned b1) {
    asm volatile(
        "mma.sync.aligned.m16n8k16.row.col.f32.f16.f16.f32 "
        "{%0,%1,%2,%3},{%4,%5,%6,%7},{%8,%9},{%0,%1,%2,%3};\n"
        : "+f"(c0), "+f"(c1), "+f"(c2), "+f"(c3)
        : "r"(a0), "r"(a1), "r"(a2), "r"(a3), "r"(b0), "r"(b1));
}

// =====================================================================
// k_prep (compact): [CTA 0] mask; [1..1024] x -> fp16; [1025..1280] weights
// =====================================================================
__global__ __launch_bounds__(256) void k_prep(const unsigned char* __restrict__ m,
                                              const float* __restrict__ x,
                                              const float* __restrict__ Wq,
                                              const float* __restrict__ Wkv,
                                              const float* __restrict__ Wout) {
    const int bid = blockIdx.x;
    if (bid == 0) {
        __shared__ int s_notI32, s_notF32;
        if (threadIdx.x == 0) { s_notI32 = 0; s_notF32 = 0; }
        __syncthreads();
        const unsigned* mw = (const unsigned*)m;
        int notI = 0, notF = 0;
        for (int i = threadIdx.x; i < BB * NN / 4; i += 256) {
            unsigned w = mw[i];
            if (w & 0xFFFFFF00u) notI = 1;
            if (w != 0u && w != 0x3F800000u) notF = 1;
        }
        if (notI) atomicOr(&s_notI32, 1);
        if (notF) atomicOr(&s_notF32, 1);
        __syncthreads();
        const int notI32 = s_notI32, notF32 = s_notF32;
        for (int i = threadIdx.x; i < BB * NN; i += 256) {
            unsigned char v;
            if (!notF32)      v = (((const unsigned*)m)[i] != 0u) ? 1 : 0;
            else if (!notI32) v = (((const int*)m)[i] != 0) ? 1 : 0;
            else              v = (m[i] != 0) ? 1 : 0;
            g_maskb[i] = v;
        }
    } else if (bid <= 1024) {
        const int base = (bid - 1) * 2048;
        #pragma unroll
        for (int s = 0; s < 8; s++) {
            int idx = base + s * 256 + threadIdx.x;
            float2 v = ((const float2*)x)[idx];
            ((unsigned*)g_xf)[idx] = pack_h2(v.x, v.y);
        }
    } else {
        const int base = (bid - 1025) * 2048;
        const int total1 = 256 * QKV_COLS;
        #pragma unroll
        for (int s = 0; s < 8; s++) {
            int idx = base + s * 256 + threadIdx.x;
            if (idx < total1) {
                int kp = idx / QKV_COLS, n = idx % QKV_COLS;
                float a, b;
                if (n < 512) {
                    a = Wq[(2 * kp) * 512 + n] * SCALE;
                    b = Wq[(2 * kp + 1) * 512 + n] * SCALE;
                } else {
                    int nn = n - 512;
                    a = Wkv[(2 * kp) * 1024 + nn];
                    b = Wkv[(2 * kp + 1) * 1024 + nn];
                }
                size_t off = (size_t)n * 256 + kp;
                unsigned hp = pack_h2(a, b);
                float2 hf = __half22float2(*(__half2*)&hp);
                unsigned lp = pack_h2(a - hf.x, b - hf.y);   // residual (fp16 subnormal range)
                g_wqh[off] = hp;
                g_wql[off] = lp;
            } else {
                int j = idx - total1;
                int kp = j / DOUT, n = j % DOUT;
                float a = Wout[(2 * kp) * DOUT + n];
                float b = Wout[(2 * kp + 1) * DOUT + n];
                ((unsigned*)g_woutf)[(size_t)n * 256 + kp] = pack_h2(a, b);
            }
        }
    }
}

// =====================================================================
// QKV GEMM, fp16 A + fp16 hi/lo W (2-mma): tile 128x64, 2-stage cp.async.
// =====================================================================
#define AS2 40     // half stride (80B) for smem rows
#define GEMMQ_SMEM ((2*128*AS2 + 2*2*64*AS2) * 2)   // 40960 bytes

__device__ __forceinline__ void gemm_qkv(__half* smh2, int cbid) {
    __half* sA = smh2;                       // 2 stages x 128*AS2
    __half* sBh = sA + 2 * 128 * AS2;        // 2 stages x 64*AS2
    __half* sBl = sBh + 2 * 64 * AS2;        // 2 stages x 64*AS2

    const int tid = threadIdx.x, lane = tid & 31, warp = tid >> 5;
    const int g = lane >> 2, t = lane & 3;
    const int cb = (cbid % (QKV_COLS / 64)) * 64;
    const int rb = (cbid / (QKV_COLS / 64)) * 128;
    const int m0 = warp * 16;

    const __half* Bh = (const __half*)g_wqh;
    const __half* Bl = (const __half*)g_wql;

    const int ar = tid >> 2, ac8 = (tid & 3) * 8;
    const int br = tid >> 2, bc8 = (tid & 3) * 8;

    auto load_stage = [&](int st, int kt) {
        const int k0 = kt * 32;
        __half* pA = sA + st * 128 * AS2;
        #pragma unroll
        for (int sIt = 0; sIt < 2; sIt++) {
            int r = ar + sIt * 64;
            cp16(&pA[r * AS2 + ac8], g_xf + (size_t)(rb + r) * DIN + k0 + ac8);
        }
        size_t go = (size_t)(cb + br) * DIN + k0 + bc8;
        cp16(&sBh[st * 64 * AS2 + br * AS2 + bc8], Bh + go);
        cp16(&sBl[st * 64 * AS2 + br * AS2 + bc8], Bl + go);
    };

    const unsigned aoff = (unsigned)((m0 + (lane & 15)) * 80 + ((lane & 16) >> 4) * 16);
    const unsigned boff = (unsigned)(((lane & 7) + ((lane & 16) >> 1)) * 80 + ((lane & 8) >> 3) * 16);
    const unsigned sA_b = (unsigned)__cvta_generic_to_shared(sA);
    const unsigned sBh_b = (unsigned)__cvta_generic_to_shared(sBh);
    const unsigned sBl_b = (unsigned)__cvta_generic_to_shared(sBl);

    float acc[8][4];
    #pragma unroll
    for (int i = 0; i < 8; i++)
        #pragma unroll
        for (int j = 0; j < 4; j++) acc[i][j] = 0.f;

    load_stage(0, 0);
    CP_COMMIT;

    for (int kt = 0; kt < 16; kt++) {
        CP_WAIT0;
        __syncthreads();
        if (kt < 15) { load_stage((kt + 1) & 1, kt + 1); CP_COMMIT; }

        const unsigned stA = (kt & 1) * 128 * AS2 * 2;
        const unsigned stB = (kt & 1) * 64 * AS2 * 2;

        #pragma unroll
        for (int kc = 0; kc < 2; kc++) {
            const unsigned ko = kc * 32;
            unsigned a0, a1, a2, a3;
            ldsm4(a0, a1, a2, a3, sA_b + stA + aoff + ko);
            #pragma unroll
            for (int nbp = 0; nbp < 4; nbp++) {
                const unsigned bo = boff + (unsigned)(nbp * 16 * 80) + ko;
                unsigned bh0, bh1, bh2, bh3, bl0, bl1, bl2, bl3;
                ldsm4(bh0, bh1, bh2, bh3, sBh_b + stB + bo);
                ldsm4(bl0, bl1, bl2, bl3, sBl_b + stB + bo);
                float* A0 = acc[2 * nbp];
                float* A1 = acc[2 * nbp + 1];
                mma16f(A0[0], A0[1], A0[2], A0[3], a0, a1, a2, a3, bh0, bh1);
                mma16f(A0[0], A0[1], A0[2], A0[3], a0, a1, a2, a3, bl0, bl1);
                mma16f(A1[0], A1[1], A1[2], A1[3], a0, a1, a2, a3, bh2, bh3);
                mma16f(A1[0], A1[1], A1[2], A1[3], a0, a1, a2, a3, bl2, bl3);
            }
        }
        __syncthreads();
    }

    if (cb < 1024) {
        #pragma unroll
        for (int nb = 0; nb < 8; nb++) {
            int col = cb + nb * 8 + 2 * t;
            int r0 = rb + m0 + g;
            int r1 = r0 + 8;
            *(__half2*)(g_qk + (size_t)r0 * QKCOLS + col) = __floats2half2_rn(acc[nb][0], acc[nb][1]);
            *(__half2*)(g_qk + (size_t)r1 * QKCOLS + col) = __floats2half2_rn(acc[nb][2], acc[nb][3]);
        }
    } else {
        int h = (cb - 1024) >> 6;
        int r0 = rb + m0 + g;
        int b = r0 >> 10, n = r0 & 1023;
        __half* vt = g_vTh + (size_t)(b * 8 + h) * 64 * NN;
        #pragma unroll
        for (int nb = 0; nb < 8; nb++) {
            int d = nb * 8 + 2 * t;
            vt[(size_t)d * NN + n] = __float2half_rn(acc[nb][0]);
            vt[(size_t)(d + 1) * NN + n] = __float2half_rn(acc[nb][1]);
            vt[(size_t)d * NN + n + 8] = __float2half_rn(acc[nb][2]);
            vt[(size_t)(d + 1) * NN + n + 8] = __float2half_rn(acc[nb][3]);
        }
    }
}

// =====================================================================
// k_mid: interleaved QKV GEMM (tensor) + bias transpose (2 i-rows/CTA).
// Grid = 512 groups x (3 GEMM + 8 transpose) = 5632 CTAs.
// Transpose: mask bytes loaded ONCE into regs and reused for both rows;
// fp16 staging + PRMT emit (value-identical to rounds 14/15).
// =====================================================================
__global__ __launch_bounds__(256, 3) void k_mid(const float* __restrict__ bias) {
    extern __shared__ __half smh2[];
    const int bid = blockIdx.x;
    const int tid = threadIdx.x;
    const int grp = bid / 11, rem = bid % 11;

    if (rem < 3) {
        gemm_qkv(smh2, grp * 3 + rem);
    } else {
        unsigned* s32 = (unsigned*)smh2;                 // 2 x 1024*5 u32 = 40KB
        const int bi2 = grp * 8 + (rem - 3);             // 0..4095 (i-row pair)
        const int row0 = 2 * bi2;                        // global (b,i) row
        const int b = row0 >> 10;
        const int i0 = row0 & (NN - 1);
        const float* src = bias + (size_t)row0 * (NN * HH);

        // mask bytes once (same j indices for both rows)
        unsigned char mreg[8];
        #pragma unroll
        for (int sIt = 0; sIt < 8; sIt++) {
            int idx = tid + sIt * 256;
            mreg[sIt] = g_maskb[b * NN + (idx >> 1)];
        }

        #pragma unroll
        for (int r2 = 0; r2 < 2; r2++) {
            const float* srcr = src + (size_t)r2 * (NN * HH);
            unsigned* s32r = s32 + r2 * (NN * 5);
            #pragma unroll
            for (int sIt = 0; sIt < 8; sIt++) {
                int idx = tid + sIt * 256;               // float4 index
                float4 v = *(const float4*)(srcr + idx * 4);
                int j = idx >> 1;
                int hg = idx & 1;
                unsigned char mb = mreg[sIt];
                float f0 = mb ? v.x : -60000.0f;
                float f1 = mb ? v.y : -60000.0f;
                float f2 = mb ? v.z : -60000.0f;
                float f3 = mb ? v.w : -60000.0f;
                int base = j * 5 + hg * 2;
                s32r[base] = pack_h2(f0, f1);
                s32r[base + 1] = pack_h2(f2, f3);
            }
        }
        __syncthreads();

        #pragma unroll
        for (int h = 0; h < HH; h++) {
            const int wI = h >> 1;
            const unsigned sel = (h & 1) ? 0x7632u : 0x5410u;
            #pragma unroll
            for (int r2 = 0; r2 < 2; r2++) {
                __half* dst = g_bias_h + (((size_t)(b * HH + h)) * NN + i0 + r2) * NN;
                const unsigned* s32r = s32 + r2 * (NN * 5);
                #pragma unroll
                for (int r = 0; r < 2; r++) {
                    int j2 = tid + r * 256;              // j-pair index
                    unsigned w0 = s32r[(2 * j2) * 5 + wI];
                    unsigned w1 = s32r[(2 * j2 + 1) * 5 + wI];
                    *(unsigned*)(dst + 2 * j2) = __byte_perm(w0, w1, sel);
                }
            }
        }
    }
}

// =====================================================================
// out-proj GEMM, plain fp16, tile 128x128 (256 CTAs): B reuse doubled,
// fewer CTAs -> less latency exposure. launch_bounds(256,2) for regs.
// =====================================================================
#define GEMM3_SMEM ((2*128*AS2 + 2*128*AS2) * 2)   // 40960 bytes
__global__ __launch_bounds__(256, 2) void k_gemm_out(const float* __restrict__ bout,
                                                     float* __restrict__ Cout) {
    extern __shared__ __half smh2[];
    __half* sA = smh2;                       // 2 stages x 128*AS2
    __half* sB = sA + 2 * 128 * AS2;         // 2 stages x 128*AS2

    const int tid = threadIdx.x, lane = tid & 31, warp = tid >> 5;
    const int g = lane >> 2, t = lane & 3;
    const int cb = (blockIdx.x & 3) * 128;
    const int rb = (blockIdx.x >> 2) * 128;
    const int m0 = warp * 16;

    const int ar = tid >> 2, ac8 = (tid & 3) * 8;    // A: 128 rows x 4 chunks, 2/thread
    const int br = tid >> 2, bc8 = (tid & 3) * 8;    // B: 128 rows x 4 chunks, 2/thread

    auto load_stage = [&](int st, int kt) {
        const int k0 = kt * 32;
        __half* pA = sA + st * 128 * AS2;
        __half* pB = sB + st * 128 * AS2;
        #pragma unroll
        for (int sIt = 0; sIt < 2; sIt++) {
            int r = ar + sIt * 64;
            cp16(&pA[r * AS2 + ac8], g_attf + (size_t)(rb + r) * INNER + k0 + ac8);
            cp16(&pB[r * AS2 + bc8], g_woutf + (size_t)(cb + r) * INNER + k0 + bc8);
        }
    };

    const unsigned aoff = (unsigned)((m0 + (lane & 15)) * 80 + ((lane & 16) >> 4) * 16);
    const unsigned boff = (unsigned)(((lane & 7) + ((lane & 16) >> 1)) * 80 + ((lane & 8) >> 3) * 16);
    const unsigned sA_b = (unsigned)__cvta_generic_to_shared(sA);
    const unsigned sB_b = (unsigned)__cvta_generic_to_shared(sB);

    float acc[16][4];
    #pragma unroll
    for (int i = 0; i < 16; i++)
        #pragma unroll
        for (int j = 0; j < 4; j++) acc[i][j] = 0.f;

    load_stage(0, 0);
    CP_COMMIT;

    for (int kt = 0; kt < 16; kt++) {
        CP_WAIT0;
        __syncthreads();
        if (kt < 15) { load_stage((kt + 1) & 1, kt + 1); CP_COMMIT; }

        const unsigned stA = (kt & 1) * 128 * AS2 * 2;
        const unsigned stB = (kt & 1) * 128 * AS2 * 2;

        #pragma unroll
        for (int kc = 0; kc < 2; kc++) {
            const unsigned ko = kc * 32;
            unsigned a0, a1, a2, a3;
            ldsm4(a0, a1, a2, a3, sA_b + stA + aoff + ko);
            #pragma unroll
            for (int nbp = 0; nbp < 8; nbp++) {
                unsigned b0, b1, c0, c1;
                ldsm4(b0, b1, c0, c1, sB_b + stB + boff + (unsigned)(nbp * 16 * 80) + ko);
                float* A0 = acc[2 * nbp];
                float* A1 = acc[2 * nbp + 1];
                mma16f(A0[0], A0[1], A0[2], A0[3], a0, a1, a2, a3, b0, b1);
                mma16f(A1[0], A1[1], A1[2], A1[3], a0, a1, a2, a3, c0, c1);
            }
        }
        __syncthreads();
    }

    #pragma unroll
    for (int nb = 0; nb < 16; nb++) {
        int col = cb + nb * 8 + 2 * t;
        float b0v = bout[col], b1v = bout[col + 1];
        int r0 = rb + m0 + g;
        int r1 = r0 + 8;
        *(float2*)(Cout + (size_t)r0 * DOUT + col) = make_float2(acc[nb][0] + b0v, acc[nb][1] + b1v);
        *(float2*)(Cout + (size_t)r1 * DOUT + col) = make_float2(acc[nb][2] + b0v, acc[nb][3] + b1v);
    }
}

// =====================================================================
// Flash attention: fp16 tiles, f16x2 ex2 softmax, ones-B row sums,
// per-warp bias staging, occ 3 (unchanged from round 15).
// =====================================================================
#define HS 72            // half stride per smem row (144B)
#define HSB 144
#define ONES16 0x3C003C00u
__global__ __launch_bounds__(256, 3) void k_flash() {
    extern __shared__ __half smh[];
    __half* Qs = smh;                     // 128*HS
    __half* Ks = Qs + 128 * HS;           // 64*HS  [token][d]
    __half* Vt = Ks + 64 * HS;            // 64*HS  [d][token]
    __half* Ps = Vt + 64 * HS;            // 128*HS (bias overlay + P)

    const int tid = threadIdx.x, lane = tid & 31, warp = tid >> 5;
    const int g = lane >> 2, t = lane & 3;
    const int it = blockIdx.x & 7;
    const int bh = blockIdx.x >> 3;
    const int b = bh >> 3, h = bh & 7;
    const int i0 = it * 128;
    const int m0 = warp * 16;
    const float NEG_INF = __int_as_float(0xff800000);

    const __half* qbase = g_qk + (size_t)b * NN * QKCOLS + h * 64;
    const __half* kbase = qbase + 512;
    const __half* vbase = g_vTh + (size_t)bh * 64 * NN;
    const __half* bbase = g_bias_h + ((size_t)bh * NN + i0) * NN;

    const unsigned aoff = (unsigned)((m0 + (lane & 15)) * HSB + ((lane & 16) >> 4) * 16);
    const unsigned boff = (unsigned)(((lane & 7) + ((lane & 16) >> 1)) * HSB + ((lane & 8) >> 3) * 16);
    const unsigned qs_b = (unsigned)__cvta_generic_to_shared(Qs);
    const unsigned ks_b = (unsigned)__cvta_generic_to_shared(Ks);
    const unsigned vt_b = (unsigned)__cvta_generic_to_shared(Vt);
    const unsigned ps_b = (unsigned)__cvta_generic_to_shared(Ps);

    // per-warp bias chunk coords: warp w owns rows m0..m0+15
    const int bw_r = m0 + (lane >> 3);
    const int bw_c8 = (lane & 7) * 8;

    // Q tile (own cp group)
    #pragma unroll
    for (int sIt = 0; sIt < 4; sIt++) {
        int idx = tid + sIt * 256;
        int r = idx >> 3, c8 = (idx & 7) * 8;
        cp16(&Qs[r * HS + c8], qbase + (size_t)(i0 + r) * QKCOLS + c8);
    }
    CP_COMMIT;

    float accO[8][4];
    #pragma unroll
    for (int i = 0; i < 8; i++)
        #pragma unroll
        for (int j = 0; j < 4; j++) accO[i][j] = 0.f;
    float mrow0 = NEG_INF, mrow1 = NEG_INF;
    float lrow0 = 0.f, lrow1 = 0.f;

    for (int jt = 0; jt < 16; jt++) {
        const int j0 = jt * 64;
        __syncthreads();                                   // buffers free (Ks/Vt/Ps)
        #pragma unroll
        for (int sIt = 0; sIt < 2; sIt++) {
            int idx = tid + sIt * 256;
            int r = idx >> 3, c8 = (idx & 7) * 8;
            cp16(&Ks[r * HS + c8], kbase + (size_t)(j0 + r) * QKCOLS + c8);
            cp16(&Vt[r * HS + c8], vbase + (size_t)r * NN + j0 + c8);
        }
        CP_COMMIT;                                         // group: K/V
        #pragma unroll
        for (int sIt = 0; sIt < 4; sIt++) {
            int r = bw_r + sIt * 4;
            cp16(&Ps[r * HS + bw_c8], bbase + (size_t)r * NN + j0 + bw_c8);
        }
        CP_COMMIT;                                         // group: bias (warp-local rows)
        CP_WAIT1;
        __syncthreads();                                   // K/V visible to all warps

        // S = Q @ K^T
        float s[8][4];
        #pragma unroll
        for (int i = 0; i < 8; i++)
            #pragma unroll
            for (int j = 0; j < 4; j++) s[i][j] = 0.f;
        #pragma unroll
        for (int kc = 0; kc < 4; kc++) {
            const unsigned ko = kc * 32;
            unsigned a0, a1, a2, a3;
            ldsm4(a0, a1, a2, a3, qs_b + aoff + ko);
            #pragma unroll
            for (int nbp = 0; nbp < 4; nbp++) {
                unsigned b0, b1, c0, c1;
                ldsm4(b0, b1, c0, c1, ks_b + boff + (unsigned)(nbp * 16 * HSB) + ko);
                float* S0 = s[2 * nbp];
                float* S1 = s[2 * nbp + 1];
                mma16f(S0[0], S0[1], S0[2], S0[3], a0, a1, a2, a3, b0, b1);
                mma16f(S1[0], S1[1], S1[2], S1[3], a0, a1, a2, a3, c0, c1);
            }
        }
        CP_WAIT0;                                          // this thread's bias chunks done
        __syncwarp();                                      // warp's own rows visible

        // + bias (fp16), row max
        float mx0 = NEG_INF, mx1 = NEG_INF;
        #pragma unroll
        for (int nb = 0; nb < 8; nb++) {
            int c = nb * 8 + 2 * t;
            float2 fA = __half22float2(*(__half2*)&Ps[(m0 + g) * HS + c]);
            float2 fB = __half22float2(*(__half2*)&Ps[(m0 + g + 8) * HS + c]);
            s[nb][0] += fA.x;
            s[nb][1] += fA.y;
            s[nb][2] += fB.x;
            s[nb][3] += fB.y;
            mx0 = fmaxf(mx0, fmaxf(s[nb][0], s[nb][1]));
            mx1 = fmaxf(mx1, fmaxf(s[nb][2], s[nb][3]));
        }
        mx0 = fmaxf(mx0, __shfl_xor_sync(0xffffffffu, mx0, 1));
        mx0 = fmaxf(mx0, __shfl_xor_sync(0xffffffffu, mx0, 2));
        mx1 = fmaxf(mx1, __shfl_xor_sync(0xffffffffu, mx1, 1));
        mx1 = fmaxf(mx1, __shfl_xor_sync(0xffffffffu, mx1, 2));

        float mn0 = fmaxf(mrow0, mx0), mn1 = fmaxf(mrow1, mx1);
        float al0 = ex2((mrow0 - mn0) * LOG2E);
        float al1 = ex2((mrow1 - mn1) * LOG2E);
        mrow0 = mn0;
        mrow1 = mn1;

        // P = exp(s - mn) via f16x2 ex2 -> stored directly as fp16 pairs
        #pragma unroll
        for (int nb = 0; nb < 8; nb++) {
            int c = nb * 8 + 2 * t;
            unsigned q01 = h2ex2(pack_h2((s[nb][0] - mn0) * LOG2E, (s[nb][1] - mn0) * LOG2E));
            unsigned q23 = h2ex2(pack_h2((s[nb][2] - mn1) * LOG2E, (s[nb][3] - mn1) * LOG2E));
            *(unsigned*)&Ps[(m0 + g) * HS + c] = q01;
            *(unsigned*)&Ps[(m0 + g + 8) * HS + c] = q23;
        }

        #pragma unroll
        for (int nb = 0; nb < 8; nb++) {
            accO[nb][0] *= al0;
            accO[nb][1] *= al0;
            accO[nb][2] *= al1;
            accO[nb][3] *= al1;
        }
        __syncwarp();                                      // P rows warp-private
        // O += P @ V ; row sums via ones-B mma
        float sacc0 = 0.f, sacc1 = 0.f, sacc2 = 0.f, sacc3 = 0.f;
        #pragma unroll
        for (int kc = 0; kc < 4; kc++) {
            const unsigned ko = kc * 32;
            unsigned a0, a1, a2, a3;
            ldsm4(a0, a1, a2, a3, ps_b + aoff + ko);
            mma16f(sacc0, sacc1, sacc2, sacc3, a0, a1, a2, a3, ONES16, ONES16);
            #pragma unroll
            for (int nbp = 0; nbp < 4; nbp++) {
                unsigned b0, b1, c0, c1;
                ldsm4(b0, b1, c0, c1, vt_b + boff + (unsigned)(nbp * 16 * HSB) + ko);
                float* O0 = accO[2 * nbp];
                float* O1 = accO[2 * nbp + 1];
                mma16f(O0[0], O0[1], O0[2], O0[3], a0, a1, a2, a3, b0, b1);
                mma16f(O1[0], O1[1], O1[2], O1[3], a0, a1, a2, a3, c0, c1);
            }
        }
        lrow0 = lrow0 * al0 + sacc0;
        lrow1 = lrow1 * al1 + sacc2;
    }

    // epilogue: normalize, store attention output as fp16
    float inv0 = 1.f / lrow0;
    float inv1 = 1.f / lrow1;
    __half* arow = g_attf + (size_t)h * 64;
    #pragma unroll
    for (int nb = 0; nb < 8; nb++) {
        int col = nb * 8 + 2 * t;
        int r0 = b * NN + i0 + m0 + g;
        int r1 = r0 + 8;
        *(__half2*)(arow + (size_t)r0 * INNER + col) =
            __floats2half2_rn(accO[nb][0] * inv0, accO[nb][1] * inv0);
        *(__half2*)(arow + (size_t)r1 * INNER + col) =
            __floats2half2_rn(accO[nb][2] * inv1, accO[nb][3] * inv1);
    }
}

// =====================================================================
extern "C" void kernel_launch(void* const* d_in, const int* in_sizes, int n_in,
                              void* d_out, int out_size) {
    (void)in_sizes; (void)n_in; (void)out_size;
    const float* x = (const float*)d_in[0];
    const unsigned char* mask = (const unsigned char*)d_in[1];
    const float* bias = (const float*)d_in[2];
    const float* Wq = (const float*)d_in[3];
    const float* Wkv = (const float*)d_in[4];
    const float* Wout = (const float*)d_in[5];
    const float* bout = (const float*)d_in[6];
    float* out = (float*)d_out;

    const int flash_smem = (128 + 64 + 64 + 128) * HS * 2;   // 55296
    cudaFuncSetAttribute(k_flash, cudaFuncAttributeMaxDynamicSharedMemorySize, flash_smem);
    cudaFuncSetAttribute(k_mid, cudaFuncAttributeMaxDynamicSharedMemorySize, GEMMQ_SMEM);
    cudaFuncSetAttribute(k_gemm_out, cudaFuncAttributeMaxDynamicSharedMemorySize, GEMM3_SMEM);

    k_prep<<<1281, 256>>>(mask, x, Wq, Wkv, Wout);
    k_mid<<<11 * 512, 256, GEMMQ_SMEM>>>(bias);
    k_flash<<<BB * HH * (NN / 128), 256, flash_smem>>>();
    k_gemm_out<<<(DOUT / 128) * (NROWS / 128), 256, GEMM3_SMEM>>>(bout, out);
}